// round 1
// baseline (speedup 1.0000x reference)
#include <cuda_runtime.h>
#include <cstdint>

// Problem constants
constexpr int B_  = 2;
constexpr int S_  = 2048;
constexpr int HID_ = 2048;
constexpr int NH_ = 16;
constexpr int HD_ = 128;
constexpr float SCALING_ = 0.08838834764831845f; // 128^-0.5

// Scratch (allocation-free rule: __device__ globals)
__device__ float g_q[(size_t)B_ * S_ * HID_];
__device__ float g_k[(size_t)B_ * S_ * HID_];
__device__ float g_v[(size_t)B_ * S_ * HID_];
__device__ float g_attn[(size_t)B_ * S_ * HID_];

// ---------------------------------------------------------------------------
// GEMM: C[M,N] = A[M,K] @ W[K,N] (+ bias), fp32, 64x64 tile, BK=16,
// 256 threads, 4x4 micro-tile per thread.
// ---------------------------------------------------------------------------
__global__ void gemm_bias_kernel(const float* __restrict__ A,
                                 const float* __restrict__ W,
                                 const float* __restrict__ bias,
                                 float* __restrict__ C,
                                 int M, int N, int K) {
    __shared__ float As[16 * 68];  // transposed: As[k][m], padded row = 68
    __shared__ float Ws[16 * 68];  // Ws[k][n]

    const int tid = threadIdx.x;
    const int tx = tid & 15;        // 0..15 -> column group
    const int ty = tid >> 4;        // 0..15 -> row group
    const int row0 = blockIdx.y * 64;
    const int col0 = blockIdx.x * 64;

    float acc[4][4] = {};

    for (int kt = 0; kt < K; kt += 16) {
        // Load A tile 64x16 -> As transposed [16][64]
        {
            int r  = tid >> 2;       // 0..63
            int kg = tid & 3;        // 0..3 (float4 group along k)
            float4 a = *reinterpret_cast<const float4*>(
                A + (size_t)(row0 + r) * K + kt + kg * 4);
            As[(kg * 4 + 0) * 68 + r] = a.x;
            As[(kg * 4 + 1) * 68 + r] = a.y;
            As[(kg * 4 + 2) * 68 + r] = a.z;
            As[(kg * 4 + 3) * 68 + r] = a.w;
        }
        // Load W tile 16x64 -> Ws[16][64]
        {
            int k  = tid >> 4;       // 0..15
            int n4 = tid & 15;       // 0..15 (float4 group along n)
            float4 w = *reinterpret_cast<const float4*>(
                W + (size_t)(kt + k) * N + col0 + n4 * 4);
            *reinterpret_cast<float4*>(&Ws[k * 68 + n4 * 4]) = w;
        }
        __syncthreads();

        #pragma unroll
        for (int k = 0; k < 16; k++) {
            float4 a4 = *reinterpret_cast<float4*>(&As[k * 68 + ty * 4]);
            float4 b4 = *reinterpret_cast<float4*>(&Ws[k * 68 + tx * 4]);
            acc[0][0] += a4.x * b4.x; acc[0][1] += a4.x * b4.y;
            acc[0][2] += a4.x * b4.z; acc[0][3] += a4.x * b4.w;
            acc[1][0] += a4.y * b4.x; acc[1][1] += a4.y * b4.y;
            acc[1][2] += a4.y * b4.z; acc[1][3] += a4.y * b4.w;
            acc[2][0] += a4.z * b4.x; acc[2][1] += a4.z * b4.y;
            acc[2][2] += a4.z * b4.z; acc[2][3] += a4.z * b4.w;
            acc[3][0] += a4.w * b4.x; acc[3][1] += a4.w * b4.y;
            acc[3][2] += a4.w * b4.z; acc[3][3] += a4.w * b4.w;
        }
        __syncthreads();
    }

    // Epilogue (float4 store per row)
    float4 bv = make_float4(0.f, 0.f, 0.f, 0.f);
    if (bias != nullptr) {
        bv = *reinterpret_cast<const float4*>(bias + col0 + tx * 4);
    }
    #pragma unroll
    for (int i = 0; i < 4; i++) {
        float4 r;
        r.x = acc[i][0] + bv.x;
        r.y = acc[i][1] + bv.y;
        r.z = acc[i][2] + bv.z;
        r.w = acc[i][3] + bv.w;
        *reinterpret_cast<float4*>(
            C + (size_t)(row0 + ty * 4 + i) * N + col0 + tx * 4) = r;
    }
}

// ---------------------------------------------------------------------------
// NeoX RoPE applied in-place to Q and K.
// One thread per (b, s, h, d<64) pair.
// ---------------------------------------------------------------------------
__global__ void rope_kernel(const int* __restrict__ pos,
                            float* __restrict__ Q,
                            float* __restrict__ Kb) {
    int idx = blockIdx.x * blockDim.x + threadIdx.x;   // total B*S*NH*64
    int d  = idx & 63;
    int h  = (idx >> 6) & (NH_ - 1);
    int bs = idx >> 10;                                // b*S + s
    if (bs >= B_ * S_) return;

    int p = pos[bs];
    float inv_freq = 1.0f / powf(10000.0f, (float)d * (2.0f / (float)HD_));
    float f = (float)p * inv_freq;
    float sn, cs;
    sincosf(f, &sn, &cs);

    size_t base = (size_t)bs * HID_ + (size_t)h * HD_;
    float q1 = Q[base + d],       q2 = Q[base + 64 + d];
    Q[base + d]      = q1 * cs - q2 * sn;
    Q[base + 64 + d] = q2 * cs + q1 * sn;
    float k1 = Kb[base + d],      k2 = Kb[base + 64 + d];
    Kb[base + d]      = k1 * cs - k2 * sn;
    Kb[base + 64 + d] = k2 * cs + k1 * sn;
}

// ---------------------------------------------------------------------------
// Causal flash attention (fp32, online softmax).
// BM = BN = 64, 256 threads. Q/K/V rows are contiguous HD=128 floats with
// stride HID in the [B,S,NH*HD] layout. Output written in same layout.
// smem: Q(64x132) K(64x132) V(64x132) S(64x65) + stats = 118784 B (dynamic).
// ---------------------------------------------------------------------------
constexpr int ATTN_SMEM_FLOATS = 3 * 64 * 132 + 64 * 65 + 3 * 64;
constexpr int ATTN_SMEM_BYTES  = ATTN_SMEM_FLOATS * 4;

__global__ void attn_kernel(const float* __restrict__ Q,
                            const float* __restrict__ K,
                            const float* __restrict__ V,
                            float* __restrict__ O) {
    extern __shared__ float sm[];
    float* Qs  = sm;                      // 64*132
    float* Ks  = Qs + 64 * 132;
    float* Vs  = Ks + 64 * 132;
    float* Ss  = Vs + 64 * 132;           // 64*65
    float* m_s = Ss + 64 * 65;            // 64
    float* l_s = m_s + 64;                // 64
    float* c_s = l_s + 64;                // 64

    const int tid = threadIdx.x;
    const int tx = tid & 15;
    const int ty = tid >> 4;
    const int bh = blockIdx.y;
    const int b  = bh / NH_;
    const int h  = bh % NH_;
    const int q0 = blockIdx.x * 64;

    const float* qb = Q + (size_t)(b * S_) * HID_ + (size_t)h * HD_;
    const float* kb = K + (size_t)(b * S_) * HID_ + (size_t)h * HD_;
    const float* vb = V + (size_t)(b * S_) * HID_ + (size_t)h * HD_;

    // Load Q tile: 64 rows x 128 cols (32 float4 per row)
    for (int t = tid; t < 64 * 32; t += 256) {
        int r = t >> 5, c4 = t & 31;
        *reinterpret_cast<float4*>(Qs + r * 132 + c4 * 4) =
            *reinterpret_cast<const float4*>(qb + (size_t)(q0 + r) * HID_ + c4 * 4);
    }
    if (tid < 64) { m_s[tid] = -1e30f; l_s[tid] = 0.f; }
    __syncthreads();

    float4 o[4][2];
    #pragma unroll
    for (int i = 0; i < 4; i++) {
        o[i][0] = make_float4(0.f, 0.f, 0.f, 0.f);
        o[i][1] = make_float4(0.f, 0.f, 0.f, 0.f);
    }

    const int ntiles = blockIdx.x + 1;   // causal: only tiles with k0 <= q0
    for (int t = 0; t < ntiles; t++) {
        const int k0 = t * 64;
        // Load K and V tiles
        for (int u = tid; u < 64 * 32; u += 256) {
            int r = u >> 5, c4 = u & 31;
            *reinterpret_cast<float4*>(Ks + r * 132 + c4 * 4) =
                *reinterpret_cast<const float4*>(kb + (size_t)(k0 + r) * HID_ + c4 * 4);
            *reinterpret_cast<float4*>(Vs + r * 132 + c4 * 4) =
                *reinterpret_cast<const float4*>(vb + (size_t)(k0 + r) * HID_ + c4 * 4);
        }
        __syncthreads();

        // S = Q @ K^T  (each thread: 4x4 of the 64x64 tile)
        float acc[4][4] = {};
        #pragma unroll 4
        for (int k4 = 0; k4 < 32; k4++) {
            float4 qv[4], kv[4];
            #pragma unroll
            for (int i = 0; i < 4; i++)
                qv[i] = *reinterpret_cast<float4*>(Qs + (ty * 4 + i) * 132 + k4 * 4);
            #pragma unroll
            for (int j = 0; j < 4; j++)
                kv[j] = *reinterpret_cast<float4*>(Ks + (tx * 4 + j) * 132 + k4 * 4);
            #pragma unroll
            for (int i = 0; i < 4; i++)
                #pragma unroll
                for (int j = 0; j < 4; j++)
                    acc[i][j] += qv[i].x * kv[j].x + qv[i].y * kv[j].y +
                                 qv[i].z * kv[j].z + qv[i].w * kv[j].w;
        }

        // Scale + causal mask, write S tile to smem
        #pragma unroll
        for (int i = 0; i < 4; i++)
            #pragma unroll
            for (int j = 0; j < 4; j++) {
                int gr = q0 + ty * 4 + i;
                int gc = k0 + tx * 4 + j;
                float v = acc[i][j] * SCALING_;
                if (gc > gr) v = -1e30f;
                Ss[(ty * 4 + i) * 65 + tx * 4 + j] = v;
            }
        __syncthreads();

        // Online softmax: one thread per row
        if (tid < 64) {
            const int r = tid;
            float mold = m_s[r];
            float tm = -1e30f;
            for (int j = 0; j < 64; j++) tm = fmaxf(tm, Ss[r * 65 + j]);
            float mnew = fmaxf(mold, tm);
            float corr = __expf(mold - mnew);
            float sum = 0.f;
            for (int j = 0; j < 64; j++) {
                float p = __expf(Ss[r * 65 + j] - mnew);
                Ss[r * 65 + j] = p;
                sum += p;
            }
            l_s[r] = l_s[r] * corr + sum;
            m_s[r] = mnew;
            c_s[r] = corr;
        }
        __syncthreads();

        // Rescale O accumulators, then O += P @ V
        #pragma unroll
        for (int i = 0; i < 4; i++) {
            float cf = c_s[ty * 4 + i];
            o[i][0].x *= cf; o[i][0].y *= cf; o[i][0].z *= cf; o[i][0].w *= cf;
            o[i][1].x *= cf; o[i][1].y *= cf; o[i][1].z *= cf; o[i][1].w *= cf;
        }
        #pragma unroll 4
        for (int j = 0; j < 64; j++) {
            float4 v0 = *reinterpret_cast<float4*>(Vs + j * 132 + tx * 8);
            float4 v1 = *reinterpret_cast<float4*>(Vs + j * 132 + tx * 8 + 4);
            #pragma unroll
            for (int i = 0; i < 4; i++) {
                float p = Ss[(ty * 4 + i) * 65 + j];
                o[i][0].x += p * v0.x; o[i][0].y += p * v0.y;
                o[i][0].z += p * v0.z; o[i][0].w += p * v0.w;
                o[i][1].x += p * v1.x; o[i][1].y += p * v1.y;
                o[i][1].z += p * v1.z; o[i][1].w += p * v1.w;
            }
        }
        __syncthreads();   // protect Ks/Vs/Ss for next iteration
    }

    // Epilogue: normalize and store (same [B,S,NH*HD] layout)
    #pragma unroll
    for (int i = 0; i < 4; i++) {
        const int r = ty * 4 + i;
        float linv = 1.0f / l_s[r];
        float4 a0 = o[i][0], a1 = o[i][1];
        a0.x *= linv; a0.y *= linv; a0.z *= linv; a0.w *= linv;
        a1.x *= linv; a1.y *= linv; a1.z *= linv; a1.w *= linv;
        float* op = O + (size_t)(b * S_ + q0 + r) * HID_ + (size_t)h * HD_ + tx * 8;
        *reinterpret_cast<float4*>(op)     = a0;
        *reinterpret_cast<float4*>(op + 4) = a1;
    }
}

// ---------------------------------------------------------------------------
// Launch
// ---------------------------------------------------------------------------
extern "C" void kernel_launch(void* const* d_in, const int* in_sizes, int n_in,
                              void* d_out, int out_size) {
    const float* hs  = (const float*)d_in[0];
    const int*   pos = (const int*)  d_in[1];
    const float* wq  = (const float*)d_in[2];
    const float* bq  = (const float*)d_in[3];
    const float* wk  = (const float*)d_in[4];
    const float* bk  = (const float*)d_in[5];
    const float* wv  = (const float*)d_in[6];
    const float* bv  = (const float*)d_in[7];
    const float* wc  = (const float*)d_in[8];
    float* out = (float*)d_out;

    float *qp, *kp, *vp, *ap;
    cudaGetSymbolAddress((void**)&qp, g_q);
    cudaGetSymbolAddress((void**)&kp, g_k);
    cudaGetSymbolAddress((void**)&vp, g_v);
    cudaGetSymbolAddress((void**)&ap, g_attn);

    const int M = B_ * S_;          // 4096
    dim3 ggrid(HID_ / 64, M / 64);  // (32, 64)

    // QKV projections
    gemm_bias_kernel<<<ggrid, 256>>>(hs, wq, bq, qp, M, HID_, HID_);
    gemm_bias_kernel<<<ggrid, 256>>>(hs, wk, bk, kp, M, HID_, HID_);
    gemm_bias_kernel<<<ggrid, 256>>>(hs, wv, bv, vp, M, HID_, HID_);

    // RoPE on Q,K
    int rope_total = B_ * S_ * NH_ * 64;
    rope_kernel<<<rope_total / 256, 256>>>(pos, qp, kp);

    // Attention
    cudaFuncSetAttribute(attn_kernel,
                         cudaFuncAttributeMaxDynamicSharedMemorySize,
                         ATTN_SMEM_BYTES);
    attn_kernel<<<dim3(S_ / 64, B_ * NH_), 256, ATTN_SMEM_BYTES>>>(qp, kp, vp, ap);

    // Output projection
    gemm_bias_kernel<<<ggrid, 256>>>(ap, wc, nullptr, out, M, HID_, HID_);
}

// round 2
// speedup vs baseline: 1.2625x; 1.2625x over previous
#include <cuda_runtime.h>
#include <cstdint>

// Problem constants
constexpr int B_  = 2;
constexpr int S_  = 2048;
constexpr int HID_ = 2048;
constexpr int NH_ = 16;
constexpr int HD_ = 128;
constexpr float SCALING_ = 0.08838834764831845f; // 128^-0.5

// Scratch (allocation-free rule: __device__ globals)
__device__ float g_q[(size_t)B_ * S_ * HID_];
__device__ float g_k[(size_t)B_ * S_ * HID_];
__device__ float g_v[(size_t)B_ * S_ * HID_];
__device__ float g_attn[(size_t)B_ * S_ * HID_];

// ---------------------------------------------------------------------------
// Helpers: cp.async, tf32 mma
// ---------------------------------------------------------------------------
__device__ __forceinline__ void cp_async16(uint32_t s, const void* g) {
    asm volatile("cp.async.cg.shared.global [%0], [%1], 16;" :: "r"(s), "l"(g));
}
__device__ __forceinline__ void cp_commit() {
    asm volatile("cp.async.commit_group;");
}
template <int N>
__device__ __forceinline__ void cp_wait() {
    asm volatile("cp.async.wait_group %0;" :: "n"(N));
}
__device__ __forceinline__ uint32_t f2tf32(float x) {
    uint32_t r;
    asm("cvt.rna.tf32.f32 %0, %1;" : "=r"(r) : "f"(x));
    return r;
}
__device__ __forceinline__ void split_tf32(float x, uint32_t& hi, uint32_t& lo) {
    hi = f2tf32(x);
    float rem = x - __uint_as_float(hi);
    lo = f2tf32(rem);
}
__device__ __forceinline__ void mma_tf32(float& c0, float& c1, float& c2, float& c3,
                                         uint32_t a0, uint32_t a1, uint32_t a2, uint32_t a3,
                                         uint32_t b0, uint32_t b1) {
    asm volatile(
        "mma.sync.aligned.m16n8k8.row.col.f32.tf32.tf32.f32 "
        "{%0,%1,%2,%3}, {%4,%5,%6,%7}, {%8,%9}, {%0,%1,%2,%3};"
        : "+f"(c0), "+f"(c1), "+f"(c2), "+f"(c3)
        : "r"(a0), "r"(a1), "r"(a2), "r"(a3), "r"(b0), "r"(b1));
}

// ---------------------------------------------------------------------------
// 3xTF32 tensor-core GEMM: C[M,N] = A[M,K] @ W[K,N] (+ bias)
// BM=128, BN=128, BK=32, 256 threads (8 warps: 2 x-M, 4 x-N), warp tile 64x32.
// Error ~fp32 via hi/lo tf32 decomposition (3 mmas per product).
// ---------------------------------------------------------------------------
constexpr int GBM = 128, GBN = 128, GBK = 32;
constexpr int A_STR = 36;               // floats per A smem row (pad for banks)
constexpr int B_STR = 136;              // floats per B smem row
constexpr int A_STAGE = GBM * A_STR;    // 4608 floats
constexpr int B_STAGE = GBK * B_STR;    // 4352 floats
constexpr int GEMM_SMEM_FLOATS = 2 * A_STAGE + 2 * B_STAGE;
constexpr int GEMM_SMEM_BYTES = GEMM_SMEM_FLOATS * 4;   // 71680

__global__ void gemm_tf32x3_kernel(const float* __restrict__ A,
                                   const float* __restrict__ W,
                                   const float* __restrict__ bias,
                                   float* __restrict__ C,
                                   int M, int N, int K) {
    extern __shared__ float sm[];
    const uint32_t sbase = (uint32_t)__cvta_generic_to_shared(sm);

    const int tid = threadIdx.x;
    const int lane = tid & 31;
    const int wid = tid >> 5;
    const int warp_m = wid & 1;          // 0..1 (64 rows each)
    const int warp_n = wid >> 1;         // 0..3 (32 cols each)
    const int row0 = blockIdx.y * GBM;
    const int col0 = blockIdx.x * GBN;

    // async tile loader
    auto load_tile = [&](int kt, int stage) {
        uint32_t a_s = sbase + (uint32_t)(stage * A_STAGE) * 4u;
        uint32_t b_s = sbase + (uint32_t)((2 * A_STAGE) + stage * B_STAGE) * 4u;
        #pragma unroll
        for (int i = 0; i < 4; i++) {
            int idx = tid + i * 256;             // 0..1023
            int r = idx >> 3, c4 = idx & 7;
            cp_async16(a_s + (uint32_t)(r * A_STR + c4 * 4) * 4u,
                       A + (size_t)(row0 + r) * K + kt + c4 * 4);
        }
        #pragma unroll
        for (int i = 0; i < 4; i++) {
            int idx = tid + i * 256;
            int r = idx >> 5, c4 = idx & 31;
            cp_async16(b_s + (uint32_t)(r * B_STR + c4 * 4) * 4u,
                       W + (size_t)(kt + r) * N + col0 + c4 * 4);
        }
        cp_commit();
    };

    float acc[4][4][4];
    #pragma unroll
    for (int i = 0; i < 4; i++)
        #pragma unroll
        for (int j = 0; j < 4; j++)
            #pragma unroll
            for (int r = 0; r < 4; r++) acc[i][j][r] = 0.f;

    load_tile(0, 0);

    const int lg = lane >> 2;    // group id 0..7
    const int lc = lane & 3;     // 0..3

    int stage = 0;
    for (int kt = 0; kt < K; kt += GBK, stage ^= 1) {
        if (kt + GBK < K) {
            load_tile(kt + GBK, stage ^ 1);
            cp_wait<1>();
        } else {
            cp_wait<0>();
        }
        __syncthreads();

        const float* Asb = sm + stage * A_STAGE;
        const float* Bsb = sm + 2 * A_STAGE + stage * B_STAGE;

        #pragma unroll
        for (int ks = 0; ks < 4; ks++) {
            const int k8 = ks * 8;
            // A fragments (4 m-tiles) -> hi/lo
            uint32_t ahi[4][4], alo[4][4];
            #pragma unroll
            for (int mt = 0; mt < 4; mt++) {
                int rb = warp_m * 64 + mt * 16 + lg;
                float x0 = Asb[rb * A_STR + k8 + lc];
                float x1 = Asb[(rb + 8) * A_STR + k8 + lc];
                float x2 = Asb[rb * A_STR + k8 + 4 + lc];
                float x3 = Asb[(rb + 8) * A_STR + k8 + 4 + lc];
                split_tf32(x0, ahi[mt][0], alo[mt][0]);
                split_tf32(x1, ahi[mt][1], alo[mt][1]);
                split_tf32(x2, ahi[mt][2], alo[mt][2]);
                split_tf32(x3, ahi[mt][3], alo[mt][3]);
            }
            // B fragments (4 n-tiles) -> hi/lo
            uint32_t bhi[4][2], blo[4][2];
            #pragma unroll
            for (int nt = 0; nt < 4; nt++) {
                int cb = warp_n * 32 + nt * 8 + lg;
                float y0 = Bsb[(k8 + lc) * B_STR + cb];
                float y1 = Bsb[(k8 + 4 + lc) * B_STR + cb];
                split_tf32(y0, bhi[nt][0], blo[nt][0]);
                split_tf32(y1, bhi[nt][1], blo[nt][1]);
            }
            // 3xTF32 mmas
            #pragma unroll
            for (int mt = 0; mt < 4; mt++)
                #pragma unroll
                for (int nt = 0; nt < 4; nt++) {
                    float* c = acc[mt][nt];
                    mma_tf32(c[0], c[1], c[2], c[3],
                             ahi[mt][0], ahi[mt][1], ahi[mt][2], ahi[mt][3],
                             bhi[nt][0], bhi[nt][1]);
                    mma_tf32(c[0], c[1], c[2], c[3],
                             ahi[mt][0], ahi[mt][1], ahi[mt][2], ahi[mt][3],
                             blo[nt][0], blo[nt][1]);
                    mma_tf32(c[0], c[1], c[2], c[3],
                             alo[mt][0], alo[mt][1], alo[mt][2], alo[mt][3],
                             bhi[nt][0], bhi[nt][1]);
                }
        }
        __syncthreads();
    }

    // Epilogue: c0/c1 at (row, 2*lc), (row, 2*lc+1); c2/c3 at (row+8, ...)
    #pragma unroll
    for (int mt = 0; mt < 4; mt++) {
        int grow = row0 + warp_m * 64 + mt * 16 + lg;
        #pragma unroll
        for (int nt = 0; nt < 4; nt++) {
            int gcol = col0 + warp_n * 32 + nt * 8 + lc * 2;
            float b0 = 0.f, b1 = 0.f;
            if (bias != nullptr) {
                b0 = bias[gcol];
                b1 = bias[gcol + 1];
            }
            float2 r0 = make_float2(acc[mt][nt][0] + b0, acc[mt][nt][1] + b1);
            float2 r1 = make_float2(acc[mt][nt][2] + b0, acc[mt][nt][3] + b1);
            *reinterpret_cast<float2*>(C + (size_t)grow * N + gcol) = r0;
            *reinterpret_cast<float2*>(C + (size_t)(grow + 8) * N + gcol) = r1;
        }
    }
}

// ---------------------------------------------------------------------------
// NeoX RoPE applied in-place to Q and K.
// ---------------------------------------------------------------------------
__global__ void rope_kernel(const int* __restrict__ pos,
                            float* __restrict__ Q,
                            float* __restrict__ Kb) {
    int idx = blockIdx.x * blockDim.x + threadIdx.x;   // total B*S*NH*64
    int d  = idx & 63;
    int h  = (idx >> 6) & (NH_ - 1);
    int bs = idx >> 10;                                // b*S + s
    if (bs >= B_ * S_) return;

    int p = pos[bs];
    float inv_freq = 1.0f / powf(10000.0f, (float)d * (2.0f / (float)HD_));
    float f = (float)p * inv_freq;
    float sn, cs;
    sincosf(f, &sn, &cs);

    size_t base = (size_t)bs * HID_ + (size_t)h * HD_;
    float q1 = Q[base + d],       q2 = Q[base + 64 + d];
    Q[base + d]      = q1 * cs - q2 * sn;
    Q[base + 64 + d] = q2 * cs + q1 * sn;
    float k1 = Kb[base + d],      k2 = Kb[base + 64 + d];
    Kb[base + d]      = k1 * cs - k2 * sn;
    Kb[base + 64 + d] = k2 * cs + k1 * sn;
}

// ---------------------------------------------------------------------------
// Causal flash attention (fp32, online softmax). Unchanged from R1.
// ---------------------------------------------------------------------------
constexpr int ATTN_SMEM_FLOATS = 3 * 64 * 132 + 64 * 65 + 3 * 64;
constexpr int ATTN_SMEM_BYTES  = ATTN_SMEM_FLOATS * 4;

__global__ void attn_kernel(const float* __restrict__ Q,
                            const float* __restrict__ K,
                            const float* __restrict__ V,
                            float* __restrict__ O) {
    extern __shared__ float smf[];
    float* Qs  = smf;                     // 64*132
    float* Ks  = Qs + 64 * 132;
    float* Vs  = Ks + 64 * 132;
    float* Ss  = Vs + 64 * 132;           // 64*65
    float* m_s = Ss + 64 * 65;            // 64
    float* l_s = m_s + 64;                // 64
    float* c_s = l_s + 64;                // 64

    const int tid = threadIdx.x;
    const int tx = tid & 15;
    const int ty = tid >> 4;
    const int bh = blockIdx.y;
    const int b  = bh / NH_;
    const int h  = bh % NH_;
    const int q0 = blockIdx.x * 64;

    const float* qb = Q + (size_t)(b * S_) * HID_ + (size_t)h * HD_;
    const float* kb = K + (size_t)(b * S_) * HID_ + (size_t)h * HD_;
    const float* vb = V + (size_t)(b * S_) * HID_ + (size_t)h * HD_;

    for (int t = tid; t < 64 * 32; t += 256) {
        int r = t >> 5, c4 = t & 31;
        *reinterpret_cast<float4*>(Qs + r * 132 + c4 * 4) =
            *reinterpret_cast<const float4*>(qb + (size_t)(q0 + r) * HID_ + c4 * 4);
    }
    if (tid < 64) { m_s[tid] = -1e30f; l_s[tid] = 0.f; }
    __syncthreads();

    float4 o[4][2];
    #pragma unroll
    for (int i = 0; i < 4; i++) {
        o[i][0] = make_float4(0.f, 0.f, 0.f, 0.f);
        o[i][1] = make_float4(0.f, 0.f, 0.f, 0.f);
    }

    const int ntiles = blockIdx.x + 1;
    for (int t = 0; t < ntiles; t++) {
        const int k0 = t * 64;
        for (int u = tid; u < 64 * 32; u += 256) {
            int r = u >> 5, c4 = u & 31;
            *reinterpret_cast<float4*>(Ks + r * 132 + c4 * 4) =
                *reinterpret_cast<const float4*>(kb + (size_t)(k0 + r) * HID_ + c4 * 4);
            *reinterpret_cast<float4*>(Vs + r * 132 + c4 * 4) =
                *reinterpret_cast<const float4*>(vb + (size_t)(k0 + r) * HID_ + c4 * 4);
        }
        __syncthreads();

        float acc[4][4] = {};
        #pragma unroll 4
        for (int k4 = 0; k4 < 32; k4++) {
            float4 qv[4], kv[4];
            #pragma unroll
            for (int i = 0; i < 4; i++)
                qv[i] = *reinterpret_cast<float4*>(Qs + (ty * 4 + i) * 132 + k4 * 4);
            #pragma unroll
            for (int j = 0; j < 4; j++)
                kv[j] = *reinterpret_cast<float4*>(Ks + (tx * 4 + j) * 132 + k4 * 4);
            #pragma unroll
            for (int i = 0; i < 4; i++)
                #pragma unroll
                for (int j = 0; j < 4; j++)
                    acc[i][j] += qv[i].x * kv[j].x + qv[i].y * kv[j].y +
                                 qv[i].z * kv[j].z + qv[i].w * kv[j].w;
        }

        #pragma unroll
        for (int i = 0; i < 4; i++)
            #pragma unroll
            for (int j = 0; j < 4; j++) {
                int gr = q0 + ty * 4 + i;
                int gc = k0 + tx * 4 + j;
                float v = acc[i][j] * SCALING_;
                if (gc > gr) v = -1e30f;
                Ss[(ty * 4 + i) * 65 + tx * 4 + j] = v;
            }
        __syncthreads();

        if (tid < 64) {
            const int r = tid;
            float mold = m_s[r];
            float tm = -1e30f;
            for (int j = 0; j < 64; j++) tm = fmaxf(tm, Ss[r * 65 + j]);
            float mnew = fmaxf(mold, tm);
            float corr = __expf(mold - mnew);
            float sum = 0.f;
            for (int j = 0; j < 64; j++) {
                float p = __expf(Ss[r * 65 + j] - mnew);
                Ss[r * 65 + j] = p;
                sum += p;
            }
            l_s[r] = l_s[r] * corr + sum;
            m_s[r] = mnew;
            c_s[r] = corr;
        }
        __syncthreads();

        #pragma unroll
        for (int i = 0; i < 4; i++) {
            float cf = c_s[ty * 4 + i];
            o[i][0].x *= cf; o[i][0].y *= cf; o[i][0].z *= cf; o[i][0].w *= cf;
            o[i][1].x *= cf; o[i][1].y *= cf; o[i][1].z *= cf; o[i][1].w *= cf;
        }
        #pragma unroll 4
        for (int j = 0; j < 64; j++) {
            float4 v0 = *reinterpret_cast<float4*>(Vs + j * 132 + tx * 8);
            float4 v1 = *reinterpret_cast<float4*>(Vs + j * 132 + tx * 8 + 4);
            #pragma unroll
            for (int i = 0; i < 4; i++) {
                float p = Ss[(ty * 4 + i) * 65 + j];
                o[i][0].x += p * v0.x; o[i][0].y += p * v0.y;
                o[i][0].z += p * v0.z; o[i][0].w += p * v0.w;
                o[i][1].x += p * v1.x; o[i][1].y += p * v1.y;
                o[i][1].z += p * v1.z; o[i][1].w += p * v1.w;
            }
        }
        __syncthreads();
    }

    #pragma unroll
    for (int i = 0; i < 4; i++) {
        const int r = ty * 4 + i;
        float linv = 1.0f / l_s[r];
        float4 a0 = o[i][0], a1 = o[i][1];
        a0.x *= linv; a0.y *= linv; a0.z *= linv; a0.w *= linv;
        a1.x *= linv; a1.y *= linv; a1.z *= linv; a1.w *= linv;
        float* op = O + (size_t)(b * S_ + q0 + r) * HID_ + (size_t)h * HD_ + tx * 8;
        *reinterpret_cast<float4*>(op)     = a0;
        *reinterpret_cast<float4*>(op + 4) = a1;
    }
}

// ---------------------------------------------------------------------------
// Launch
// ---------------------------------------------------------------------------
extern "C" void kernel_launch(void* const* d_in, const int* in_sizes, int n_in,
                              void* d_out, int out_size) {
    const float* hs  = (const float*)d_in[0];
    const int*   pos = (const int*)  d_in[1];
    const float* wq  = (const float*)d_in[2];
    const float* bq  = (const float*)d_in[3];
    const float* wk  = (const float*)d_in[4];
    const float* bk  = (const float*)d_in[5];
    const float* wv  = (const float*)d_in[6];
    const float* bv  = (const float*)d_in[7];
    const float* wc  = (const float*)d_in[8];
    float* out = (float*)d_out;

    float *qp, *kp, *vp, *ap;
    cudaGetSymbolAddress((void**)&qp, g_q);
    cudaGetSymbolAddress((void**)&kp, g_k);
    cudaGetSymbolAddress((void**)&vp, g_v);
    cudaGetSymbolAddress((void**)&ap, g_attn);

    const int M = B_ * S_;                      // 4096
    dim3 ggrid(HID_ / GBN, M / GBM);            // (16, 32)

    cudaFuncSetAttribute(gemm_tf32x3_kernel,
                         cudaFuncAttributeMaxDynamicSharedMemorySize,
                         GEMM_SMEM_BYTES);

    // QKV projections (3xTF32 tensor cores)
    gemm_tf32x3_kernel<<<ggrid, 256, GEMM_SMEM_BYTES>>>(hs, wq, bq, qp, M, HID_, HID_);
    gemm_tf32x3_kernel<<<ggrid, 256, GEMM_SMEM_BYTES>>>(hs, wk, bk, kp, M, HID_, HID_);
    gemm_tf32x3_kernel<<<ggrid, 256, GEMM_SMEM_BYTES>>>(hs, wv, bv, vp, M, HID_, HID_);

    // RoPE on Q,K
    int rope_total = B_ * S_ * NH_ * 64;
    rope_kernel<<<rope_total / 256, 256>>>(pos, qp, kp);

    // Attention
    cudaFuncSetAttribute(attn_kernel,
                         cudaFuncAttributeMaxDynamicSharedMemorySize,
                         ATTN_SMEM_BYTES);
    attn_kernel<<<dim3(S_ / 64, B_ * NH_), 256, ATTN_SMEM_BYTES>>>(qp, kp, vp, ap);

    // Output projection
    gemm_tf32x3_kernel<<<ggrid, 256, GEMM_SMEM_BYTES>>>(ap, wc, nullptr, out, M, HID_, HID_);
}

// round 4
// speedup vs baseline: 1.3246x; 1.0492x over previous
#include <cuda_runtime.h>
#include <cstdint>

// Problem constants
constexpr int B_  = 2;
constexpr int S_  = 2048;
constexpr int HID_ = 2048;
constexpr int NH_ = 16;
constexpr int HD_ = 128;
constexpr float SCALING_ = 0.08838834764831845f; // 128^-0.5
constexpr int M_ = B_ * S_;   // 4096
constexpr int KD8_ = HID_ / 8;   // 256 k-steps across K

// Scratch (allocation-free rule: __device__ globals)
__device__ float g_q[(size_t)M_ * HID_];
__device__ float g_k[(size_t)M_ * HID_];
__device__ float g_v[(size_t)M_ * HID_];
__device__ float g_attn[(size_t)M_ * HID_];
// Fragment-packed operands (hi/lo tf32 split):
// Apack: [M/16][K/8][32 lanes][8 floats]  (a0-3 hi, a0-3 lo)
__device__ float g_apack[(size_t)M_ * HID_ * 2];
// Bpack per weight: [N/8][K/8][32 lanes][4 floats] (b0hi,b1hi,b0lo,b1lo)
__device__ float g_bpack[(size_t)4 * HID_ * HID_ * 2];

// ---------------------------------------------------------------------------
// PTX helpers
// ---------------------------------------------------------------------------
__device__ __forceinline__ void cp_async16(uint32_t s, const void* g) {
    asm volatile("cp.async.cg.shared.global [%0], [%1], 16;" :: "r"(s), "l"(g));
}
__device__ __forceinline__ void cp_commit() {
    asm volatile("cp.async.commit_group;");
}
template <int N>
__device__ __forceinline__ void cp_wait() {
    asm volatile("cp.async.wait_group %0;" :: "n"(N));
}
__device__ __forceinline__ void tf32split(float x, float& hi, float& lo) {
    uint32_t h;
    asm("cvt.rna.tf32.f32 %0, %1;" : "=r"(h) : "f"(x));
    hi = __uint_as_float(h);
    uint32_t l;
    asm("cvt.rna.tf32.f32 %0, %1;" : "=r"(l) : "f"(x - hi));
    lo = __uint_as_float(l);
}
__device__ __forceinline__ void mma_tf32(float& c0, float& c1, float& c2, float& c3,
                                         uint32_t a0, uint32_t a1, uint32_t a2, uint32_t a3,
                                         uint32_t b0, uint32_t b1) {
    asm volatile(
        "mma.sync.aligned.m16n8k8.row.col.f32.tf32.tf32.f32 "
        "{%0,%1,%2,%3}, {%4,%5,%6,%7}, {%8,%9}, {%0,%1,%2,%3};"
        : "+f"(c0), "+f"(c1), "+f"(c2), "+f"(c3)
        : "r"(a0), "r"(a1), "r"(a2), "r"(a3), "r"(b0), "r"(b1));
}

// ---------------------------------------------------------------------------
// Pack A (activations): in[M][2048] -> Apack[mt][ks][lane][8]
// One thread per (mt, ks, lane); writes 2 float4 (hi frag, lo frag).
// ---------------------------------------------------------------------------
__global__ void pack_a_kernel(const float* __restrict__ A, float* __restrict__ P) {
    int idx = blockIdx.x * blockDim.x + threadIdx.x;   // (M/16)*256*32
    int lane = idx & 31;
    int t = idx >> 5;
    int ks = t & (KD8_ - 1);
    int mt = t >> 8;
    int lg = lane >> 2, lc = lane & 3;
    int row = mt * 16 + lg;
    int col = ks * 8 + lc;
    float a0 = A[(size_t)row * HID_ + col];
    float a1 = A[(size_t)(row + 8) * HID_ + col];
    float a2 = A[(size_t)row * HID_ + col + 4];
    float a3 = A[(size_t)(row + 8) * HID_ + col + 4];
    float4 h4, l4;
    tf32split(a0, h4.x, l4.x);
    tf32split(a1, h4.y, l4.y);
    tf32split(a2, h4.z, l4.z);
    tf32split(a3, h4.w, l4.w);
    float* dst = P + (size_t)idx * 8;
    *reinterpret_cast<float4*>(dst)     = h4;
    *reinterpret_cast<float4*>(dst + 4) = l4;
}

// ---------------------------------------------------------------------------
// Pack B (weights): W[K=2048][N=2048] -> Bpack[nt][ks][lane][4]
// b0 = W[k0+lc][n0+lg], b1 = W[k0+4+lc][n0+lg]; pack {b0h, b1h, b0l, b1l}.
// ---------------------------------------------------------------------------
__global__ void pack_b_kernel(const float* __restrict__ W, float* __restrict__ P) {
    int idx = blockIdx.x * blockDim.x + threadIdx.x;   // (N/8)*256*32
    int lane = idx & 31;
    int t = idx >> 5;
    int ks = t & (KD8_ - 1);
    int nt = t >> 8;
    int lg = lane >> 2, lc = lane & 3;
    int n = nt * 8 + lg;
    int k = ks * 8 + lc;
    float b0 = W[(size_t)k * HID_ + n];
    float b1 = W[(size_t)(k + 4) * HID_ + n];
    float4 v;
    tf32split(b0, v.x, v.z);
    tf32split(b1, v.y, v.w);
    *reinterpret_cast<float4*>(P + (size_t)idx * 4) = v;
}

// ---------------------------------------------------------------------------
// 3xTF32 mma.sync GEMM on fragment-packed operands.
// CTA tile 128x128, BK=32 (4 k-steps), 256 threads (8 warps: 2m x 4n),
// warp tile 64x32. 3-stage cp.async pipeline. smem/stage = 64KB (A 32K, B 32K).
// ---------------------------------------------------------------------------
constexpr int NT_IT = HID_ / 32;          // 64 K-tiles
constexpr uint32_t STAGE_B = 65536;
constexpr int GEMM_DSMEM = 3 * STAGE_B;   // 196608

__global__ void __launch_bounds__(256, 1)
gemm_tc_kernel(const float* __restrict__ Apack, const float* __restrict__ Bpack,
               const float* __restrict__ bias, float* __restrict__ C) {
    extern __shared__ __align__(16) char dsm[];
    const uint32_t sb = (uint32_t)__cvta_generic_to_shared(dsm);

    const int tid = threadIdx.x;
    const int lane = tid & 31;
    const int wid = tid >> 5;
    const int warp_m = wid & 1;
    const int warp_n = wid >> 1;
    const int row0 = blockIdx.y * 128;
    const int col0 = blockIdx.x * 128;
    const int lg = lane >> 2, lc = lane & 3;

    // Base pointers into packed global for this CTA
    const float* Ab = Apack + ((size_t)(row0 >> 4) * KD8_) * 256;   // + kt*4*256
    const float* Bb = Bpack + ((size_t)(col0 >> 3) * KD8_) * 128;   // + kt*4*128

    auto load_stage = [&](int kt, int s) {
        uint32_t sa = sb + (uint32_t)s * STAGE_B;
        uint32_t sbm = sa + 32768;
        const float* Abase = Ab + (size_t)kt * 1024;   // kt*4 ksteps * 256 floats
        const float* Bbase = Bb + (size_t)kt * 512;
        #pragma unroll
        for (int i = 0; i < 8; i++) {          // A: 2048 x 16B
            int c = tid + i * 256;
            int mt = c >> 8, inner = c & 255;
            cp_async16(sa + (uint32_t)c * 16,
                       Abase + (size_t)mt * (KD8_ * 256) + inner * 4);
        }
        #pragma unroll
        for (int i = 0; i < 8; i++) {          // B: 2048 x 16B
            int c = tid + i * 256;
            int nt = c >> 7, inner = c & 127;
            cp_async16(sbm + (uint32_t)c * 16,
                       Bbase + (size_t)nt * (KD8_ * 128) + inner * 4);
        }
        cp_commit();
    };

    float acc[4][4][4];
    #pragma unroll
    for (int i = 0; i < 4; i++)
        #pragma unroll
        for (int j = 0; j < 4; j++)
            #pragma unroll
            for (int r = 0; r < 4; r++) acc[i][j][r] = 0.f;

    load_stage(0, 0);
    load_stage(1, 1);
    load_stage(2, 2);

    for (int kt = 0; kt < NT_IT; kt++) {
        const int s = kt % 3;
        cp_wait<2>();
        __syncthreads();

        const float* sa_f = reinterpret_cast<const float*>(dsm + (size_t)s * STAGE_B);
        const float* sb_f = sa_f + 8192;

        #pragma unroll
        for (int ks = 0; ks < 4; ks++) {
            float4 ah[4], al[4], bf[4];
            #pragma unroll
            for (int mt = 0; mt < 4; mt++) {
                const float4* p = reinterpret_cast<const float4*>(
                    sa_f + ((((warp_m * 4 + mt) * 4 + ks) * 32 + lane) << 3));
                ah[mt] = p[0];
                al[mt] = p[1];
            }
            #pragma unroll
            for (int nt = 0; nt < 4; nt++) {
                bf[nt] = *reinterpret_cast<const float4*>(
                    sb_f + ((((warp_n * 4 + nt) * 4 + ks) * 32 + lane) << 2));
            }
            #pragma unroll
            for (int mt = 0; mt < 4; mt++) {
                uint32_t ah0 = __float_as_uint(ah[mt].x), ah1 = __float_as_uint(ah[mt].y);
                uint32_t ah2 = __float_as_uint(ah[mt].z), ah3 = __float_as_uint(ah[mt].w);
                uint32_t al0 = __float_as_uint(al[mt].x), al1 = __float_as_uint(al[mt].y);
                uint32_t al2 = __float_as_uint(al[mt].z), al3 = __float_as_uint(al[mt].w);
                #pragma unroll
                for (int nt = 0; nt < 4; nt++) {
                    uint32_t bh0 = __float_as_uint(bf[nt].x), bh1 = __float_as_uint(bf[nt].y);
                    uint32_t bl0 = __float_as_uint(bf[nt].z), bl1 = __float_as_uint(bf[nt].w);
                    float* c = acc[mt][nt];
                    mma_tf32(c[0], c[1], c[2], c[3], ah0, ah1, ah2, ah3, bh0, bh1);
                    mma_tf32(c[0], c[1], c[2], c[3], ah0, ah1, ah2, ah3, bl0, bl1);
                    mma_tf32(c[0], c[1], c[2], c[3], al0, al1, al2, al3, bh0, bh1);
                }
            }
        }
        __syncthreads();
        if (kt + 3 < NT_IT) load_stage(kt + 3, s);
    }

    // Epilogue: registers -> gmem (float2 per fragment row)
    #pragma unroll
    for (int mt = 0; mt < 4; mt++) {
        int grow = row0 + (warp_m * 4 + mt) * 16 + lg;
        #pragma unroll
        for (int nt = 0; nt < 4; nt++) {
            int gcol = col0 + (warp_n * 4 + nt) * 8 + lc * 2;
            float b0 = 0.f, b1 = 0.f;
            if (bias != nullptr) {
                b0 = bias[gcol];
                b1 = bias[gcol + 1];
            }
            float2 r0 = make_float2(acc[mt][nt][0] + b0, acc[mt][nt][1] + b1);
            float2 r1 = make_float2(acc[mt][nt][2] + b0, acc[mt][nt][3] + b1);
            *reinterpret_cast<float2*>(C + (size_t)grow * HID_ + gcol) = r0;
            *reinterpret_cast<float2*>(C + (size_t)(grow + 8) * HID_ + gcol) = r1;
        }
    }
}

// ---------------------------------------------------------------------------
// NeoX RoPE applied in-place to Q and K.
// ---------------------------------------------------------------------------
__global__ void rope_kernel(const int* __restrict__ pos,
                            float* __restrict__ Q,
                            float* __restrict__ Kb) {
    int idx = blockIdx.x * blockDim.x + threadIdx.x;
    int d  = idx & 63;
    int h  = (idx >> 6) & (NH_ - 1);
    int bs = idx >> 10;
    if (bs >= B_ * S_) return;

    int p = pos[bs];
    float inv_freq = 1.0f / powf(10000.0f, (float)d * (2.0f / (float)HD_));
    float f = (float)p * inv_freq;
    float sn, cs;
    sincosf(f, &sn, &cs);

    size_t base = (size_t)bs * HID_ + (size_t)h * HD_;
    float q1 = Q[base + d],  q2 = Q[base + 64 + d];
    Q[base + d]      = q1 * cs - q2 * sn;
    Q[base + 64 + d] = q2 * cs + q1 * sn;
    float k1 = Kb[base + d], k2 = Kb[base + 64 + d];
    Kb[base + d]      = k1 * cs - k2 * sn;
    Kb[base + 64 + d] = k2 * cs + k1 * sn;
}

// ---------------------------------------------------------------------------
// Causal flash attention (fp32, online softmax). Unchanged (R2-validated).
// ---------------------------------------------------------------------------
constexpr int ATTN_SMEM_FLOATS = 3 * 64 * 132 + 64 * 65 + 3 * 64;
constexpr int ATTN_SMEM_BYTES  = ATTN_SMEM_FLOATS * 4;

__global__ void attn_kernel(const float* __restrict__ Q,
                            const float* __restrict__ K,
                            const float* __restrict__ V,
                            float* __restrict__ O) {
    extern __shared__ float smf[];
    float* Qs  = smf;
    float* Ks  = Qs + 64 * 132;
    float* Vs  = Ks + 64 * 132;
    float* Ss  = Vs + 64 * 132;
    float* m_s = Ss + 64 * 65;
    float* l_s = m_s + 64;
    float* c_s = l_s + 64;

    const int tid = threadIdx.x;
    const int tx = tid & 15;
    const int ty = tid >> 4;
    const int bh = blockIdx.y;
    const int b  = bh / NH_;
    const int h  = bh % NH_;
    const int q0 = blockIdx.x * 64;

    const float* qb = Q + (size_t)(b * S_) * HID_ + (size_t)h * HD_;
    const float* kb = K + (size_t)(b * S_) * HID_ + (size_t)h * HD_;
    const float* vb = V + (size_t)(b * S_) * HID_ + (size_t)h * HD_;

    for (int t = tid; t < 64 * 32; t += 256) {
        int r = t >> 5, c4 = t & 31;
        *reinterpret_cast<float4*>(Qs + r * 132 + c4 * 4) =
            *reinterpret_cast<const float4*>(qb + (size_t)(q0 + r) * HID_ + c4 * 4);
    }
    if (tid < 64) { m_s[tid] = -1e30f; l_s[tid] = 0.f; }
    __syncthreads();

    float4 o[4][2];
    #pragma unroll
    for (int i = 0; i < 4; i++) {
        o[i][0] = make_float4(0.f, 0.f, 0.f, 0.f);
        o[i][1] = make_float4(0.f, 0.f, 0.f, 0.f);
    }

    const int ntiles = blockIdx.x + 1;
    for (int t = 0; t < ntiles; t++) {
        const int k0 = t * 64;
        for (int u = tid; u < 64 * 32; u += 256) {
            int r = u >> 5, c4 = u & 31;
            *reinterpret_cast<float4*>(Ks + r * 132 + c4 * 4) =
                *reinterpret_cast<const float4*>(kb + (size_t)(k0 + r) * HID_ + c4 * 4);
            *reinterpret_cast<float4*>(Vs + r * 132 + c4 * 4) =
                *reinterpret_cast<const float4*>(vb + (size_t)(k0 + r) * HID_ + c4 * 4);
        }
        __syncthreads();

        float acc[4][4] = {};
        #pragma unroll 4
        for (int k4 = 0; k4 < 32; k4++) {
            float4 qv[4], kv[4];
            #pragma unroll
            for (int i = 0; i < 4; i++)
                qv[i] = *reinterpret_cast<float4*>(Qs + (ty * 4 + i) * 132 + k4 * 4);
            #pragma unroll
            for (int j = 0; j < 4; j++)
                kv[j] = *reinterpret_cast<float4*>(Ks + (tx * 4 + j) * 132 + k4 * 4);
            #pragma unroll
            for (int i = 0; i < 4; i++)
                #pragma unroll
                for (int j = 0; j < 4; j++)
                    acc[i][j] += qv[i].x * kv[j].x + qv[i].y * kv[j].y +
                                 qv[i].z * kv[j].z + qv[i].w * kv[j].w;
        }

        #pragma unroll
        for (int i = 0; i < 4; i++)
            #pragma unroll
            for (int j = 0; j < 4; j++) {
                int gr = q0 + ty * 4 + i;
                int gc = k0 + tx * 4 + j;
                float v = acc[i][j] * SCALING_;
                if (gc > gr) v = -1e30f;
                Ss[(ty * 4 + i) * 65 + tx * 4 + j] = v;
            }
        __syncthreads();

        if (tid < 64) {
            const int r = tid;
            float mold = m_s[r];
            float tm = -1e30f;
            for (int j = 0; j < 64; j++) tm = fmaxf(tm, Ss[r * 65 + j]);
            float mnew = fmaxf(mold, tm);
            float corr = __expf(mold - mnew);
            float sum = 0.f;
            for (int j = 0; j < 64; j++) {
                float p = __expf(Ss[r * 65 + j] - mnew);
                Ss[r * 65 + j] = p;
                sum += p;
            }
            l_s[r] = l_s[r] * corr + sum;
            m_s[r] = mnew;
            c_s[r] = corr;
        }
        __syncthreads();

        #pragma unroll
        for (int i = 0; i < 4; i++) {
            float cf = c_s[ty * 4 + i];
            o[i][0].x *= cf; o[i][0].y *= cf; o[i][0].z *= cf; o[i][0].w *= cf;
            o[i][1].x *= cf; o[i][1].y *= cf; o[i][1].z *= cf; o[i][1].w *= cf;
        }
        #pragma unroll 4
        for (int j = 0; j < 64; j++) {
            float4 v0 = *reinterpret_cast<float4*>(Vs + j * 132 + tx * 8);
            float4 v1 = *reinterpret_cast<float4*>(Vs + j * 132 + tx * 8 + 4);
            #pragma unroll
            for (int i = 0; i < 4; i++) {
                float p = Ss[(ty * 4 + i) * 65 + j];
                o[i][0].x += p * v0.x; o[i][0].y += p * v0.y;
                o[i][0].z += p * v0.z; o[i][0].w += p * v0.w;
                o[i][1].x += p * v1.x; o[i][1].y += p * v1.y;
                o[i][1].z += p * v1.z; o[i][1].w += p * v1.w;
            }
        }
        __syncthreads();
    }

    #pragma unroll
    for (int i = 0; i < 4; i++) {
        const int r = ty * 4 + i;
        float linv = 1.0f / l_s[r];
        float4 a0 = o[i][0], a1 = o[i][1];
        a0.x *= linv; a0.y *= linv; a0.z *= linv; a0.w *= linv;
        a1.x *= linv; a1.y *= linv; a1.z *= linv; a1.w *= linv;
        float* op = O + (size_t)(b * S_ + q0 + r) * HID_ + (size_t)h * HD_ + tx * 8;
        *reinterpret_cast<float4*>(op)     = a0;
        *reinterpret_cast<float4*>(op + 4) = a1;
    }
}

// ---------------------------------------------------------------------------
// Launch
// ---------------------------------------------------------------------------
extern "C" void kernel_launch(void* const* d_in, const int* in_sizes, int n_in,
                              void* d_out, int out_size) {
    const float* hs  = (const float*)d_in[0];
    const int*   pos = (const int*)  d_in[1];
    const float* wq  = (const float*)d_in[2];
    const float* bq  = (const float*)d_in[3];
    const float* wk  = (const float*)d_in[4];
    const float* bk  = (const float*)d_in[5];
    const float* wv  = (const float*)d_in[6];
    const float* bv  = (const float*)d_in[7];
    const float* wc  = (const float*)d_in[8];
    float* out = (float*)d_out;

    float *qp, *kp, *vp, *ap, *apack, *bpack;
    cudaGetSymbolAddress((void**)&qp, g_q);
    cudaGetSymbolAddress((void**)&kp, g_k);
    cudaGetSymbolAddress((void**)&vp, g_v);
    cudaGetSymbolAddress((void**)&ap, g_attn);
    cudaGetSymbolAddress((void**)&apack, g_apack);
    cudaGetSymbolAddress((void**)&bpack, g_bpack);

    const size_t BPSZ = (size_t)HID_ * HID_ * 2;   // floats per packed weight

    cudaFuncSetAttribute(gemm_tc_kernel,
                         cudaFuncAttributeMaxDynamicSharedMemorySize, GEMM_DSMEM);
    cudaFuncSetAttribute(attn_kernel,
                         cudaFuncAttributeMaxDynamicSharedMemorySize, ATTN_SMEM_BYTES);

    // Pack weights (fragment layout + tf32 hi/lo split)
    const int pb_blocks = (HID_ / 8) * KD8_ * 32 / 256;   // 8192
    pack_b_kernel<<<pb_blocks, 256>>>(wq, bpack + 0 * BPSZ);
    pack_b_kernel<<<pb_blocks, 256>>>(wk, bpack + 1 * BPSZ);
    pack_b_kernel<<<pb_blocks, 256>>>(wv, bpack + 2 * BPSZ);
    pack_b_kernel<<<pb_blocks, 256>>>(wc, bpack + 3 * BPSZ);

    // Pack activations
    const int pa_blocks = (M_ / 16) * KD8_ * 32 / 256;    // 8192
    pack_a_kernel<<<pa_blocks, 256>>>(hs, apack);

    dim3 ggrid(HID_ / 128, M_ / 128);   // (16, 32)
    gemm_tc_kernel<<<ggrid, 256, GEMM_DSMEM>>>(apack, bpack + 0 * BPSZ, bq, qp);
    gemm_tc_kernel<<<ggrid, 256, GEMM_DSMEM>>>(apack, bpack + 1 * BPSZ, bk, kp);
    gemm_tc_kernel<<<ggrid, 256, GEMM_DSMEM>>>(apack, bpack + 2 * BPSZ, bv, vp);

    // RoPE
    int rope_total = B_ * S_ * NH_ * 64;
    rope_kernel<<<rope_total / 256, 256>>>(pos, qp, kp);

    // Attention
    attn_kernel<<<dim3(S_ / 64, B_ * NH_), 256, ATTN_SMEM_BYTES>>>(qp, kp, vp, ap);

    // Output projection
    pack_a_kernel<<<pa_blocks, 256>>>(ap, apack);
    gemm_tc_kernel<<<ggrid, 256, GEMM_DSMEM>>>(apack, bpack + 3 * BPSZ, nullptr, out);
}

// round 5
// speedup vs baseline: 1.6593x; 1.2527x over previous
#include <cuda_runtime.h>
#include <cuda_fp16.h>
#include <cstdint>

// Problem constants
constexpr int B_  = 2;
constexpr int S_  = 2048;
constexpr int HID_ = 2048;
constexpr int NH_ = 16;
constexpr int HD_ = 128;
constexpr float SCALING_ = 0.08838834764831845f; // 128^-0.5
constexpr int M_ = B_ * S_;      // 4096
constexpr int KS16_ = HID_ / 16; // 128 k16-steps across K
constexpr float LO_SCALE = 4096.f;
constexpr float INV_LO  = 1.f / 4096.f;

// Scratch (allocation-free rule: __device__ globals)
__device__ float g_q[(size_t)M_ * HID_];
__device__ float g_k[(size_t)M_ * HID_];
__device__ float g_v[(size_t)M_ * HID_];
__device__ float g_attn[(size_t)M_ * HID_];
// Fragment-packed fp16 hi/lo operands:
// Apack: [M/16][K/16][32 lanes][16 halfs] (8 hi frag, 8 lo frag)
__device__ __half g_apack[(size_t)M_ * HID_ * 2];
// Bpack per weight: [N/8][K/16][32 lanes][8 halfs] (4 hi, 4 lo)
__device__ __half g_bpack[(size_t)4 * HID_ * HID_ * 2];

// ---------------------------------------------------------------------------
// PTX helpers
// ---------------------------------------------------------------------------
__device__ __forceinline__ void cp_async16(uint32_t s, const void* g) {
    asm volatile("cp.async.cg.shared.global [%0], [%1], 16;" :: "r"(s), "l"(g));
}
__device__ __forceinline__ void cp_commit() {
    asm volatile("cp.async.commit_group;");
}
template <int N>
__device__ __forceinline__ void cp_wait() {
    asm volatile("cp.async.wait_group %0;" :: "n"(N));
}
__device__ __forceinline__ void mma_f16(float* c, uint4 a, uint32_t b0, uint32_t b1) {
    asm volatile(
        "mma.sync.aligned.m16n8k16.row.col.f32.f16.f16.f32 "
        "{%0,%1,%2,%3}, {%4,%5,%6,%7}, {%8,%9}, {%0,%1,%2,%3};"
        : "+f"(c[0]), "+f"(c[1]), "+f"(c[2]), "+f"(c[3])
        : "r"(a.x), "r"(a.y), "r"(a.z), "r"(a.w), "r"(b0), "r"(b1));
}
__device__ __forceinline__ void h_split(float x, __half& hi, __half& lo) {
    hi = __float2half_rn(x);
    lo = __float2half_rn((x - __half2float(hi)) * LO_SCALE);
}

// ---------------------------------------------------------------------------
// Pack A (activations): A[M][2048] -> Apack[mt][ks16][lane][16 halfs]
// m16n8k16 A-fragment order: {x0,x1},{x2,x3},{x4,x5},{x6,x7} hi then lo.
// ---------------------------------------------------------------------------
__global__ void pack_a_kernel(const float* __restrict__ A, __half* __restrict__ P) {
    int idx = blockIdx.x * blockDim.x + threadIdx.x;   // (M/16)*(K/16)*32
    int lane = idx & 31;
    int t = idx >> 5;
    int ks = t & (KS16_ - 1);
    int mt = t >> 7;
    int lg = lane >> 2, lc = lane & 3;
    int row = mt * 16 + lg;
    int col = ks * 16 + lc * 2;
    const float* r0 = A + (size_t)row * HID_ + col;
    const float* r1 = A + (size_t)(row + 8) * HID_ + col;
    float x[8] = { r0[0], r0[1], r1[0], r1[1], r0[8], r0[9], r1[8], r1[9] };
    __half out[16];
    #pragma unroll
    for (int i = 0; i < 8; i++) h_split(x[i], out[i], out[8 + i]);
    uint4* dst = reinterpret_cast<uint4*>(P + (size_t)idx * 16);
    dst[0] = *reinterpret_cast<uint4*>(&out[0]);
    dst[1] = *reinterpret_cast<uint4*>(&out[8]);
}

// ---------------------------------------------------------------------------
// Pack B (weights): W[K][N] -> Bpack[nt][ks16][lane][8 halfs]
// B-fragment (col): {y0,y1},{y2,y3} hi then lo; y = W[k0+{2lc,2lc+1,2lc+8,2lc+9}][n]
// ---------------------------------------------------------------------------
__global__ void pack_b_kernel(const float* __restrict__ W, __half* __restrict__ P) {
    int idx = blockIdx.x * blockDim.x + threadIdx.x;   // (N/8)*(K/16)*32
    int lane = idx & 31;
    int t = idx >> 5;
    int ks = t & (KS16_ - 1);
    int nt = t >> 7;
    int lg = lane >> 2, lc = lane & 3;
    int n = nt * 8 + lg;
    int k = ks * 16 + lc * 2;
    float y0 = W[(size_t)k * HID_ + n];
    float y1 = W[(size_t)(k + 1) * HID_ + n];
    float y2 = W[(size_t)(k + 8) * HID_ + n];
    float y3 = W[(size_t)(k + 9) * HID_ + n];
    __half out[8];
    h_split(y0, out[0], out[4]);
    h_split(y1, out[1], out[5]);
    h_split(y2, out[2], out[6]);
    h_split(y3, out[3], out[7]);
    *reinterpret_cast<uint4*>(P + (size_t)idx * 8) = *reinterpret_cast<uint4*>(&out[0]);
}

// ---------------------------------------------------------------------------
// fp16 3-pass GEMM on fragment-packed operands (fp32-accurate).
// CTA tile 128x128, BK=32 (2 k16-steps), 256 threads (8 warps: 2m x 4n),
// warp tile 64x32. 3-stage cp.async pipeline, 32KB/stage.
// acc = acc_hi + acc_lo/4096  (lo terms pre-scaled by 4096 at pack time)
// ---------------------------------------------------------------------------
constexpr int NT_IT = HID_ / 32;          // 64 K-tiles
constexpr uint32_t STAGE_B = 32768;       // A 16KB + B 16KB
constexpr int GEMM_DSMEM = 3 * STAGE_B;   // 98304

__global__ void __launch_bounds__(256, 1)
gemm_tc_kernel(const __half* __restrict__ Apack, const __half* __restrict__ Bpack,
               const float* __restrict__ bias, float* __restrict__ C) {
    extern __shared__ __align__(16) char dsm[];
    const uint32_t sb = (uint32_t)__cvta_generic_to_shared(dsm);

    const int tid = threadIdx.x;
    const int lane = tid & 31;
    const int wid = tid >> 5;
    const int warp_m = wid & 1;
    const int warp_n = wid >> 1;
    const int row0 = blockIdx.y * 128;
    const int col0 = blockIdx.x * 128;
    const int lg = lane >> 2, lc = lane & 3;

    // Packed global bases for this CTA
    const __half* Ab = Apack + (size_t)(row0 >> 4) * (KS16_ * 32 * 16);  // per mt: 65536 halfs
    const __half* Bb = Bpack + (size_t)(col0 >> 3) * (KS16_ * 32 * 8);   // per nt: 32768 halfs

    auto load_stage = [&](int kt, int s) {
        uint32_t sa = sb + (uint32_t)s * STAGE_B;
        uint32_t sbm = sa + 16384;
        const __half* Abase = Ab + (size_t)kt * 1024;   // 2 ks16 * 32 * 16 halfs
        const __half* Bbase = Bb + (size_t)kt * 512;    // 2 ks16 * 32 * 8 halfs
        #pragma unroll
        for (int i = 0; i < 4; i++) {          // A: 1024 x 16B
            int c = tid + i * 256;
            int mt = c >> 7, inner = c & 127;
            cp_async16(sa + (uint32_t)c * 16,
                       Abase + (size_t)mt * 65536 + inner * 8);
        }
        #pragma unroll
        for (int i = 0; i < 4; i++) {          // B: 1024 x 16B
            int c = tid + i * 256;
            int nt = c >> 6, inner = c & 63;
            cp_async16(sbm + (uint32_t)c * 16,
                       Bbase + (size_t)nt * 32768 + inner * 8);
        }
        cp_commit();
    };

    float acch[4][4][4], accl[4][4][4];
    #pragma unroll
    for (int i = 0; i < 4; i++)
        #pragma unroll
        for (int j = 0; j < 4; j++)
            #pragma unroll
            for (int r = 0; r < 4; r++) { acch[i][j][r] = 0.f; accl[i][j][r] = 0.f; }

    load_stage(0, 0);
    load_stage(1, 1);
    load_stage(2, 2);

    for (int kt = 0; kt < NT_IT; kt++) {
        const int s = kt % 3;
        cp_wait<2>();
        __syncthreads();

        const uint4* sa_v = reinterpret_cast<const uint4*>(dsm + (size_t)s * STAGE_B);
        const uint4* sb_v = reinterpret_cast<const uint4*>(dsm + (size_t)s * STAGE_B + 16384);

        #pragma unroll
        for (int ks = 0; ks < 2; ks++) {
            uint4 ah[4], al[4], bf[4];
            #pragma unroll
            for (int mt = 0; mt < 4; mt++) {
                int base = (((warp_m * 4 + mt) * 2 + ks) * 32 + lane) * 2;
                ah[mt] = sa_v[base];
                al[mt] = sa_v[base + 1];
            }
            #pragma unroll
            for (int nt = 0; nt < 4; nt++)
                bf[nt] = sb_v[((warp_n * 4 + nt) * 2 + ks) * 32 + lane];
            #pragma unroll
            for (int mt = 0; mt < 4; mt++)
                #pragma unroll
                for (int nt = 0; nt < 4; nt++) {
                    mma_f16(acch[mt][nt], ah[mt], bf[nt].x, bf[nt].y);  // hi*hi
                    mma_f16(accl[mt][nt], ah[mt], bf[nt].z, bf[nt].w);  // hi*lo'
                    mma_f16(accl[mt][nt], al[mt], bf[nt].x, bf[nt].y);  // lo'*hi
                }
        }
        __syncthreads();
        if (kt + 3 < NT_IT) load_stage(kt + 3, s);
    }

    // Epilogue
    #pragma unroll
    for (int mt = 0; mt < 4; mt++) {
        int grow = row0 + (warp_m * 4 + mt) * 16 + lg;
        #pragma unroll
        for (int nt = 0; nt < 4; nt++) {
            int gcol = col0 + (warp_n * 4 + nt) * 8 + lc * 2;
            float b0 = 0.f, b1 = 0.f;
            if (bias != nullptr) { b0 = bias[gcol]; b1 = bias[gcol + 1]; }
            float* ch = acch[mt][nt];
            float* cl = accl[mt][nt];
            float2 r0 = make_float2(ch[0] + cl[0] * INV_LO + b0,
                                    ch[1] + cl[1] * INV_LO + b1);
            float2 r1 = make_float2(ch[2] + cl[2] * INV_LO + b0,
                                    ch[3] + cl[3] * INV_LO + b1);
            *reinterpret_cast<float2*>(C + (size_t)grow * HID_ + gcol) = r0;
            *reinterpret_cast<float2*>(C + (size_t)(grow + 8) * HID_ + gcol) = r1;
        }
    }
}

// ---------------------------------------------------------------------------
// NeoX RoPE applied in-place to Q and K.
// ---------------------------------------------------------------------------
__global__ void rope_kernel(const int* __restrict__ pos,
                            float* __restrict__ Q,
                            float* __restrict__ Kb) {
    int idx = blockIdx.x * blockDim.x + threadIdx.x;
    int d  = idx & 63;
    int h  = (idx >> 6) & (NH_ - 1);
    int bs = idx >> 10;
    if (bs >= B_ * S_) return;

    int p = pos[bs];
    float inv_freq = 1.0f / powf(10000.0f, (float)d * (2.0f / (float)HD_));
    float f = (float)p * inv_freq;
    float sn, cs;
    sincosf(f, &sn, &cs);

    size_t base = (size_t)bs * HID_ + (size_t)h * HD_;
    float q1 = Q[base + d],  q2 = Q[base + 64 + d];
    Q[base + d]      = q1 * cs - q2 * sn;
    Q[base + 64 + d] = q2 * cs + q1 * sn;
    float k1 = Kb[base + d], k2 = Kb[base + 64 + d];
    Kb[base + d]      = k1 * cs - k2 * sn;
    Kb[base + 64 + d] = k2 * cs + k1 * sn;
}

// ---------------------------------------------------------------------------
// Causal flash attention (fp32, online softmax). Unchanged (validated).
// ---------------------------------------------------------------------------
constexpr int ATTN_SMEM_FLOATS = 3 * 64 * 132 + 64 * 65 + 3 * 64;
constexpr int ATTN_SMEM_BYTES  = ATTN_SMEM_FLOATS * 4;

__global__ void attn_kernel(const float* __restrict__ Q,
                            const float* __restrict__ K,
                            const float* __restrict__ V,
                            float* __restrict__ O) {
    extern __shared__ float smf[];
    float* Qs  = smf;
    float* Ks  = Qs + 64 * 132;
    float* Vs  = Ks + 64 * 132;
    float* Ss  = Vs + 64 * 132;
    float* m_s = Ss + 64 * 65;
    float* l_s = m_s + 64;
    float* c_s = l_s + 64;

    const int tid = threadIdx.x;
    const int tx = tid & 15;
    const int ty = tid >> 4;
    const int bh = blockIdx.y;
    const int b  = bh / NH_;
    const int h  = bh % NH_;
    const int q0 = blockIdx.x * 64;

    const float* qb = Q + (size_t)(b * S_) * HID_ + (size_t)h * HD_;
    const float* kb = K + (size_t)(b * S_) * HID_ + (size_t)h * HD_;
    const float* vb = V + (size_t)(b * S_) * HID_ + (size_t)h * HD_;

    for (int t = tid; t < 64 * 32; t += 256) {
        int r = t >> 5, c4 = t & 31;
        *reinterpret_cast<float4*>(Qs + r * 132 + c4 * 4) =
            *reinterpret_cast<const float4*>(qb + (size_t)(q0 + r) * HID_ + c4 * 4);
    }
    if (tid < 64) { m_s[tid] = -1e30f; l_s[tid] = 0.f; }
    __syncthreads();

    float4 o[4][2];
    #pragma unroll
    for (int i = 0; i < 4; i++) {
        o[i][0] = make_float4(0.f, 0.f, 0.f, 0.f);
        o[i][1] = make_float4(0.f, 0.f, 0.f, 0.f);
    }

    const int ntiles = blockIdx.x + 1;
    for (int t = 0; t < ntiles; t++) {
        const int k0 = t * 64;
        for (int u = tid; u < 64 * 32; u += 256) {
            int r = u >> 5, c4 = u & 31;
            *reinterpret_cast<float4*>(Ks + r * 132 + c4 * 4) =
                *reinterpret_cast<const float4*>(kb + (size_t)(k0 + r) * HID_ + c4 * 4);
            *reinterpret_cast<float4*>(Vs + r * 132 + c4 * 4) =
                *reinterpret_cast<const float4*>(vb + (size_t)(k0 + r) * HID_ + c4 * 4);
        }
        __syncthreads();

        float acc[4][4] = {};
        #pragma unroll 4
        for (int k4 = 0; k4 < 32; k4++) {
            float4 qv[4], kv[4];
            #pragma unroll
            for (int i = 0; i < 4; i++)
                qv[i] = *reinterpret_cast<float4*>(Qs + (ty * 4 + i) * 132 + k4 * 4);
            #pragma unroll
            for (int j = 0; j < 4; j++)
                kv[j] = *reinterpret_cast<float4*>(Ks + (tx * 4 + j) * 132 + k4 * 4);
            #pragma unroll
            for (int i = 0; i < 4; i++)
                #pragma unroll
                for (int j = 0; j < 4; j++)
                    acc[i][j] += qv[i].x * kv[j].x + qv[i].y * kv[j].y +
                                 qv[i].z * kv[j].z + qv[i].w * kv[j].w;
        }

        #pragma unroll
        for (int i = 0; i < 4; i++)
            #pragma unroll
            for (int j = 0; j < 4; j++) {
                int gr = q0 + ty * 4 + i;
                int gc = k0 + tx * 4 + j;
                float v = acc[i][j] * SCALING_;
                if (gc > gr) v = -1e30f;
                Ss[(ty * 4 + i) * 65 + tx * 4 + j] = v;
            }
        __syncthreads();

        if (tid < 64) {
            const int r = tid;
            float mold = m_s[r];
            float tm = -1e30f;
            for (int j = 0; j < 64; j++) tm = fmaxf(tm, Ss[r * 65 + j]);
            float mnew = fmaxf(mold, tm);
            float corr = __expf(mold - mnew);
            float sum = 0.f;
            for (int j = 0; j < 64; j++) {
                float p = __expf(Ss[r * 65 + j] - mnew);
                Ss[r * 65 + j] = p;
                sum += p;
            }
            l_s[r] = l_s[r] * corr + sum;
            m_s[r] = mnew;
            c_s[r] = corr;
        }
        __syncthreads();

        #pragma unroll
        for (int i = 0; i < 4; i++) {
            float cf = c_s[ty * 4 + i];
            o[i][0].x *= cf; o[i][0].y *= cf; o[i][0].z *= cf; o[i][0].w *= cf;
            o[i][1].x *= cf; o[i][1].y *= cf; o[i][1].z *= cf; o[i][1].w *= cf;
        }
        #pragma unroll 4
        for (int j = 0; j < 64; j++) {
            float4 v0 = *reinterpret_cast<float4*>(Vs + j * 132 + tx * 8);
            float4 v1 = *reinterpret_cast<float4*>(Vs + j * 132 + tx * 8 + 4);
            #pragma unroll
            for (int i = 0; i < 4; i++) {
                float p = Ss[(ty * 4 + i) * 65 + j];
                o[i][0].x += p * v0.x; o[i][0].y += p * v0.y;
                o[i][0].z += p * v0.z; o[i][0].w += p * v0.w;
                o[i][1].x += p * v1.x; o[i][1].y += p * v1.y;
                o[i][1].z += p * v1.z; o[i][1].w += p * v1.w;
            }
        }
        __syncthreads();
    }

    #pragma unroll
    for (int i = 0; i < 4; i++) {
        const int r = ty * 4 + i;
        float linv = 1.0f / l_s[r];
        float4 a0 = o[i][0], a1 = o[i][1];
        a0.x *= linv; a0.y *= linv; a0.z *= linv; a0.w *= linv;
        a1.x *= linv; a1.y *= linv; a1.z *= linv; a1.w *= linv;
        float* op = O + (size_t)(b * S_ + q0 + r) * HID_ + (size_t)h * HD_ + tx * 8;
        *reinterpret_cast<float4*>(op)     = a0;
        *reinterpret_cast<float4*>(op + 4) = a1;
    }
}

// ---------------------------------------------------------------------------
// Launch
// ---------------------------------------------------------------------------
extern "C" void kernel_launch(void* const* d_in, const int* in_sizes, int n_in,
                              void* d_out, int out_size) {
    const float* hs  = (const float*)d_in[0];
    const int*   pos = (const int*)  d_in[1];
    const float* wq  = (const float*)d_in[2];
    const float* bq  = (const float*)d_in[3];
    const float* wk  = (const float*)d_in[4];
    const float* bk  = (const float*)d_in[5];
    const float* wv  = (const float*)d_in[6];
    const float* bv  = (const float*)d_in[7];
    const float* wc  = (const float*)d_in[8];
    float* out = (float*)d_out;

    float *qp, *kp, *vp, *ap;
    __half *apack, *bpack;
    cudaGetSymbolAddress((void**)&qp, g_q);
    cudaGetSymbolAddress((void**)&kp, g_k);
    cudaGetSymbolAddress((void**)&vp, g_v);
    cudaGetSymbolAddress((void**)&ap, g_attn);
    cudaGetSymbolAddress((void**)&apack, g_apack);
    cudaGetSymbolAddress((void**)&bpack, g_bpack);

    const size_t BPSZ = (size_t)HID_ * HID_ * 2;   // halfs per packed weight

    cudaFuncSetAttribute(gemm_tc_kernel,
                         cudaFuncAttributeMaxDynamicSharedMemorySize, GEMM_DSMEM);
    cudaFuncSetAttribute(attn_kernel,
                         cudaFuncAttributeMaxDynamicSharedMemorySize, ATTN_SMEM_BYTES);

    // Pack weights (fp16 hi/lo fragment layout)
    const int pb_blocks = (HID_ / 8) * KS16_ * 32 / 256;   // 4096
    pack_b_kernel<<<pb_blocks, 256>>>(wq, bpack + 0 * BPSZ);
    pack_b_kernel<<<pb_blocks, 256>>>(wk, bpack + 1 * BPSZ);
    pack_b_kernel<<<pb_blocks, 256>>>(wv, bpack + 2 * BPSZ);
    pack_b_kernel<<<pb_blocks, 256>>>(wc, bpack + 3 * BPSZ);

    // Pack activations
    const int pa_blocks = (M_ / 16) * KS16_ * 32 / 256;    // 4096
    pack_a_kernel<<<pa_blocks, 256>>>(hs, apack);

    dim3 ggrid(HID_ / 128, M_ / 128);   // (16, 32)
    gemm_tc_kernel<<<ggrid, 256, GEMM_DSMEM>>>(apack, bpack + 0 * BPSZ, bq, qp);
    gemm_tc_kernel<<<ggrid, 256, GEMM_DSMEM>>>(apack, bpack + 1 * BPSZ, bk, kp);
    gemm_tc_kernel<<<ggrid, 256, GEMM_DSMEM>>>(apack, bpack + 2 * BPSZ, bv, vp);

    // RoPE
    int rope_total = B_ * S_ * NH_ * 64;
    rope_kernel<<<rope_total / 256, 256>>>(pos, qp, kp);

    // Attention
    attn_kernel<<<dim3(S_ / 64, B_ * NH_), 256, ATTN_SMEM_BYTES>>>(qp, kp, vp, ap);

    // Output projection
    pack_a_kernel<<<pa_blocks, 256>>>(ap, apack);
    gemm_tc_kernel<<<ggrid, 256, GEMM_DSMEM>>>(apack, bpack + 3 * BPSZ, nullptr, out);
}

// round 6
// speedup vs baseline: 3.3841x; 2.0395x over previous
#include <cuda_runtime.h>
#include <cuda_fp16.h>
#include <cstdint>

// Problem constants
constexpr int B_  = 2;
constexpr int S_  = 2048;
constexpr int HID_ = 2048;
constexpr int NH_ = 16;
constexpr int HD_ = 128;
constexpr float SCALING_ = 0.08838834764831845f; // 128^-0.5
constexpr int M_ = B_ * S_;      // 4096
constexpr int KS16_ = HID_ / 16; // 128 k16-steps across K
constexpr float LO_SCALE = 4096.f;
constexpr float INV_LO  = 1.f / 4096.f;

// Scratch (allocation-free rule: __device__ globals)
__device__ float g_q[(size_t)M_ * HID_];
__device__ float g_k[(size_t)M_ * HID_];
__device__ float g_v[(size_t)M_ * HID_];
__device__ float g_attn[(size_t)M_ * HID_];
// GEMM fragment-packed fp16 hi/lo operands
__device__ __half g_apack[(size_t)M_ * HID_ * 2];
__device__ __half g_bpack[(size_t)4 * HID_ * HID_ * 2];
// Attention fragment-packed operands (hi/lo, unscaled lo)
// Qpack: [bh][mt=S/16][ks=8][lane][16]   (A-frag, rope+scale applied)
__device__ __half g_qpack[(size_t)32 * 128 * 8 * 32 * 16];
// Kpack: [bh][nt=S/8][ks=8][lane][8]     (B-frag, rope applied)
__device__ __half g_kpack[(size_t)32 * 256 * 8 * 32 * 8];
// Vpack: [bh][nt=HD/8][ks=S/16][lane][8] (B-frag)
__device__ __half g_vpack[(size_t)32 * 16 * 128 * 32 * 8];

// ---------------------------------------------------------------------------
// PTX helpers
// ---------------------------------------------------------------------------
__device__ __forceinline__ void cp_async16(uint32_t s, const void* g) {
    asm volatile("cp.async.cg.shared.global [%0], [%1], 16;" :: "r"(s), "l"(g));
}
__device__ __forceinline__ void cp_commit() {
    asm volatile("cp.async.commit_group;");
}
template <int N>
__device__ __forceinline__ void cp_wait() {
    asm volatile("cp.async.wait_group %0;" :: "n"(N));
}
__device__ __forceinline__ void mma_f16(float* c, uint4 a, uint32_t b0, uint32_t b1) {
    asm volatile(
        "mma.sync.aligned.m16n8k16.row.col.f32.f16.f16.f32 "
        "{%0,%1,%2,%3}, {%4,%5,%6,%7}, {%8,%9}, {%0,%1,%2,%3};"
        : "+f"(c[0]), "+f"(c[1]), "+f"(c[2]), "+f"(c[3])
        : "r"(a.x), "r"(a.y), "r"(a.z), "r"(a.w), "r"(b0), "r"(b1));
}
__device__ __forceinline__ void h_split(float x, __half& hi, __half& lo) {
    hi = __float2half_rn(x);
    lo = __float2half_rn((x - __half2float(hi)) * LO_SCALE);
}
// Unscaled split (for O(1) attention operands)
__device__ __forceinline__ void h_split_ns(float x, __half& hi, __half& lo) {
    hi = __float2half_rn(x);
    lo = __float2half_rn(x - __half2float(hi));
}
__device__ __forceinline__ uint32_t h2u(__half2 v) {
    return *reinterpret_cast<uint32_t*>(&v);
}
// NeoX rope for a single element at head-dim d (value x, partner y = q[d^64])
__device__ __forceinline__ float rope_val(float x, float y, int d, int p) {
    int dj = d & 63;
    float inv_freq = 1.0f / powf(10000.0f, (float)dj * (2.0f / (float)HD_));
    float f = (float)p * inv_freq;
    float sn, cs;
    sincosf(f, &sn, &cs);
    return (d < 64) ? (x * cs - y * sn) : (x * cs + y * sn);
}

// ---------------------------------------------------------------------------
// GEMM pack kernels (unchanged from R5)
// ---------------------------------------------------------------------------
__global__ void pack_a_kernel(const float* __restrict__ A, __half* __restrict__ P) {
    int idx = blockIdx.x * blockDim.x + threadIdx.x;
    int lane = idx & 31;
    int t = idx >> 5;
    int ks = t & (KS16_ - 1);
    int mt = t >> 7;
    int lg = lane >> 2, lc = lane & 3;
    int row = mt * 16 + lg;
    int col = ks * 16 + lc * 2;
    const float* r0 = A + (size_t)row * HID_ + col;
    const float* r1 = A + (size_t)(row + 8) * HID_ + col;
    float x[8] = { r0[0], r0[1], r1[0], r1[1], r0[8], r0[9], r1[8], r1[9] };
    __half out[16];
    #pragma unroll
    for (int i = 0; i < 8; i++) h_split(x[i], out[i], out[8 + i]);
    uint4* dst = reinterpret_cast<uint4*>(P + (size_t)idx * 16);
    dst[0] = *reinterpret_cast<uint4*>(&out[0]);
    dst[1] = *reinterpret_cast<uint4*>(&out[8]);
}

__global__ void pack_b_kernel(const float* __restrict__ W, __half* __restrict__ P) {
    int idx = blockIdx.x * blockDim.x + threadIdx.x;
    int lane = idx & 31;
    int t = idx >> 5;
    int ks = t & (KS16_ - 1);
    int nt = t >> 7;
    int lg = lane >> 2, lc = lane & 3;
    int n = nt * 8 + lg;
    int k = ks * 16 + lc * 2;
    float y0 = W[(size_t)k * HID_ + n];
    float y1 = W[(size_t)(k + 1) * HID_ + n];
    float y2 = W[(size_t)(k + 8) * HID_ + n];
    float y3 = W[(size_t)(k + 9) * HID_ + n];
    __half out[8];
    h_split(y0, out[0], out[4]);
    h_split(y1, out[1], out[5]);
    h_split(y2, out[2], out[6]);
    h_split(y3, out[3], out[7]);
    *reinterpret_cast<uint4*>(P + (size_t)idx * 8) = *reinterpret_cast<uint4*>(&out[0]);
}

// ---------------------------------------------------------------------------
// fp16 3-pass GEMM (unchanged from R5)
// ---------------------------------------------------------------------------
constexpr int NT_IT = HID_ / 32;
constexpr uint32_t STAGE_B = 32768;
constexpr int GEMM_DSMEM = 3 * STAGE_B;

__global__ void __launch_bounds__(256, 1)
gemm_tc_kernel(const __half* __restrict__ Apack, const __half* __restrict__ Bpack,
               const float* __restrict__ bias, float* __restrict__ C) {
    extern __shared__ __align__(16) char dsm[];
    const uint32_t sb = (uint32_t)__cvta_generic_to_shared(dsm);

    const int tid = threadIdx.x;
    const int lane = tid & 31;
    const int wid = tid >> 5;
    const int warp_m = wid & 1;
    const int warp_n = wid >> 1;
    const int row0 = blockIdx.y * 128;
    const int col0 = blockIdx.x * 128;
    const int lg = lane >> 2, lc = lane & 3;

    const __half* Ab = Apack + (size_t)(row0 >> 4) * (KS16_ * 32 * 16);
    const __half* Bb = Bpack + (size_t)(col0 >> 3) * (KS16_ * 32 * 8);

    auto load_stage = [&](int kt, int s) {
        uint32_t sa = sb + (uint32_t)s * STAGE_B;
        uint32_t sbm = sa + 16384;
        const __half* Abase = Ab + (size_t)kt * 1024;
        const __half* Bbase = Bb + (size_t)kt * 512;
        #pragma unroll
        for (int i = 0; i < 4; i++) {
            int c = tid + i * 256;
            int mt = c >> 7, inner = c & 127;
            cp_async16(sa + (uint32_t)c * 16, Abase + (size_t)mt * 65536 + inner * 8);
        }
        #pragma unroll
        for (int i = 0; i < 4; i++) {
            int c = tid + i * 256;
            int nt = c >> 6, inner = c & 63;
            cp_async16(sbm + (uint32_t)c * 16, Bbase + (size_t)nt * 32768 + inner * 8);
        }
        cp_commit();
    };

    float acch[4][4][4], accl[4][4][4];
    #pragma unroll
    for (int i = 0; i < 4; i++)
        #pragma unroll
        for (int j = 0; j < 4; j++)
            #pragma unroll
            for (int r = 0; r < 4; r++) { acch[i][j][r] = 0.f; accl[i][j][r] = 0.f; }

    load_stage(0, 0);
    load_stage(1, 1);
    load_stage(2, 2);

    for (int kt = 0; kt < NT_IT; kt++) {
        const int s = kt % 3;
        cp_wait<2>();
        __syncthreads();

        const uint4* sa_v = reinterpret_cast<const uint4*>(dsm + (size_t)s * STAGE_B);
        const uint4* sb_v = reinterpret_cast<const uint4*>(dsm + (size_t)s * STAGE_B + 16384);

        #pragma unroll
        for (int ks = 0; ks < 2; ks++) {
            uint4 ah[4], al[4], bf[4];
            #pragma unroll
            for (int mt = 0; mt < 4; mt++) {
                int base = (((warp_m * 4 + mt) * 2 + ks) * 32 + lane) * 2;
                ah[mt] = sa_v[base];
                al[mt] = sa_v[base + 1];
            }
            #pragma unroll
            for (int nt = 0; nt < 4; nt++)
                bf[nt] = sb_v[((warp_n * 4 + nt) * 2 + ks) * 32 + lane];
            #pragma unroll
            for (int mt = 0; mt < 4; mt++)
                #pragma unroll
                for (int nt = 0; nt < 4; nt++) {
                    mma_f16(acch[mt][nt], ah[mt], bf[nt].x, bf[nt].y);
                    mma_f16(accl[mt][nt], ah[mt], bf[nt].z, bf[nt].w);
                    mma_f16(accl[mt][nt], al[mt], bf[nt].x, bf[nt].y);
                }
        }
        __syncthreads();
        if (kt + 3 < NT_IT) load_stage(kt + 3, s);
    }

    #pragma unroll
    for (int mt = 0; mt < 4; mt++) {
        int grow = row0 + (warp_m * 4 + mt) * 16 + lg;
        #pragma unroll
        for (int nt = 0; nt < 4; nt++) {
            int gcol = col0 + (warp_n * 4 + nt) * 8 + lc * 2;
            float b0 = 0.f, b1 = 0.f;
            if (bias != nullptr) { b0 = bias[gcol]; b1 = bias[gcol + 1]; }
            float* ch = acch[mt][nt];
            float* cl = accl[mt][nt];
            float2 r0 = make_float2(ch[0] + cl[0] * INV_LO + b0,
                                    ch[1] + cl[1] * INV_LO + b1);
            float2 r1 = make_float2(ch[2] + cl[2] * INV_LO + b0,
                                    ch[3] + cl[3] * INV_LO + b1);
            *reinterpret_cast<float2*>(C + (size_t)grow * HID_ + gcol) = r0;
            *reinterpret_cast<float2*>(C + (size_t)(grow + 8) * HID_ + gcol) = r1;
        }
    }
}

// ---------------------------------------------------------------------------
// Attention pack kernels: rope + scaling fused, fp16 hi/lo (unscaled lo),
// fragment layouts ready for mma.
// ---------------------------------------------------------------------------
// Qpack: A-frag. threads: [bh(32)][mt(128)][ks(8)][lane(32)]
__global__ void pack_q_rope_kernel(const float* __restrict__ Q, const int* __restrict__ pos,
                                   __half* __restrict__ P) {
    int idx = blockIdx.x * blockDim.x + threadIdx.x;
    int lane = idx & 31;
    int t = idx >> 5;
    int ks = t & 7;
    int mt = (t >> 3) & 127;
    int bh = t >> 10;
    int b = bh >> 4, h = bh & 15;
    int lg = lane >> 2, lc = lane & 3;
    int s0 = mt * 16 + lg;
    int p0 = pos[b * S_ + s0];
    int p1 = pos[b * S_ + s0 + 8];
    const float* r0 = Q + (size_t)(b * S_ + s0) * HID_ + h * HD_;
    const float* r1 = r0 + (size_t)8 * HID_;
    int c0 = ks * 16 + 2 * lc;
    int cols[4] = { c0, c0 + 1, c0 + 8, c0 + 9 };
    int idx0[4] = { 0, 1, 4, 5 };   // a-slot for row lg
    int idx1[4] = { 2, 3, 6, 7 };   // a-slot for row lg+8
    float vals[8];
    #pragma unroll
    for (int i = 0; i < 4; i++) {
        int d = cols[i];
        vals[idx0[i]] = rope_val(r0[d], r0[d ^ 64], d, p0) * SCALING_;
        vals[idx1[i]] = rope_val(r1[d], r1[d ^ 64], d, p1) * SCALING_;
    }
    __half out[16];
    #pragma unroll
    for (int i = 0; i < 8; i++) h_split_ns(vals[i], out[i], out[8 + i]);
    uint4* dst = reinterpret_cast<uint4*>(P + (size_t)idx * 16);
    dst[0] = *reinterpret_cast<uint4*>(&out[0]);
    dst[1] = *reinterpret_cast<uint4*>(&out[8]);
}

// Kpack: B-frag. threads: [bh(32)][nt(256)][ks(8)][lane(32)]
__global__ void pack_k_rope_kernel(const float* __restrict__ K, const int* __restrict__ pos,
                                   __half* __restrict__ P) {
    int idx = blockIdx.x * blockDim.x + threadIdx.x;
    int lane = idx & 31;
    int t = idx >> 5;
    int ks = t & 7;
    int nt = (t >> 3) & 255;
    int bh = t >> 11;
    int b = bh >> 4, h = bh & 15;
    int lg = lane >> 2, lc = lane & 3;
    int tok = nt * 8 + lg;
    int p = pos[b * S_ + tok];
    const float* kr = K + (size_t)(b * S_ + tok) * HID_ + h * HD_;
    int c0 = ks * 16 + 2 * lc;
    int cols[4] = { c0, c0 + 1, c0 + 8, c0 + 9 };
    __half out[8];
    #pragma unroll
    for (int i = 0; i < 4; i++) {
        int d = cols[i];
        float v = rope_val(kr[d], kr[d ^ 64], d, p);
        h_split_ns(v, out[i], out[4 + i]);
    }
    *reinterpret_cast<uint4*>(P + (size_t)idx * 8) = *reinterpret_cast<uint4*>(&out[0]);
}

// Vpack: B-frag. threads: [bh(32)][nt(16)][ks(128)][lane(32)]
__global__ void pack_v_kernel(const float* __restrict__ V, __half* __restrict__ P) {
    int idx = blockIdx.x * blockDim.x + threadIdx.x;
    int lane = idx & 31;
    int t = idx >> 5;
    int ks = t & 127;
    int nt = (t >> 7) & 15;
    int bh = t >> 11;
    int b = bh >> 4, h = bh & 15;
    int lg = lane >> 2, lc = lane & 3;
    int n = nt * 8 + lg;                 // head-dim
    int k0 = ks * 16 + 2 * lc;           // token
    int toks[4] = { k0, k0 + 1, k0 + 8, k0 + 9 };
    __half out[8];
    #pragma unroll
    for (int i = 0; i < 4; i++) {
        float v = V[(size_t)(b * S_ + toks[i]) * HID_ + h * HD_ + n];
        h_split_ns(v, out[i], out[4 + i]);
    }
    *reinterpret_cast<uint4*>(P + (size_t)idx * 8) = *reinterpret_cast<uint4*>(&out[0]);
}

// ---------------------------------------------------------------------------
// Tensor-core causal flash attention (fp16 3-pass, fp32-accurate).
// Grid (S/128, B*NH), 256 threads = 8 warps, each warp owns m16 of 128 q-rows.
// BN=64 k-tiles, K/V double-buffered cp.async, Q resident in smem.
// smem: Q 64KB + 2 x (K 32KB + V 32KB) = 192KB.
// ---------------------------------------------------------------------------
constexpr int AT2_SMEM = 65536 + 2 * 65536;   // 196608

__global__ void __launch_bounds__(256, 1)
attn_tc_kernel(const __half* __restrict__ Qp, const __half* __restrict__ Kp,
               const __half* __restrict__ Vp, float* __restrict__ O) {
    extern __shared__ __align__(16) char smem_raw[];
    const uint32_t sb = (uint32_t)__cvta_generic_to_shared(smem_raw);
    const int tid = threadIdx.x;
    const int lane = tid & 31;
    const int warp = tid >> 5;
    const int lg = lane >> 2, lc = lane & 3;
    const int qi = blockIdx.x;
    const int bh = blockIdx.y;
    const int b = bh >> 4, h = bh & 15;
    const int q0 = qi * 128;
    const int ntiles = 2 * qi + 2;

    const __half* Qb = Qp + ((size_t)bh * 128 + (size_t)qi * 8) * 4096;
    const __half* Kb = Kp + (size_t)bh * 256 * 2048;
    const __half* Vb = Vp + (size_t)bh * 16 * 32768;

    // Q tile: 32768 halves contiguous
    #pragma unroll
    for (int i = 0; i < 16; i++) {
        int c = tid + i * 256;
        cp_async16(sb + (uint32_t)c * 16, Qb + (size_t)c * 8);
    }
    cp_commit();

    auto load_KV = [&](int t, int s) {
        uint32_t base = sb + 65536 + (uint32_t)s * 65536;
        const __half* Ksrc = Kb + (size_t)t * 16384;   // 8 nt contiguous
        #pragma unroll
        for (int i = 0; i < 8; i++) {
            int c = tid + i * 256;
            cp_async16(base + (uint32_t)c * 16, Ksrc + (size_t)c * 8);
        }
        #pragma unroll
        for (int i = 0; i < 8; i++) {
            int c = tid + i * 256;
            int nt = c >> 7, inner = c & 127;
            cp_async16(base + 32768 + (uint32_t)c * 16,
                       Vb + (size_t)nt * 32768 + (size_t)t * 1024 + inner * 8);
        }
        cp_commit();
    };
    load_KV(0, 0);
    load_KV(1, 1);

    float oacc[16][4];
    #pragma unroll
    for (int i = 0; i < 16; i++)
        #pragma unroll
        for (int r = 0; r < 4; r++) oacc[i][r] = 0.f;
    float m0 = -1e30f, m1 = -1e30f, l0 = 0.f, l1 = 0.f;

    const uint4* Qv = reinterpret_cast<const uint4*>(smem_raw);

    for (int t = 0; t < ntiles; t++) {
        cp_wait<1>();
        __syncthreads();
        const int s = t & 1;
        const uint4* Kv = reinterpret_cast<const uint4*>(smem_raw + 65536 + (size_t)s * 65536);
        const uint4* Vv = Kv + 2048;

        // S = Q @ K^T  (3-pass into single fp32 acc)
        float sacc[8][4];
        #pragma unroll
        for (int nt = 0; nt < 8; nt++)
            #pragma unroll
            for (int r = 0; r < 4; r++) sacc[nt][r] = 0.f;
        #pragma unroll
        for (int ks = 0; ks < 8; ks++) {
            int qbase = ((warp * 8 + ks) * 32 + lane) * 2;
            uint4 ahi = Qv[qbase];
            uint4 alo = Qv[qbase + 1];
            #pragma unroll
            for (int nt = 0; nt < 8; nt++) {
                uint4 kf = Kv[(nt * 8 + ks) * 32 + lane];
                mma_f16(sacc[nt], ahi, kf.x, kf.y);
                mma_f16(sacc[nt], ahi, kf.z, kf.w);
                mma_f16(sacc[nt], alo, kf.x, kf.y);
            }
        }

        // Causal mask (only on the two diagonal tiles)
        if (t >= ntiles - 2) {
            int gr0 = q0 + warp * 16 + lg;
            int gr1 = gr0 + 8;
            #pragma unroll
            for (int nt = 0; nt < 8; nt++) {
                int gc = t * 64 + nt * 8 + 2 * lc;
                if (gc > gr0)     sacc[nt][0] = -1e30f;
                if (gc + 1 > gr0) sacc[nt][1] = -1e30f;
                if (gc > gr1)     sacc[nt][2] = -1e30f;
                if (gc + 1 > gr1) sacc[nt][3] = -1e30f;
            }
        }

        // Online softmax (rows lg -> index 0, lg+8 -> index 1)
        float mx0 = -1e30f, mx1 = -1e30f;
        #pragma unroll
        for (int nt = 0; nt < 8; nt++) {
            mx0 = fmaxf(mx0, fmaxf(sacc[nt][0], sacc[nt][1]));
            mx1 = fmaxf(mx1, fmaxf(sacc[nt][2], sacc[nt][3]));
        }
        mx0 = fmaxf(mx0, __shfl_xor_sync(0xFFFFFFFFu, mx0, 1));
        mx0 = fmaxf(mx0, __shfl_xor_sync(0xFFFFFFFFu, mx0, 2));
        mx1 = fmaxf(mx1, __shfl_xor_sync(0xFFFFFFFFu, mx1, 1));
        mx1 = fmaxf(mx1, __shfl_xor_sync(0xFFFFFFFFu, mx1, 2));
        float mn0 = fmaxf(m0, mx0), mn1 = fmaxf(m1, mx1);
        float c0 = __expf(m0 - mn0), c1 = __expf(m1 - mn1);
        m0 = mn0; m1 = mn1;
        float sum0 = 0.f, sum1 = 0.f;
        #pragma unroll
        for (int nt = 0; nt < 8; nt++) {
            sacc[nt][0] = __expf(sacc[nt][0] - mn0); sum0 += sacc[nt][0];
            sacc[nt][1] = __expf(sacc[nt][1] - mn0); sum0 += sacc[nt][1];
            sacc[nt][2] = __expf(sacc[nt][2] - mn1); sum1 += sacc[nt][2];
            sacc[nt][3] = __expf(sacc[nt][3] - mn1); sum1 += sacc[nt][3];
        }
        sum0 += __shfl_xor_sync(0xFFFFFFFFu, sum0, 1);
        sum0 += __shfl_xor_sync(0xFFFFFFFFu, sum0, 2);
        sum1 += __shfl_xor_sync(0xFFFFFFFFu, sum1, 1);
        sum1 += __shfl_xor_sync(0xFFFFFFFFu, sum1, 2);
        l0 = l0 * c0 + sum0;
        l1 = l1 * c1 + sum1;
        #pragma unroll
        for (int nt = 0; nt < 16; nt++) {
            oacc[nt][0] *= c0; oacc[nt][1] *= c0;
            oacc[nt][2] *= c1; oacc[nt][3] *= c1;
        }

        // O += P @ V  (P -> fp16 hi/lo frags straight from sacc layout)
        #pragma unroll
        for (int j = 0; j < 4; j++) {
            const float* pa = sacc[2 * j];
            const float* pb = sacc[2 * j + 1];
            __half2 h01 = __floats2half2_rn(pa[0], pa[1]);
            __half2 h23 = __floats2half2_rn(pa[2], pa[3]);
            __half2 h45 = __floats2half2_rn(pb[0], pb[1]);
            __half2 h67 = __floats2half2_rn(pb[2], pb[3]);
            __half2 l01 = __floats2half2_rn(pa[0] - __low2float(h01), pa[1] - __high2float(h01));
            __half2 l23 = __floats2half2_rn(pa[2] - __low2float(h23), pa[3] - __high2float(h23));
            __half2 l45 = __floats2half2_rn(pb[0] - __low2float(h45), pb[1] - __high2float(h45));
            __half2 l67 = __floats2half2_rn(pb[2] - __low2float(h67), pb[3] - __high2float(h67));
            uint4 phi = make_uint4(h2u(h01), h2u(h23), h2u(h45), h2u(h67));
            uint4 plo = make_uint4(h2u(l01), h2u(l23), h2u(l45), h2u(l67));
            #pragma unroll
            for (int nt = 0; nt < 16; nt++) {
                uint4 vf = Vv[(nt * 4 + j) * 32 + lane];
                mma_f16(oacc[nt], phi, vf.x, vf.y);
                mma_f16(oacc[nt], phi, vf.z, vf.w);
                mma_f16(oacc[nt], plo, vf.x, vf.y);
            }
        }

        __syncthreads();
        if (t + 2 < ntiles) load_KV(t + 2, s);
    }

    // Epilogue: normalize and store to [B,S,NH*HD] fp32
    float inv0 = 1.f / l0, inv1 = 1.f / l1;
    int r0 = q0 + warp * 16 + lg;
    float* out0 = O + (size_t)(b * S_ + r0) * HID_ + h * HD_;
    float* out1 = out0 + (size_t)8 * HID_;
    #pragma unroll
    for (int nt = 0; nt < 16; nt++) {
        int col = nt * 8 + 2 * lc;
        *reinterpret_cast<float2*>(out0 + col) =
            make_float2(oacc[nt][0] * inv0, oacc[nt][1] * inv0);
        *reinterpret_cast<float2*>(out1 + col) =
            make_float2(oacc[nt][2] * inv1, oacc[nt][3] * inv1);
    }
}

// ---------------------------------------------------------------------------
// Launch
// ---------------------------------------------------------------------------
extern "C" void kernel_launch(void* const* d_in, const int* in_sizes, int n_in,
                              void* d_out, int out_size) {
    const float* hs  = (const float*)d_in[0];
    const int*   pos = (const int*)  d_in[1];
    const float* wq  = (const float*)d_in[2];
    const float* bq  = (const float*)d_in[3];
    const float* wk  = (const float*)d_in[4];
    const float* bk  = (const float*)d_in[5];
    const float* wv  = (const float*)d_in[6];
    const float* bv  = (const float*)d_in[7];
    const float* wc  = (const float*)d_in[8];
    float* out = (float*)d_out;

    float *qp, *kp, *vp, *ap;
    __half *apack, *bpack, *qpk, *kpk, *vpk;
    cudaGetSymbolAddress((void**)&qp, g_q);
    cudaGetSymbolAddress((void**)&kp, g_k);
    cudaGetSymbolAddress((void**)&vp, g_v);
    cudaGetSymbolAddress((void**)&ap, g_attn);
    cudaGetSymbolAddress((void**)&apack, g_apack);
    cudaGetSymbolAddress((void**)&bpack, g_bpack);
    cudaGetSymbolAddress((void**)&qpk, g_qpack);
    cudaGetSymbolAddress((void**)&kpk, g_kpack);
    cudaGetSymbolAddress((void**)&vpk, g_vpack);

    const size_t BPSZ = (size_t)HID_ * HID_ * 2;

    cudaFuncSetAttribute(gemm_tc_kernel,
                         cudaFuncAttributeMaxDynamicSharedMemorySize, GEMM_DSMEM);
    cudaFuncSetAttribute(attn_tc_kernel,
                         cudaFuncAttributeMaxDynamicSharedMemorySize, AT2_SMEM);

    // Weight + activation packs
    const int pb_blocks = (HID_ / 8) * KS16_ * 32 / 256;   // 4096
    pack_b_kernel<<<pb_blocks, 256>>>(wq, bpack + 0 * BPSZ);
    pack_b_kernel<<<pb_blocks, 256>>>(wk, bpack + 1 * BPSZ);
    pack_b_kernel<<<pb_blocks, 256>>>(wv, bpack + 2 * BPSZ);
    pack_b_kernel<<<pb_blocks, 256>>>(wc, bpack + 3 * BPSZ);
    const int pa_blocks = (M_ / 16) * KS16_ * 32 / 256;    // 4096
    pack_a_kernel<<<pa_blocks, 256>>>(hs, apack);

    // QKV projections
    dim3 ggrid(HID_ / 128, M_ / 128);   // (16, 32)
    gemm_tc_kernel<<<ggrid, 256, GEMM_DSMEM>>>(apack, bpack + 0 * BPSZ, bq, qp);
    gemm_tc_kernel<<<ggrid, 256, GEMM_DSMEM>>>(apack, bpack + 1 * BPSZ, bk, kp);
    gemm_tc_kernel<<<ggrid, 256, GEMM_DSMEM>>>(apack, bpack + 2 * BPSZ, bv, vp);

    // Attention packs (rope + scale fused)
    pack_q_rope_kernel<<<32 * 128 * 8 * 32 / 256, 256>>>(qp, pos, qpk);
    pack_k_rope_kernel<<<32 * 256 * 8 * 32 / 256, 256>>>(kp, pos, kpk);
    pack_v_kernel<<<32 * 16 * 128 * 32 / 256, 256>>>(vp, vpk);

    // Tensor-core attention
    attn_tc_kernel<<<dim3(S_ / 128, B_ * NH_), 256, AT2_SMEM>>>(qpk, kpk, vpk, ap);

    // Output projection
    pack_a_kernel<<<pa_blocks, 256>>>(ap, apack);
    gemm_tc_kernel<<<ggrid, 256, GEMM_DSMEM>>>(apack, bpack + 3 * BPSZ, nullptr, out);
}

// round 7
// speedup vs baseline: 3.6609x; 1.0818x over previous
#include <cuda_runtime.h>
#include <cuda_fp16.h>
#include <cstdint>

// Problem constants
constexpr int B_  = 2;
constexpr int S_  = 2048;
constexpr int HID_ = 2048;
constexpr int NH_ = 16;
constexpr int HD_ = 128;
constexpr float SCALING_ = 0.08838834764831845f; // 128^-0.5
constexpr int M_ = B_ * S_;      // 4096
constexpr int KS16_ = HID_ / 16; // 128 k16-steps across K
constexpr float LO_SCALE = 4096.f;
constexpr float INV_LO  = 1.f / 4096.f;

// Scratch (allocation-free rule: __device__ globals)
__device__ float g_q[(size_t)M_ * HID_];
__device__ float g_k[(size_t)M_ * HID_];
__device__ float g_v[(size_t)M_ * HID_];
// GEMM fragment-packed fp16 hi/lo operands
__device__ __half g_apack[(size_t)M_ * HID_ * 2];
__device__ __half g_bpack[(size_t)4 * HID_ * HID_ * 2];
// Attention fragment-packed operands (hi/lo, unscaled lo)
__device__ __half g_qpack[(size_t)32 * 128 * 8 * 32 * 16];
__device__ __half g_kpack[(size_t)32 * 256 * 8 * 32 * 8];
__device__ __half g_vpack[(size_t)32 * 16 * 128 * 32 * 8];

// ---------------------------------------------------------------------------
// PTX helpers
// ---------------------------------------------------------------------------
__device__ __forceinline__ void cp_async16(uint32_t s, const void* g) {
    asm volatile("cp.async.cg.shared.global [%0], [%1], 16;" :: "r"(s), "l"(g));
}
__device__ __forceinline__ void cp_commit() {
    asm volatile("cp.async.commit_group;");
}
template <int N>
__device__ __forceinline__ void cp_wait() {
    asm volatile("cp.async.wait_group %0;" :: "n"(N));
}
__device__ __forceinline__ void mma_f16(float* c, uint4 a, uint32_t b0, uint32_t b1) {
    asm volatile(
        "mma.sync.aligned.m16n8k16.row.col.f32.f16.f16.f32 "
        "{%0,%1,%2,%3}, {%4,%5,%6,%7}, {%8,%9}, {%0,%1,%2,%3};"
        : "+f"(c[0]), "+f"(c[1]), "+f"(c[2]), "+f"(c[3])
        : "r"(a.x), "r"(a.y), "r"(a.z), "r"(a.w), "r"(b0), "r"(b1));
}
__device__ __forceinline__ void h_split(float x, __half& hi, __half& lo) {
    hi = __float2half_rn(x);
    lo = __float2half_rn((x - __half2float(hi)) * LO_SCALE);
}
__device__ __forceinline__ void h_split_ns(float x, __half& hi, __half& lo) {
    hi = __float2half_rn(x);
    lo = __float2half_rn(x - __half2float(hi));
}
__device__ __forceinline__ uint32_t h2u(__half2 v) {
    return *reinterpret_cast<uint32_t*>(&v);
}
__device__ __forceinline__ float rope_val(float x, float y, int d, int p) {
    int dj = d & 63;
    float inv_freq = 1.0f / powf(10000.0f, (float)dj * (2.0f / (float)HD_));
    float f = (float)p * inv_freq;
    float sn, cs;
    sincosf(f, &sn, &cs);
    return (d < 64) ? (x * cs - y * sn) : (x * cs + y * sn);
}

// ---------------------------------------------------------------------------
// GEMM pack kernels
// ---------------------------------------------------------------------------
__global__ void pack_a_kernel(const float* __restrict__ A, __half* __restrict__ P) {
    int idx = blockIdx.x * blockDim.x + threadIdx.x;
    int lane = idx & 31;
    int t = idx >> 5;
    int ks = t & (KS16_ - 1);
    int mt = t >> 7;
    int lg = lane >> 2, lc = lane & 3;
    int row = mt * 16 + lg;
    int col = ks * 16 + lc * 2;
    const float* r0 = A + (size_t)row * HID_ + col;
    const float* r1 = A + (size_t)(row + 8) * HID_ + col;
    float x[8] = { r0[0], r0[1], r1[0], r1[1], r0[8], r0[9], r1[8], r1[9] };
    __half out[16];
    #pragma unroll
    for (int i = 0; i < 8; i++) h_split(x[i], out[i], out[8 + i]);
    uint4* dst = reinterpret_cast<uint4*>(P + (size_t)idx * 16);
    dst[0] = *reinterpret_cast<uint4*>(&out[0]);
    dst[1] = *reinterpret_cast<uint4*>(&out[8]);
}

__global__ void pack_b_kernel(const float* __restrict__ W, __half* __restrict__ P) {
    int idx = blockIdx.x * blockDim.x + threadIdx.x;
    int lane = idx & 31;
    int t = idx >> 5;
    int ks = t & (KS16_ - 1);
    int nt = t >> 7;
    int lg = lane >> 2, lc = lane & 3;
    int n = nt * 8 + lg;
    int k = ks * 16 + lc * 2;
    float y0 = W[(size_t)k * HID_ + n];
    float y1 = W[(size_t)(k + 1) * HID_ + n];
    float y2 = W[(size_t)(k + 8) * HID_ + n];
    float y3 = W[(size_t)(k + 9) * HID_ + n];
    __half out[8];
    h_split(y0, out[0], out[4]);
    h_split(y1, out[1], out[5]);
    h_split(y2, out[2], out[6]);
    h_split(y3, out[3], out[7]);
    *reinterpret_cast<uint4*>(P + (size_t)idx * 8) = *reinterpret_cast<uint4*>(&out[0]);
}

// ---------------------------------------------------------------------------
// fp16 3-pass GEMM body (pass-major mma ordering to break RAW chains)
// ---------------------------------------------------------------------------
constexpr int NT_IT = HID_ / 32;
constexpr uint32_t STAGE_B = 32768;
constexpr int GEMM_DSMEM = 3 * STAGE_B;

__device__ __forceinline__ void gemm_body(
    const __half* __restrict__ Apack, const __half* __restrict__ Bpack,
    const float* __restrict__ bias, float* __restrict__ C,
    char* dsm, int row0, int col0)
{
    const uint32_t sb = (uint32_t)__cvta_generic_to_shared(dsm);
    const int tid = threadIdx.x;
    const int lane = tid & 31;
    const int wid = tid >> 5;
    const int warp_m = wid & 1;
    const int warp_n = wid >> 1;
    const int lg = lane >> 2, lc = lane & 3;

    const __half* Ab = Apack + (size_t)(row0 >> 4) * (KS16_ * 32 * 16);
    const __half* Bb = Bpack + (size_t)(col0 >> 3) * (KS16_ * 32 * 8);

    auto load_stage = [&](int kt, int s) {
        uint32_t sa = sb + (uint32_t)s * STAGE_B;
        uint32_t sbm = sa + 16384;
        const __half* Abase = Ab + (size_t)kt * 1024;
        const __half* Bbase = Bb + (size_t)kt * 512;
        #pragma unroll
        for (int i = 0; i < 4; i++) {
            int c = tid + i * 256;
            int mt = c >> 7, inner = c & 127;
            cp_async16(sa + (uint32_t)c * 16, Abase + (size_t)mt * 65536 + inner * 8);
        }
        #pragma unroll
        for (int i = 0; i < 4; i++) {
            int c = tid + i * 256;
            int nt = c >> 6, inner = c & 63;
            cp_async16(sbm + (uint32_t)c * 16, Bbase + (size_t)nt * 32768 + inner * 8);
        }
        cp_commit();
    };

    float acch[4][4][4], accl[4][4][4];
    #pragma unroll
    for (int i = 0; i < 4; i++)
        #pragma unroll
        for (int j = 0; j < 4; j++)
            #pragma unroll
            for (int r = 0; r < 4; r++) { acch[i][j][r] = 0.f; accl[i][j][r] = 0.f; }

    load_stage(0, 0);
    load_stage(1, 1);
    load_stage(2, 2);

    for (int kt = 0; kt < NT_IT; kt++) {
        const int s = kt % 3;
        cp_wait<2>();
        __syncthreads();

        const uint4* sa_v = reinterpret_cast<const uint4*>(dsm + (size_t)s * STAGE_B);
        const uint4* sb_v = reinterpret_cast<const uint4*>(dsm + (size_t)s * STAGE_B + 16384);

        #pragma unroll
        for (int ks = 0; ks < 2; ks++) {
            uint4 ah[4], al[4], bf[4];
            #pragma unroll
            for (int mt = 0; mt < 4; mt++) {
                int base = (((warp_m * 4 + mt) * 2 + ks) * 32 + lane) * 2;
                ah[mt] = sa_v[base];
                al[mt] = sa_v[base + 1];
            }
            #pragma unroll
            for (int nt = 0; nt < 4; nt++)
                bf[nt] = sb_v[((warp_n * 4 + nt) * 2 + ks) * 32 + lane];
            // pass-major: 16 independent mmas per pass
            #pragma unroll
            for (int mt = 0; mt < 4; mt++)
                #pragma unroll
                for (int nt = 0; nt < 4; nt++)
                    mma_f16(acch[mt][nt], ah[mt], bf[nt].x, bf[nt].y);
            #pragma unroll
            for (int mt = 0; mt < 4; mt++)
                #pragma unroll
                for (int nt = 0; nt < 4; nt++)
                    mma_f16(accl[mt][nt], ah[mt], bf[nt].z, bf[nt].w);
            #pragma unroll
            for (int mt = 0; mt < 4; mt++)
                #pragma unroll
                for (int nt = 0; nt < 4; nt++)
                    mma_f16(accl[mt][nt], al[mt], bf[nt].x, bf[nt].y);
        }
        __syncthreads();
        if (kt + 3 < NT_IT) load_stage(kt + 3, s);
    }

    #pragma unroll
    for (int mt = 0; mt < 4; mt++) {
        int grow = row0 + (warp_m * 4 + mt) * 16 + lg;
        #pragma unroll
        for (int nt = 0; nt < 4; nt++) {
            int gcol = col0 + (warp_n * 4 + nt) * 8 + lc * 2;
            float b0 = 0.f, b1 = 0.f;
            if (bias != nullptr) { b0 = bias[gcol]; b1 = bias[gcol + 1]; }
            float* ch = acch[mt][nt];
            float* cl = accl[mt][nt];
            float2 r0 = make_float2(ch[0] + cl[0] * INV_LO + b0,
                                    ch[1] + cl[1] * INV_LO + b1);
            float2 r1 = make_float2(ch[2] + cl[2] * INV_LO + b0,
                                    ch[3] + cl[3] * INV_LO + b1);
            *reinterpret_cast<float2*>(C + (size_t)grow * HID_ + gcol) = r0;
            *reinterpret_cast<float2*>(C + (size_t)(grow + 8) * HID_ + gcol) = r1;
        }
    }
}

// Merged QKV GEMM: grid (16, 32, 3); z selects weight/bias/output
__global__ void __launch_bounds__(256, 1)
gemm_qkv_kernel(const __half* __restrict__ Apack, const __half* __restrict__ Bpack,
                const float* __restrict__ bq, const float* __restrict__ bk,
                const float* __restrict__ bv,
                float* __restrict__ Q, float* __restrict__ K, float* __restrict__ V) {
    extern __shared__ __align__(16) char dsm[];
    const int z = blockIdx.z;
    const size_t BPSZ = (size_t)HID_ * HID_ * 2;
    const float* bias = (z == 0) ? bq : (z == 1) ? bk : bv;
    float* C = (z == 0) ? Q : (z == 1) ? K : V;
    gemm_body(Apack, Bpack + (size_t)z * BPSZ, bias, C,
              dsm, blockIdx.y * 128, blockIdx.x * 128);
}

// Single GEMM (out-projection)
__global__ void __launch_bounds__(256, 1)
gemm_tc_kernel(const __half* __restrict__ Apack, const __half* __restrict__ Bpack,
               const float* __restrict__ bias, float* __restrict__ C) {
    extern __shared__ __align__(16) char dsm[];
    gemm_body(Apack, Bpack, bias, C, dsm, blockIdx.y * 128, blockIdx.x * 128);
}

// ---------------------------------------------------------------------------
// Attention pack kernels (rope + scale fused)
// ---------------------------------------------------------------------------
__global__ void pack_q_rope_kernel(const float* __restrict__ Q, const int* __restrict__ pos,
                                   __half* __restrict__ P) {
    int idx = blockIdx.x * blockDim.x + threadIdx.x;
    int lane = idx & 31;
    int t = idx >> 5;
    int ks = t & 7;
    int mt = (t >> 3) & 127;
    int bh = t >> 10;
    int b = bh >> 4, h = bh & 15;
    int lg = lane >> 2, lc = lane & 3;
    int s0 = mt * 16 + lg;
    int p0 = pos[b * S_ + s0];
    int p1 = pos[b * S_ + s0 + 8];
    const float* r0 = Q + (size_t)(b * S_ + s0) * HID_ + h * HD_;
    const float* r1 = r0 + (size_t)8 * HID_;
    int c0 = ks * 16 + 2 * lc;
    int cols[4] = { c0, c0 + 1, c0 + 8, c0 + 9 };
    int idx0[4] = { 0, 1, 4, 5 };
    int idx1[4] = { 2, 3, 6, 7 };
    float vals[8];
    #pragma unroll
    for (int i = 0; i < 4; i++) {
        int d = cols[i];
        vals[idx0[i]] = rope_val(r0[d], r0[d ^ 64], d, p0) * SCALING_;
        vals[idx1[i]] = rope_val(r1[d], r1[d ^ 64], d, p1) * SCALING_;
    }
    __half out[16];
    #pragma unroll
    for (int i = 0; i < 8; i++) h_split_ns(vals[i], out[i], out[8 + i]);
    uint4* dst = reinterpret_cast<uint4*>(P + (size_t)idx * 16);
    dst[0] = *reinterpret_cast<uint4*>(&out[0]);
    dst[1] = *reinterpret_cast<uint4*>(&out[8]);
}

__global__ void pack_k_rope_kernel(const float* __restrict__ K, const int* __restrict__ pos,
                                   __half* __restrict__ P) {
    int idx = blockIdx.x * blockDim.x + threadIdx.x;
    int lane = idx & 31;
    int t = idx >> 5;
    int ks = t & 7;
    int nt = (t >> 3) & 255;
    int bh = t >> 11;
    int b = bh >> 4, h = bh & 15;
    int lg = lane >> 2, lc = lane & 3;
    int tok = nt * 8 + lg;
    int p = pos[b * S_ + tok];
    const float* kr = K + (size_t)(b * S_ + tok) * HID_ + h * HD_;
    int c0 = ks * 16 + 2 * lc;
    int cols[4] = { c0, c0 + 1, c0 + 8, c0 + 9 };
    __half out[8];
    #pragma unroll
    for (int i = 0; i < 4; i++) {
        int d = cols[i];
        float v = rope_val(kr[d], kr[d ^ 64], d, p);
        h_split_ns(v, out[i], out[4 + i]);
    }
    *reinterpret_cast<uint4*>(P + (size_t)idx * 8) = *reinterpret_cast<uint4*>(&out[0]);
}

__global__ void pack_v_kernel(const float* __restrict__ V, __half* __restrict__ P) {
    int idx = blockIdx.x * blockDim.x + threadIdx.x;
    int lane = idx & 31;
    int t = idx >> 5;
    int ks = t & 127;
    int nt = (t >> 7) & 15;
    int bh = t >> 11;
    int b = bh >> 4, h = bh & 15;
    int lg = lane >> 2, lc = lane & 3;
    int n = nt * 8 + lg;
    int k0 = ks * 16 + 2 * lc;
    int toks[4] = { k0, k0 + 1, k0 + 8, k0 + 9 };
    __half out[8];
    #pragma unroll
    for (int i = 0; i < 4; i++) {
        float v = V[(size_t)(b * S_ + toks[i]) * HID_ + h * HD_ + n];
        h_split_ns(v, out[i], out[4 + i]);
    }
    *reinterpret_cast<uint4*>(P + (size_t)idx * 8) = *reinterpret_cast<uint4*>(&out[0]);
}

// ---------------------------------------------------------------------------
// Tensor-core causal flash attention. Epilogue writes the out-projection's
// A-fragment pack directly (scaled hi/lo split). Heavy tiles scheduled first.
// ---------------------------------------------------------------------------
constexpr int AT2_SMEM = 65536 + 2 * 65536;   // 196608

__global__ void __launch_bounds__(256, 1)
attn_tc_kernel(const __half* __restrict__ Qp, const __half* __restrict__ Kp,
               const __half* __restrict__ Vp, __half* __restrict__ APout) {
    extern __shared__ __align__(16) char smem_raw[];
    const uint32_t sb = (uint32_t)__cvta_generic_to_shared(smem_raw);
    const int tid = threadIdx.x;
    const int lane = tid & 31;
    const int warp = tid >> 5;
    const int lg = lane >> 2, lc = lane & 3;
    const int qi = gridDim.x - 1 - blockIdx.x;   // heavy diagonals first
    const int bh = blockIdx.y;
    const int b = bh >> 4, h = bh & 15;
    const int q0 = qi * 128;
    const int ntiles = 2 * qi + 2;

    const __half* Qb = Qp + ((size_t)bh * 128 + (size_t)qi * 8) * 4096;
    const __half* Kb = Kp + (size_t)bh * 256 * 2048;
    const __half* Vb = Vp + (size_t)bh * 16 * 32768;

    #pragma unroll
    for (int i = 0; i < 16; i++) {
        int c = tid + i * 256;
        cp_async16(sb + (uint32_t)c * 16, Qb + (size_t)c * 8);
    }
    cp_commit();

    auto load_KV = [&](int t, int s) {
        uint32_t base = sb + 65536 + (uint32_t)s * 65536;
        const __half* Ksrc = Kb + (size_t)t * 16384;
        #pragma unroll
        for (int i = 0; i < 8; i++) {
            int c = tid + i * 256;
            cp_async16(base + (uint32_t)c * 16, Ksrc + (size_t)c * 8);
        }
        #pragma unroll
        for (int i = 0; i < 8; i++) {
            int c = tid + i * 256;
            int nt = c >> 7, inner = c & 127;
            cp_async16(base + 32768 + (uint32_t)c * 16,
                       Vb + (size_t)nt * 32768 + (size_t)t * 1024 + inner * 8);
        }
        cp_commit();
    };
    load_KV(0, 0);
    load_KV(1, 1);

    float oacc[16][4];
    #pragma unroll
    for (int i = 0; i < 16; i++)
        #pragma unroll
        for (int r = 0; r < 4; r++) oacc[i][r] = 0.f;
    float m0 = -1e30f, m1 = -1e30f, l0 = 0.f, l1 = 0.f;

    const uint4* Qv = reinterpret_cast<const uint4*>(smem_raw);

    for (int t = 0; t < ntiles; t++) {
        cp_wait<1>();
        __syncthreads();
        const int s = t & 1;
        const uint4* Kv = reinterpret_cast<const uint4*>(smem_raw + 65536 + (size_t)s * 65536);
        const uint4* Vv = Kv + 2048;

        // S = Q @ K^T (pass-major: RAW distance 8)
        float sacc[8][4];
        #pragma unroll
        for (int nt = 0; nt < 8; nt++)
            #pragma unroll
            for (int r = 0; r < 4; r++) sacc[nt][r] = 0.f;
        #pragma unroll
        for (int ks = 0; ks < 8; ks++) {
            int qbase = ((warp * 8 + ks) * 32 + lane) * 2;
            uint4 ahi = Qv[qbase];
            uint4 alo = Qv[qbase + 1];
            uint4 kf[8];
            #pragma unroll
            for (int nt = 0; nt < 8; nt++)
                kf[nt] = Kv[(nt * 8 + ks) * 32 + lane];
            #pragma unroll
            for (int nt = 0; nt < 8; nt++)
                mma_f16(sacc[nt], ahi, kf[nt].x, kf[nt].y);
            #pragma unroll
            for (int nt = 0; nt < 8; nt++)
                mma_f16(sacc[nt], ahi, kf[nt].z, kf[nt].w);
            #pragma unroll
            for (int nt = 0; nt < 8; nt++)
                mma_f16(sacc[nt], alo, kf[nt].x, kf[nt].y);
        }

        if (t >= ntiles - 2) {
            int gr0 = q0 + warp * 16 + lg;
            int gr1 = gr0 + 8;
            #pragma unroll
            for (int nt = 0; nt < 8; nt++) {
                int gc = t * 64 + nt * 8 + 2 * lc;
                if (gc > gr0)     sacc[nt][0] = -1e30f;
                if (gc + 1 > gr0) sacc[nt][1] = -1e30f;
                if (gc > gr1)     sacc[nt][2] = -1e30f;
                if (gc + 1 > gr1) sacc[nt][3] = -1e30f;
            }
        }

        // Online softmax
        float mx0 = -1e30f, mx1 = -1e30f;
        #pragma unroll
        for (int nt = 0; nt < 8; nt++) {
            mx0 = fmaxf(mx0, fmaxf(sacc[nt][0], sacc[nt][1]));
            mx1 = fmaxf(mx1, fmaxf(sacc[nt][2], sacc[nt][3]));
        }
        mx0 = fmaxf(mx0, __shfl_xor_sync(0xFFFFFFFFu, mx0, 1));
        mx0 = fmaxf(mx0, __shfl_xor_sync(0xFFFFFFFFu, mx0, 2));
        mx1 = fmaxf(mx1, __shfl_xor_sync(0xFFFFFFFFu, mx1, 1));
        mx1 = fmaxf(mx1, __shfl_xor_sync(0xFFFFFFFFu, mx1, 2));
        float mn0 = fmaxf(m0, mx0), mn1 = fmaxf(m1, mx1);
        float c0 = __expf(m0 - mn0), c1 = __expf(m1 - mn1);
        m0 = mn0; m1 = mn1;
        float sum0 = 0.f, sum1 = 0.f;
        #pragma unroll
        for (int nt = 0; nt < 8; nt++) {
            sacc[nt][0] = __expf(sacc[nt][0] - mn0); sum0 += sacc[nt][0];
            sacc[nt][1] = __expf(sacc[nt][1] - mn0); sum0 += sacc[nt][1];
            sacc[nt][2] = __expf(sacc[nt][2] - mn1); sum1 += sacc[nt][2];
            sacc[nt][3] = __expf(sacc[nt][3] - mn1); sum1 += sacc[nt][3];
        }
        sum0 += __shfl_xor_sync(0xFFFFFFFFu, sum0, 1);
        sum0 += __shfl_xor_sync(0xFFFFFFFFu, sum0, 2);
        sum1 += __shfl_xor_sync(0xFFFFFFFFu, sum1, 1);
        sum1 += __shfl_xor_sync(0xFFFFFFFFu, sum1, 2);
        l0 = l0 * c0 + sum0;
        l1 = l1 * c1 + sum1;
        #pragma unroll
        for (int nt = 0; nt < 16; nt++) {
            oacc[nt][0] *= c0; oacc[nt][1] *= c0;
            oacc[nt][2] *= c1; oacc[nt][3] *= c1;
        }

        // O += P @ V (nt-blocks of 8, pass-major)
        #pragma unroll
        for (int j = 0; j < 4; j++) {
            const float* pa = sacc[2 * j];
            const float* pb = sacc[2 * j + 1];
            __half2 h01 = __floats2half2_rn(pa[0], pa[1]);
            __half2 h23 = __floats2half2_rn(pa[2], pa[3]);
            __half2 h45 = __floats2half2_rn(pb[0], pb[1]);
            __half2 h67 = __floats2half2_rn(pb[2], pb[3]);
            __half2 l01 = __floats2half2_rn(pa[0] - __low2float(h01), pa[1] - __high2float(h01));
            __half2 l23 = __floats2half2_rn(pa[2] - __low2float(h23), pa[3] - __high2float(h23));
            __half2 l45 = __floats2half2_rn(pb[0] - __low2float(h45), pb[1] - __high2float(h45));
            __half2 l67 = __floats2half2_rn(pb[2] - __low2float(h67), pb[3] - __high2float(h67));
            uint4 phi = make_uint4(h2u(h01), h2u(h23), h2u(h45), h2u(h67));
            uint4 plo = make_uint4(h2u(l01), h2u(l23), h2u(l45), h2u(l67));
            #pragma unroll
            for (int blk = 0; blk < 2; blk++) {
                uint4 vf[8];
                #pragma unroll
                for (int i = 0; i < 8; i++)
                    vf[i] = Vv[((blk * 8 + i) * 4 + j) * 32 + lane];
                #pragma unroll
                for (int i = 0; i < 8; i++)
                    mma_f16(oacc[blk * 8 + i], phi, vf[i].x, vf[i].y);
                #pragma unroll
                for (int i = 0; i < 8; i++)
                    mma_f16(oacc[blk * 8 + i], phi, vf[i].z, vf[i].w);
                #pragma unroll
                for (int i = 0; i < 8; i++)
                    mma_f16(oacc[blk * 8 + i], plo, vf[i].x, vf[i].y);
            }
        }

        __syncthreads();
        if (t + 2 < ntiles) load_KV(t + 2, s);
    }

    // Epilogue: normalize + write out-proj A-frag pack directly (scaled split)
    float inv0 = 1.f / l0, inv1 = 1.f / l1;
    const int mtg = b * 128 + qi * 8 + warp;          // global row / 16
    #pragma unroll
    for (int j = 0; j < 8; j++) {
        const int ksg = h * 8 + j;                     // global k16-step
        float x[8] = {
            oacc[2 * j][0] * inv0,     oacc[2 * j][1] * inv0,
            oacc[2 * j][2] * inv1,     oacc[2 * j][3] * inv1,
            oacc[2 * j + 1][0] * inv0, oacc[2 * j + 1][1] * inv0,
            oacc[2 * j + 1][2] * inv1, oacc[2 * j + 1][3] * inv1
        };
        __half out[16];
        #pragma unroll
        for (int i = 0; i < 8; i++) h_split(x[i], out[i], out[8 + i]);
        uint4* dst = reinterpret_cast<uint4*>(
            APout + (((size_t)mtg * KS16_ + ksg) * 32 + lane) * 16);
        dst[0] = *reinterpret_cast<uint4*>(&out[0]);
        dst[1] = *reinterpret_cast<uint4*>(&out[8]);
    }
}

// ---------------------------------------------------------------------------
// Launch
// ---------------------------------------------------------------------------
extern "C" void kernel_launch(void* const* d_in, const int* in_sizes, int n_in,
                              void* d_out, int out_size) {
    const float* hs  = (const float*)d_in[0];
    const int*   pos = (const int*)  d_in[1];
    const float* wq  = (const float*)d_in[2];
    const float* bq  = (const float*)d_in[3];
    const float* wk  = (const float*)d_in[4];
    const float* bk  = (const float*)d_in[5];
    const float* wv  = (const float*)d_in[6];
    const float* bv  = (const float*)d_in[7];
    const float* wc  = (const float*)d_in[8];
    float* out = (float*)d_out;

    float *qp, *kp, *vp;
    __half *apack, *bpack, *qpk, *kpk, *vpk;
    cudaGetSymbolAddress((void**)&qp, g_q);
    cudaGetSymbolAddress((void**)&kp, g_k);
    cudaGetSymbolAddress((void**)&vp, g_v);
    cudaGetSymbolAddress((void**)&apack, g_apack);
    cudaGetSymbolAddress((void**)&bpack, g_bpack);
    cudaGetSymbolAddress((void**)&qpk, g_qpack);
    cudaGetSymbolAddress((void**)&kpk, g_kpack);
    cudaGetSymbolAddress((void**)&vpk, g_vpack);

    const size_t BPSZ = (size_t)HID_ * HID_ * 2;

    cudaFuncSetAttribute(gemm_qkv_kernel,
                         cudaFuncAttributeMaxDynamicSharedMemorySize, GEMM_DSMEM);
    cudaFuncSetAttribute(gemm_tc_kernel,
                         cudaFuncAttributeMaxDynamicSharedMemorySize, GEMM_DSMEM);
    cudaFuncSetAttribute(attn_tc_kernel,
                         cudaFuncAttributeMaxDynamicSharedMemorySize, AT2_SMEM);

    // Weight + activation packs
    const int pb_blocks = (HID_ / 8) * KS16_ * 32 / 256;   // 4096
    pack_b_kernel<<<pb_blocks, 256>>>(wq, bpack + 0 * BPSZ);
    pack_b_kernel<<<pb_blocks, 256>>>(wk, bpack + 1 * BPSZ);
    pack_b_kernel<<<pb_blocks, 256>>>(wv, bpack + 2 * BPSZ);
    pack_b_kernel<<<pb_blocks, 256>>>(wc, bpack + 3 * BPSZ);
    const int pa_blocks = (M_ / 16) * KS16_ * 32 / 256;    // 4096
    pack_a_kernel<<<pa_blocks, 256>>>(hs, apack);

    // Fused QKV projections (one launch, grid.z selects weight)
    dim3 qkv_grid(HID_ / 128, M_ / 128, 3);   // (16, 32, 3)
    gemm_qkv_kernel<<<qkv_grid, 256, GEMM_DSMEM>>>(apack, bpack, bq, bk, bv,
                                                   qp, kp, vp);

    // Attention packs (rope + scale fused)
    pack_q_rope_kernel<<<32 * 128 * 8 * 32 / 256, 256>>>(qp, pos, qpk);
    pack_k_rope_kernel<<<32 * 256 * 8 * 32 / 256, 256>>>(kp, pos, kpk);
    pack_v_kernel<<<32 * 16 * 128 * 32 / 256, 256>>>(vp, vpk);

    // Tensor-core attention (writes out-proj A-pack directly)
    attn_tc_kernel<<<dim3(S_ / 128, B_ * NH_), 256, AT2_SMEM>>>(qpk, kpk, vpk, apack);

    // Output projection
    dim3 ggrid(HID_ / 128, M_ / 128);   // (16, 32)
    gemm_tc_kernel<<<ggrid, 256, GEMM_DSMEM>>>(apack, bpack + 3 * BPSZ, nullptr, out);
}

// round 8
// speedup vs baseline: 4.1039x; 1.1210x over previous
#include <cuda_runtime.h>
#include <cuda_fp16.h>
#include <cstdint>

// Problem constants
constexpr int B_  = 2;
constexpr int S_  = 2048;
constexpr int HID_ = 2048;
constexpr int NH_ = 16;
constexpr int HD_ = 128;
constexpr float SCALING_ = 0.08838834764831845f; // 128^-0.5
constexpr int M_ = B_ * S_;      // 4096
constexpr int KS16_ = HID_ / 16; // 128 k16-steps across K
constexpr float LO_SCALE = 4096.f;
constexpr float INV_LO  = 1.f / 4096.f;

// Scratch (allocation-free rule: __device__ globals)
__device__ float g_q[(size_t)M_ * HID_];
__device__ float g_k[(size_t)M_ * HID_];
__device__ float g_v[(size_t)M_ * HID_];
// GEMM fragment-packed fp16 hi/lo operands
__device__ __half g_apack[(size_t)M_ * HID_ * 2];
__device__ __half g_bpack[(size_t)4 * HID_ * HID_ * 2];
// Attention fragment-packed operands (hi/lo, unscaled lo)
__device__ __half g_qpack[(size_t)32 * 128 * 8 * 32 * 16];
__device__ __half g_kpack[(size_t)32 * 256 * 8 * 32 * 8];
__device__ __half g_vpack[(size_t)32 * 16 * 128 * 32 * 8];

// ---------------------------------------------------------------------------
// PTX helpers
// ---------------------------------------------------------------------------
__device__ __forceinline__ void cp_async16(uint32_t s, const void* g) {
    asm volatile("cp.async.cg.shared.global [%0], [%1], 16;" :: "r"(s), "l"(g));
}
__device__ __forceinline__ void cp_commit() {
    asm volatile("cp.async.commit_group;");
}
template <int N>
__device__ __forceinline__ void cp_wait() {
    asm volatile("cp.async.wait_group %0;" :: "n"(N));
}
__device__ __forceinline__ void mma_f16(float* c, uint4 a, uint32_t b0, uint32_t b1) {
    asm volatile(
        "mma.sync.aligned.m16n8k16.row.col.f32.f16.f16.f32 "
        "{%0,%1,%2,%3}, {%4,%5,%6,%7}, {%8,%9}, {%0,%1,%2,%3};"
        : "+f"(c[0]), "+f"(c[1]), "+f"(c[2]), "+f"(c[3])
        : "r"(a.x), "r"(a.y), "r"(a.z), "r"(a.w), "r"(b0), "r"(b1));
}
__device__ __forceinline__ void h_split(float x, __half& hi, __half& lo) {
    hi = __float2half_rn(x);
    lo = __float2half_rn((x - __half2float(hi)) * LO_SCALE);
}
__device__ __forceinline__ void h_split_ns(float x, __half& hi, __half& lo) {
    hi = __float2half_rn(x);
    lo = __float2half_rn(x - __half2float(hi));
}
__device__ __forceinline__ uint32_t h2u(__half2 v) {
    return *reinterpret_cast<uint32_t*>(&v);
}
__device__ __forceinline__ float rope_val(float x, float y, int d, int p) {
    int dj = d & 63;
    float inv_freq = 1.0f / powf(10000.0f, (float)dj * (2.0f / (float)HD_));
    float f = (float)p * inv_freq;
    float sn, cs;
    sincosf(f, &sn, &cs);
    return (d < 64) ? (x * cs - y * sn) : (x * cs + y * sn);
}

// ---------------------------------------------------------------------------
// GEMM pack kernels
// ---------------------------------------------------------------------------
__global__ void pack_a_kernel(const float* __restrict__ A, __half* __restrict__ P) {
    int idx = blockIdx.x * blockDim.x + threadIdx.x;
    int lane = idx & 31;
    int t = idx >> 5;
    int ks = t & (KS16_ - 1);
    int mt = t >> 7;
    int lg = lane >> 2, lc = lane & 3;
    int row = mt * 16 + lg;
    int col = ks * 16 + lc * 2;
    const float* r0 = A + (size_t)row * HID_ + col;
    const float* r1 = A + (size_t)(row + 8) * HID_ + col;
    float x[8] = { r0[0], r0[1], r1[0], r1[1], r0[8], r0[9], r1[8], r1[9] };
    __half out[16];
    #pragma unroll
    for (int i = 0; i < 8; i++) h_split(x[i], out[i], out[8 + i]);
    uint4* dst = reinterpret_cast<uint4*>(P + (size_t)idx * 16);
    dst[0] = *reinterpret_cast<uint4*>(&out[0]);
    dst[1] = *reinterpret_cast<uint4*>(&out[8]);
}

// All four weights in one launch (grid.y selects the weight)
__global__ void pack_b4_kernel(const float* __restrict__ w0, const float* __restrict__ w1,
                               const float* __restrict__ w2, const float* __restrict__ w3,
                               __half* __restrict__ P) {
    const int z = blockIdx.y;
    const float* W = (z == 0) ? w0 : (z == 1) ? w1 : (z == 2) ? w2 : w3;
    __half* Pz = P + (size_t)z * HID_ * HID_ * 2;
    int idx = blockIdx.x * blockDim.x + threadIdx.x;
    int lane = idx & 31;
    int t = idx >> 5;
    int ks = t & (KS16_ - 1);
    int nt = t >> 7;
    int lg = lane >> 2, lc = lane & 3;
    int n = nt * 8 + lg;
    int k = ks * 16 + lc * 2;
    float y0 = W[(size_t)k * HID_ + n];
    float y1 = W[(size_t)(k + 1) * HID_ + n];
    float y2 = W[(size_t)(k + 8) * HID_ + n];
    float y3 = W[(size_t)(k + 9) * HID_ + n];
    __half out[8];
    h_split(y0, out[0], out[4]);
    h_split(y1, out[1], out[5]);
    h_split(y2, out[2], out[6]);
    h_split(y3, out[3], out[7]);
    *reinterpret_cast<uint4*>(Pz + (size_t)idx * 8) = *reinterpret_cast<uint4*>(&out[0]);
}

// ---------------------------------------------------------------------------
// fp16 GEMM body. PASS3=true: hh + ah*bl + al*bh (fp32-accurate).
// PASS3=false: hh + al*bh (2-pass; first-order accurate, ~2e-4 rel).
// ---------------------------------------------------------------------------
constexpr int NT_IT = HID_ / 32;
constexpr uint32_t STAGE_B = 32768;
constexpr int GEMM_DSMEM = 3 * STAGE_B;

template <bool PASS3>
__device__ __forceinline__ void gemm_body(
    const __half* __restrict__ Apack, const __half* __restrict__ Bpack,
    const float* __restrict__ bias, float* __restrict__ C,
    char* dsm, int row0, int col0)
{
    const uint32_t sb = (uint32_t)__cvta_generic_to_shared(dsm);
    const int tid = threadIdx.x;
    const int lane = tid & 31;
    const int wid = tid >> 5;
    const int warp_m = wid & 1;
    const int warp_n = wid >> 1;
    const int lg = lane >> 2, lc = lane & 3;

    const __half* Ab = Apack + (size_t)(row0 >> 4) * (KS16_ * 32 * 16);
    const __half* Bb = Bpack + (size_t)(col0 >> 3) * (KS16_ * 32 * 8);

    auto load_stage = [&](int kt, int s) {
        uint32_t sa = sb + (uint32_t)s * STAGE_B;
        uint32_t sbm = sa + 16384;
        const __half* Abase = Ab + (size_t)kt * 1024;
        const __half* Bbase = Bb + (size_t)kt * 512;
        #pragma unroll
        for (int i = 0; i < 4; i++) {
            int c = tid + i * 256;
            int mt = c >> 7, inner = c & 127;
            cp_async16(sa + (uint32_t)c * 16, Abase + (size_t)mt * 65536 + inner * 8);
        }
        #pragma unroll
        for (int i = 0; i < 4; i++) {
            int c = tid + i * 256;
            int nt = c >> 6, inner = c & 63;
            cp_async16(sbm + (uint32_t)c * 16, Bbase + (size_t)nt * 32768 + inner * 8);
        }
        cp_commit();
    };

    float acch[4][4][4], accl[4][4][4];
    #pragma unroll
    for (int i = 0; i < 4; i++)
        #pragma unroll
        for (int j = 0; j < 4; j++)
            #pragma unroll
            for (int r = 0; r < 4; r++) { acch[i][j][r] = 0.f; accl[i][j][r] = 0.f; }

    load_stage(0, 0);
    load_stage(1, 1);
    load_stage(2, 2);

    for (int kt = 0; kt < NT_IT; kt++) {
        const int s = kt % 3;
        cp_wait<2>();
        __syncthreads();

        const uint4* sa_v = reinterpret_cast<const uint4*>(dsm + (size_t)s * STAGE_B);
        const uint4* sb_v = reinterpret_cast<const uint4*>(dsm + (size_t)s * STAGE_B + 16384);

        #pragma unroll
        for (int ks = 0; ks < 2; ks++) {
            uint4 ah[4], al[4], bf[4];
            #pragma unroll
            for (int mt = 0; mt < 4; mt++) {
                int base = (((warp_m * 4 + mt) * 2 + ks) * 32 + lane) * 2;
                ah[mt] = sa_v[base];
                al[mt] = sa_v[base + 1];
            }
            #pragma unroll
            for (int nt = 0; nt < 4; nt++)
                bf[nt] = sb_v[((warp_n * 4 + nt) * 2 + ks) * 32 + lane];
            #pragma unroll
            for (int mt = 0; mt < 4; mt++)
                #pragma unroll
                for (int nt = 0; nt < 4; nt++)
                    mma_f16(acch[mt][nt], ah[mt], bf[nt].x, bf[nt].y);
            if (PASS3) {
                #pragma unroll
                for (int mt = 0; mt < 4; mt++)
                    #pragma unroll
                    for (int nt = 0; nt < 4; nt++)
                        mma_f16(accl[mt][nt], ah[mt], bf[nt].z, bf[nt].w);
            }
            #pragma unroll
            for (int mt = 0; mt < 4; mt++)
                #pragma unroll
                for (int nt = 0; nt < 4; nt++)
                    mma_f16(accl[mt][nt], al[mt], bf[nt].x, bf[nt].y);
        }
        __syncthreads();
        if (kt + 3 < NT_IT) load_stage(kt + 3, s);
    }

    #pragma unroll
    for (int mt = 0; mt < 4; mt++) {
        int grow = row0 + (warp_m * 4 + mt) * 16 + lg;
        #pragma unroll
        for (int nt = 0; nt < 4; nt++) {
            int gcol = col0 + (warp_n * 4 + nt) * 8 + lc * 2;
            float b0 = 0.f, b1 = 0.f;
            if (bias != nullptr) { b0 = bias[gcol]; b1 = bias[gcol + 1]; }
            float* ch = acch[mt][nt];
            float* cl = accl[mt][nt];
            float2 r0 = make_float2(ch[0] + cl[0] * INV_LO + b0,
                                    ch[1] + cl[1] * INV_LO + b1);
            float2 r1 = make_float2(ch[2] + cl[2] * INV_LO + b0,
                                    ch[3] + cl[3] * INV_LO + b1);
            *reinterpret_cast<float2*>(C + (size_t)grow * HID_ + gcol) = r0;
            *reinterpret_cast<float2*>(C + (size_t)(grow + 8) * HID_ + gcol) = r1;
        }
    }
}

// Merged QKV GEMM: grid (16, 32, 3). Q,K stay 3-pass (softmax-amplified);
// V demoted to 2-pass (linear error path).
__global__ void __launch_bounds__(256, 1)
gemm_qkv_kernel(const __half* __restrict__ Apack, const __half* __restrict__ Bpack,
                const float* __restrict__ bq, const float* __restrict__ bk,
                const float* __restrict__ bv,
                float* __restrict__ Q, float* __restrict__ K, float* __restrict__ V) {
    extern __shared__ __align__(16) char dsm[];
    const int z = blockIdx.z;
    const size_t BPSZ = (size_t)HID_ * HID_ * 2;
    if (z == 2) {
        gemm_body<false>(Apack, Bpack + 2 * BPSZ, bv, V,
                         dsm, blockIdx.y * 128, blockIdx.x * 128);
    } else if (z == 1) {
        gemm_body<true>(Apack, Bpack + 1 * BPSZ, bk, K,
                        dsm, blockIdx.y * 128, blockIdx.x * 128);
    } else {
        gemm_body<true>(Apack, Bpack, bq, Q,
                        dsm, blockIdx.y * 128, blockIdx.x * 128);
    }
}

// Out-projection GEMM (2-pass: linear error path)
__global__ void __launch_bounds__(256, 1)
gemm_tc_kernel(const __half* __restrict__ Apack, const __half* __restrict__ Bpack,
               const float* __restrict__ bias, float* __restrict__ C) {
    extern __shared__ __align__(16) char dsm[];
    gemm_body<false>(Apack, Bpack, bias, C, dsm, blockIdx.y * 128, blockIdx.x * 128);
}

// ---------------------------------------------------------------------------
// Attention pack kernels (rope + scale fused)
// ---------------------------------------------------------------------------
__global__ void pack_q_rope_kernel(const float* __restrict__ Q, const int* __restrict__ pos,
                                   __half* __restrict__ P) {
    int idx = blockIdx.x * blockDim.x + threadIdx.x;
    int lane = idx & 31;
    int t = idx >> 5;
    int ks = t & 7;
    int mt = (t >> 3) & 127;
    int bh = t >> 10;
    int b = bh >> 4, h = bh & 15;
    int lg = lane >> 2, lc = lane & 3;
    int s0 = mt * 16 + lg;
    int p0 = pos[b * S_ + s0];
    int p1 = pos[b * S_ + s0 + 8];
    const float* r0 = Q + (size_t)(b * S_ + s0) * HID_ + h * HD_;
    const float* r1 = r0 + (size_t)8 * HID_;
    int c0 = ks * 16 + 2 * lc;
    int cols[4] = { c0, c0 + 1, c0 + 8, c0 + 9 };
    int idx0[4] = { 0, 1, 4, 5 };
    int idx1[4] = { 2, 3, 6, 7 };
    float vals[8];
    #pragma unroll
    for (int i = 0; i < 4; i++) {
        int d = cols[i];
        vals[idx0[i]] = rope_val(r0[d], r0[d ^ 64], d, p0) * SCALING_;
        vals[idx1[i]] = rope_val(r1[d], r1[d ^ 64], d, p1) * SCALING_;
    }
    __half out[16];
    #pragma unroll
    for (int i = 0; i < 8; i++) h_split_ns(vals[i], out[i], out[8 + i]);
    uint4* dst = reinterpret_cast<uint4*>(P + (size_t)idx * 16);
    dst[0] = *reinterpret_cast<uint4*>(&out[0]);
    dst[1] = *reinterpret_cast<uint4*>(&out[8]);
}

__global__ void pack_k_rope_kernel(const float* __restrict__ K, const int* __restrict__ pos,
                                   __half* __restrict__ P) {
    int idx = blockIdx.x * blockDim.x + threadIdx.x;
    int lane = idx & 31;
    int t = idx >> 5;
    int ks = t & 7;
    int nt = (t >> 3) & 255;
    int bh = t >> 11;
    int b = bh >> 4, h = bh & 15;
    int lg = lane >> 2, lc = lane & 3;
    int tok = nt * 8 + lg;
    int p = pos[b * S_ + tok];
    const float* kr = K + (size_t)(b * S_ + tok) * HID_ + h * HD_;
    int c0 = ks * 16 + 2 * lc;
    int cols[4] = { c0, c0 + 1, c0 + 8, c0 + 9 };
    __half out[8];
    #pragma unroll
    for (int i = 0; i < 4; i++) {
        int d = cols[i];
        float v = rope_val(kr[d], kr[d ^ 64], d, p);
        h_split_ns(v, out[i], out[4 + i]);
    }
    *reinterpret_cast<uint4*>(P + (size_t)idx * 8) = *reinterpret_cast<uint4*>(&out[0]);
}

__global__ void pack_v_kernel(const float* __restrict__ V, __half* __restrict__ P) {
    int idx = blockIdx.x * blockDim.x + threadIdx.x;
    int lane = idx & 31;
    int t = idx >> 5;
    int ks = t & 127;
    int nt = (t >> 7) & 15;
    int bh = t >> 11;
    int b = bh >> 4, h = bh & 15;
    int lg = lane >> 2, lc = lane & 3;
    int n = nt * 8 + lg;
    int k0 = ks * 16 + 2 * lc;
    int toks[4] = { k0, k0 + 1, k0 + 8, k0 + 9 };
    __half out[8];
    #pragma unroll
    for (int i = 0; i < 4; i++) {
        float v = V[(size_t)(b * S_ + toks[i]) * HID_ + h * HD_ + n];
        h_split_ns(v, out[i], out[4 + i]);
    }
    *reinterpret_cast<uint4*>(P + (size_t)idx * 8) = *reinterpret_cast<uint4*>(&out[0]);
}

// ---------------------------------------------------------------------------
// Tensor-core causal flash attention. QK stays 3-pass; PV demoted to 2-pass
// (drop P-lo, keep P-hi x V-hi and P-hi x V-lo). Flattened heavy-first grid.
// ---------------------------------------------------------------------------
constexpr int AT2_SMEM = 65536 + 2 * 65536;   // 196608

__global__ void __launch_bounds__(256, 1)
attn_tc_kernel(const __half* __restrict__ Qp, const __half* __restrict__ Kp,
               const __half* __restrict__ Vp, __half* __restrict__ APout) {
    extern __shared__ __align__(16) char smem_raw[];
    const uint32_t sb = (uint32_t)__cvta_generic_to_shared(smem_raw);
    const int tid = threadIdx.x;
    const int lane = tid & 31;
    const int warp = tid >> 5;
    const int lg = lane >> 2, lc = lane & 3;
    // Flattened heavy-first: first 32 CTAs are qi=15 (heaviest), etc.
    const int qi = 15 - (int)(blockIdx.x >> 5);
    const int bh = blockIdx.x & 31;
    const int b = bh >> 4, h = bh & 15;
    const int q0 = qi * 128;
    const int ntiles = 2 * qi + 2;

    const __half* Qb = Qp + ((size_t)bh * 128 + (size_t)qi * 8) * 4096;
    const __half* Kb = Kp + (size_t)bh * 256 * 2048;
    const __half* Vb = Vp + (size_t)bh * 16 * 32768;

    #pragma unroll
    for (int i = 0; i < 16; i++) {
        int c = tid + i * 256;
        cp_async16(sb + (uint32_t)c * 16, Qb + (size_t)c * 8);
    }
    cp_commit();

    auto load_KV = [&](int t, int s) {
        uint32_t base = sb + 65536 + (uint32_t)s * 65536;
        const __half* Ksrc = Kb + (size_t)t * 16384;
        #pragma unroll
        for (int i = 0; i < 8; i++) {
            int c = tid + i * 256;
            cp_async16(base + (uint32_t)c * 16, Ksrc + (size_t)c * 8);
        }
        #pragma unroll
        for (int i = 0; i < 8; i++) {
            int c = tid + i * 256;
            int nt = c >> 7, inner = c & 127;
            cp_async16(base + 32768 + (uint32_t)c * 16,
                       Vb + (size_t)nt * 32768 + (size_t)t * 1024 + inner * 8);
        }
        cp_commit();
    };
    load_KV(0, 0);
    load_KV(1, 1);

    float oacc[16][4];
    #pragma unroll
    for (int i = 0; i < 16; i++)
        #pragma unroll
        for (int r = 0; r < 4; r++) oacc[i][r] = 0.f;
    float m0 = -1e30f, m1 = -1e30f, l0 = 0.f, l1 = 0.f;

    const uint4* Qv = reinterpret_cast<const uint4*>(smem_raw);

    for (int t = 0; t < ntiles; t++) {
        cp_wait<1>();
        __syncthreads();
        const int s = t & 1;
        const uint4* Kv = reinterpret_cast<const uint4*>(smem_raw + 65536 + (size_t)s * 65536);
        const uint4* Vv = Kv + 2048;

        // S = Q @ K^T (3-pass; softmax-amplified path keeps full accuracy)
        float sacc[8][4];
        #pragma unroll
        for (int nt = 0; nt < 8; nt++)
            #pragma unroll
            for (int r = 0; r < 4; r++) sacc[nt][r] = 0.f;
        #pragma unroll
        for (int ks = 0; ks < 8; ks++) {
            int qbase = ((warp * 8 + ks) * 32 + lane) * 2;
            uint4 ahi = Qv[qbase];
            uint4 alo = Qv[qbase + 1];
            uint4 kf[8];
            #pragma unroll
            for (int nt = 0; nt < 8; nt++)
                kf[nt] = Kv[(nt * 8 + ks) * 32 + lane];
            #pragma unroll
            for (int nt = 0; nt < 8; nt++)
                mma_f16(sacc[nt], ahi, kf[nt].x, kf[nt].y);
            #pragma unroll
            for (int nt = 0; nt < 8; nt++)
                mma_f16(sacc[nt], ahi, kf[nt].z, kf[nt].w);
            #pragma unroll
            for (int nt = 0; nt < 8; nt++)
                mma_f16(sacc[nt], alo, kf[nt].x, kf[nt].y);
        }

        if (t >= ntiles - 2) {
            int gr0 = q0 + warp * 16 + lg;
            int gr1 = gr0 + 8;
            #pragma unroll
            for (int nt = 0; nt < 8; nt++) {
                int gc = t * 64 + nt * 8 + 2 * lc;
                if (gc > gr0)     sacc[nt][0] = -1e30f;
                if (gc + 1 > gr0) sacc[nt][1] = -1e30f;
                if (gc > gr1)     sacc[nt][2] = -1e30f;
                if (gc + 1 > gr1) sacc[nt][3] = -1e30f;
            }
        }

        // Online softmax
        float mx0 = -1e30f, mx1 = -1e30f;
        #pragma unroll
        for (int nt = 0; nt < 8; nt++) {
            mx0 = fmaxf(mx0, fmaxf(sacc[nt][0], sacc[nt][1]));
            mx1 = fmaxf(mx1, fmaxf(sacc[nt][2], sacc[nt][3]));
        }
        mx0 = fmaxf(mx0, __shfl_xor_sync(0xFFFFFFFFu, mx0, 1));
        mx0 = fmaxf(mx0, __shfl_xor_sync(0xFFFFFFFFu, mx0, 2));
        mx1 = fmaxf(mx1, __shfl_xor_sync(0xFFFFFFFFu, mx1, 1));
        mx1 = fmaxf(mx1, __shfl_xor_sync(0xFFFFFFFFu, mx1, 2));
        float mn0 = fmaxf(m0, mx0), mn1 = fmaxf(m1, mx1);
        float c0 = __expf(m0 - mn0), c1 = __expf(m1 - mn1);
        m0 = mn0; m1 = mn1;
        float sum0 = 0.f, sum1 = 0.f;
        #pragma unroll
        for (int nt = 0; nt < 8; nt++) {
            sacc[nt][0] = __expf(sacc[nt][0] - mn0); sum0 += sacc[nt][0];
            sacc[nt][1] = __expf(sacc[nt][1] - mn0); sum0 += sacc[nt][1];
            sacc[nt][2] = __expf(sacc[nt][2] - mn1); sum1 += sacc[nt][2];
            sacc[nt][3] = __expf(sacc[nt][3] - mn1); sum1 += sacc[nt][3];
        }
        sum0 += __shfl_xor_sync(0xFFFFFFFFu, sum0, 1);
        sum0 += __shfl_xor_sync(0xFFFFFFFFu, sum0, 2);
        sum1 += __shfl_xor_sync(0xFFFFFFFFu, sum1, 1);
        sum1 += __shfl_xor_sync(0xFFFFFFFFu, sum1, 2);
        l0 = l0 * c0 + sum0;
        l1 = l1 * c1 + sum1;
        #pragma unroll
        for (int nt = 0; nt < 16; nt++) {
            oacc[nt][0] *= c0; oacc[nt][1] *= c0;
            oacc[nt][2] *= c1; oacc[nt][3] *= c1;
        }

        // O += P @ V  (2-pass: P-hi x V-hi + P-hi x V-lo; P-lo dropped)
        #pragma unroll
        for (int j = 0; j < 4; j++) {
            const float* pa = sacc[2 * j];
            const float* pb = sacc[2 * j + 1];
            __half2 h01 = __floats2half2_rn(pa[0], pa[1]);
            __half2 h23 = __floats2half2_rn(pa[2], pa[3]);
            __half2 h45 = __floats2half2_rn(pb[0], pb[1]);
            __half2 h67 = __floats2half2_rn(pb[2], pb[3]);
            uint4 phi = make_uint4(h2u(h01), h2u(h23), h2u(h45), h2u(h67));
            #pragma unroll
            for (int blk = 0; blk < 2; blk++) {
                uint4 vf[8];
                #pragma unroll
                for (int i = 0; i < 8; i++)
                    vf[i] = Vv[((blk * 8 + i) * 4 + j) * 32 + lane];
                #pragma unroll
                for (int i = 0; i < 8; i++)
                    mma_f16(oacc[blk * 8 + i], phi, vf[i].x, vf[i].y);
                #pragma unroll
                for (int i = 0; i < 8; i++)
                    mma_f16(oacc[blk * 8 + i], phi, vf[i].z, vf[i].w);
            }
        }

        __syncthreads();
        if (t + 2 < ntiles) load_KV(t + 2, s);
    }

    // Epilogue: normalize + write out-proj A-frag pack directly (scaled split)
    float inv0 = 1.f / l0, inv1 = 1.f / l1;
    const int mtg = b * 128 + qi * 8 + warp;          // global row / 16
    #pragma unroll
    for (int j = 0; j < 8; j++) {
        const int ksg = h * 8 + j;                     // global k16-step
        float x[8] = {
            oacc[2 * j][0] * inv0,     oacc[2 * j][1] * inv0,
            oacc[2 * j][2] * inv1,     oacc[2 * j][3] * inv1,
            oacc[2 * j + 1][0] * inv0, oacc[2 * j + 1][1] * inv0,
            oacc[2 * j + 1][2] * inv1, oacc[2 * j + 1][3] * inv1
        };
        __half out[16];
        #pragma unroll
        for (int i = 0; i < 8; i++) h_split(x[i], out[i], out[8 + i]);
        uint4* dst = reinterpret_cast<uint4*>(
            APout + (((size_t)mtg * KS16_ + ksg) * 32 + lane) * 16);
        dst[0] = *reinterpret_cast<uint4*>(&out[0]);
        dst[1] = *reinterpret_cast<uint4*>(&out[8]);
    }
}

// ---------------------------------------------------------------------------
// Launch
// ---------------------------------------------------------------------------
extern "C" void kernel_launch(void* const* d_in, const int* in_sizes, int n_in,
                              void* d_out, int out_size) {
    const float* hs  = (const float*)d_in[0];
    const int*   pos = (const int*)  d_in[1];
    const float* wq  = (const float*)d_in[2];
    const float* bq  = (const float*)d_in[3];
    const float* wk  = (const float*)d_in[4];
    const float* bk  = (const float*)d_in[5];
    const float* wv  = (const float*)d_in[6];
    const float* bv  = (const float*)d_in[7];
    const float* wc  = (const float*)d_in[8];
    float* out = (float*)d_out;

    float *qp, *kp, *vp;
    __half *apack, *bpack, *qpk, *kpk, *vpk;
    cudaGetSymbolAddress((void**)&qp, g_q);
    cudaGetSymbolAddress((void**)&kp, g_k);
    cudaGetSymbolAddress((void**)&vp, g_v);
    cudaGetSymbolAddress((void**)&apack, g_apack);
    cudaGetSymbolAddress((void**)&bpack, g_bpack);
    cudaGetSymbolAddress((void**)&qpk, g_qpack);
    cudaGetSymbolAddress((void**)&kpk, g_kpack);
    cudaGetSymbolAddress((void**)&vpk, g_vpack);

    const size_t BPSZ = (size_t)HID_ * HID_ * 2;

    cudaFuncSetAttribute(gemm_qkv_kernel,
                         cudaFuncAttributeMaxDynamicSharedMemorySize, GEMM_DSMEM);
    cudaFuncSetAttribute(gemm_tc_kernel,
                         cudaFuncAttributeMaxDynamicSharedMemorySize, GEMM_DSMEM);
    cudaFuncSetAttribute(attn_tc_kernel,
                         cudaFuncAttributeMaxDynamicSharedMemorySize, AT2_SMEM);

    // Weight + activation packs
    dim3 pbgrid((HID_ / 8) * KS16_ * 32 / 256, 4);   // (4096, 4)
    pack_b4_kernel<<<pbgrid, 256>>>(wq, wk, wv, wc, bpack);
    const int pa_blocks = (M_ / 16) * KS16_ * 32 / 256;    // 4096
    pack_a_kernel<<<pa_blocks, 256>>>(hs, apack);

    // Fused QKV projections (one launch, grid.z selects weight; V is 2-pass)
    dim3 qkv_grid(HID_ / 128, M_ / 128, 3);   // (16, 32, 3)
    gemm_qkv_kernel<<<qkv_grid, 256, GEMM_DSMEM>>>(apack, bpack, bq, bk, bv,
                                                   qp, kp, vp);

    // Attention packs (rope + scale fused)
    pack_q_rope_kernel<<<32 * 128 * 8 * 32 / 256, 256>>>(qp, pos, qpk);
    pack_k_rope_kernel<<<32 * 256 * 8 * 32 / 256, 256>>>(kp, pos, kpk);
    pack_v_kernel<<<32 * 16 * 128 * 32 / 256, 256>>>(vp, vpk);

    // Tensor-core attention (flattened heavy-first grid)
    attn_tc_kernel<<<512, 256, AT2_SMEM>>>(qpk, kpk, vpk, apack);

    // Output projection (2-pass)
    dim3 ggrid(HID_ / 128, M_ / 128);   // (16, 32)
    gemm_tc_kernel<<<ggrid, 256, GEMM_DSMEM>>>(apack, bpack + 3 * BPSZ, nullptr, out);
}

// round 9
// speedup vs baseline: 4.2446x; 1.0343x over previous
#include <cuda_runtime.h>
#include <cuda_fp16.h>
#include <cstdint>

// Problem constants
constexpr int B_  = 2;
constexpr int S_  = 2048;
constexpr int HID_ = 2048;
constexpr int NH_ = 16;
constexpr int HD_ = 128;
constexpr float SCALING_ = 0.08838834764831845f; // 128^-0.5
constexpr int M_ = B_ * S_;      // 4096
constexpr int KS16_ = HID_ / 16; // 128 k16-steps across K
constexpr float LO_SCALE = 4096.f;
constexpr float INV_LO  = 1.f / 4096.f;

// Scratch (allocation-free rule: __device__ globals)
__device__ __half g_apack[(size_t)M_ * HID_ * 2];
__device__ __half g_bpack[(size_t)4 * HID_ * HID_ * 2];
// Attention fragment-packed operands (hi/lo, unscaled lo)
__device__ __half g_qpack[(size_t)32 * 128 * 8 * 32 * 16];
__device__ __half g_kpack[(size_t)32 * 256 * 8 * 32 * 8];
__device__ __half g_vpack[(size_t)32 * 16 * 128 * 32 * 8];

// ---------------------------------------------------------------------------
// PTX helpers
// ---------------------------------------------------------------------------
__device__ __forceinline__ void cp_async16(uint32_t s, const void* g) {
    asm volatile("cp.async.cg.shared.global [%0], [%1], 16;" :: "r"(s), "l"(g));
}
__device__ __forceinline__ void cp_commit() {
    asm volatile("cp.async.commit_group;");
}
template <int N>
__device__ __forceinline__ void cp_wait() {
    asm volatile("cp.async.wait_group %0;" :: "n"(N));
}
__device__ __forceinline__ void mma_f16(float* c, uint4 a, uint32_t b0, uint32_t b1) {
    asm volatile(
        "mma.sync.aligned.m16n8k16.row.col.f32.f16.f16.f32 "
        "{%0,%1,%2,%3}, {%4,%5,%6,%7}, {%8,%9}, {%0,%1,%2,%3};"
        : "+f"(c[0]), "+f"(c[1]), "+f"(c[2]), "+f"(c[3])
        : "r"(a.x), "r"(a.y), "r"(a.z), "r"(a.w), "r"(b0), "r"(b1));
}
__device__ __forceinline__ void h_split(float x, __half& hi, __half& lo) {
    hi = __float2half_rn(x);
    lo = __float2half_rn((x - __half2float(hi)) * LO_SCALE);
}
__device__ __forceinline__ void h_split_ns(float x, __half& hi, __half& lo) {
    hi = __float2half_rn(x);
    lo = __float2half_rn(x - __half2float(hi));
}
__device__ __forceinline__ uint32_t h2u(__half2 v) {
    return *reinterpret_cast<uint32_t*>(&v);
}
// NeoX rope: value x at head-dim d, partner y = tile[d^64], position p.
// inv_freq = 10000^(-(d&63)/64) = exp2(-(d&63) * log2(10000)/64)
__device__ __forceinline__ float rope_val(float x, float y, int d, int p) {
    int dj = d & 63;
    float inv_freq = exp2f((float)dj * -0.2076205f);
    float f = (float)p * inv_freq;
    float sn, cs;
    sincosf(f, &sn, &cs);
    return (d < 64) ? (x * cs - y * sn) : (x * cs + y * sn);
}

// ---------------------------------------------------------------------------
// Pack kernels (hidden-state activations + 4 weights)
// ---------------------------------------------------------------------------
__global__ void pack_a_kernel(const float* __restrict__ A, __half* __restrict__ P) {
    int idx = blockIdx.x * blockDim.x + threadIdx.x;
    int lane = idx & 31;
    int t = idx >> 5;
    int ks = t & (KS16_ - 1);
    int mt = t >> 7;
    int lg = lane >> 2, lc = lane & 3;
    int row = mt * 16 + lg;
    int col = ks * 16 + lc * 2;
    const float* r0 = A + (size_t)row * HID_ + col;
    const float* r1 = A + (size_t)(row + 8) * HID_ + col;
    float x[8] = { r0[0], r0[1], r1[0], r1[1], r0[8], r0[9], r1[8], r1[9] };
    __half out[16];
    #pragma unroll
    for (int i = 0; i < 8; i++) h_split(x[i], out[i], out[8 + i]);
    uint4* dst = reinterpret_cast<uint4*>(P + (size_t)idx * 16);
    dst[0] = *reinterpret_cast<uint4*>(&out[0]);
    dst[1] = *reinterpret_cast<uint4*>(&out[8]);
}

__global__ void pack_b4_kernel(const float* __restrict__ w0, const float* __restrict__ w1,
                               const float* __restrict__ w2, const float* __restrict__ w3,
                               __half* __restrict__ P) {
    const int z = blockIdx.y;
    const float* W = (z == 0) ? w0 : (z == 1) ? w1 : (z == 2) ? w2 : w3;
    __half* Pz = P + (size_t)z * HID_ * HID_ * 2;
    int idx = blockIdx.x * blockDim.x + threadIdx.x;
    int lane = idx & 31;
    int t = idx >> 5;
    int ks = t & (KS16_ - 1);
    int nt = t >> 7;
    int lg = lane >> 2, lc = lane & 3;
    int n = nt * 8 + lg;
    int k = ks * 16 + lc * 2;
    float y0 = W[(size_t)k * HID_ + n];
    float y1 = W[(size_t)(k + 1) * HID_ + n];
    float y2 = W[(size_t)(k + 8) * HID_ + n];
    float y3 = W[(size_t)(k + 9) * HID_ + n];
    __half out[8];
    h_split(y0, out[0], out[4]);
    h_split(y1, out[1], out[5]);
    h_split(y2, out[2], out[6]);
    h_split(y3, out[3], out[7]);
    *reinterpret_cast<uint4*>(Pz + (size_t)idx * 8) = *reinterpret_cast<uint4*>(&out[0]);
}

// ---------------------------------------------------------------------------
// fp16 GEMM mainloop (2-pass: hh + al'*bh). Results left in acch/accl.
// ---------------------------------------------------------------------------
constexpr int NT_IT = HID_ / 32;
constexpr uint32_t STAGE_B = 32768;
constexpr int GEMM_DSMEM = 3 * STAGE_B;   // 98304

__device__ __forceinline__ void gemm_mainloop(
    const __half* __restrict__ Apack, const __half* __restrict__ Bpack,
    char* dsm, int row0, int col0,
    float acch[4][4][4], float accl[4][4][4])
{
    const uint32_t sb = (uint32_t)__cvta_generic_to_shared(dsm);
    const int tid = threadIdx.x;
    const int lane = tid & 31;
    const int wid = tid >> 5;
    const int warp_m = wid & 1;
    const int warp_n = wid >> 1;

    const __half* Ab = Apack + (size_t)(row0 >> 4) * (KS16_ * 32 * 16);
    const __half* Bb = Bpack + (size_t)(col0 >> 3) * (KS16_ * 32 * 8);

    auto load_stage = [&](int kt, int s) {
        uint32_t sa = sb + (uint32_t)s * STAGE_B;
        uint32_t sbm = sa + 16384;
        const __half* Abase = Ab + (size_t)kt * 1024;
        const __half* Bbase = Bb + (size_t)kt * 512;
        #pragma unroll
        for (int i = 0; i < 4; i++) {
            int c = tid + i * 256;
            int mt = c >> 7, inner = c & 127;
            cp_async16(sa + (uint32_t)c * 16, Abase + (size_t)mt * 65536 + inner * 8);
        }
        #pragma unroll
        for (int i = 0; i < 4; i++) {
            int c = tid + i * 256;
            int nt = c >> 6, inner = c & 63;
            cp_async16(sbm + (uint32_t)c * 16, Bbase + (size_t)nt * 32768 + inner * 8);
        }
        cp_commit();
    };

    #pragma unroll
    for (int i = 0; i < 4; i++)
        #pragma unroll
        for (int j = 0; j < 4; j++)
            #pragma unroll
            for (int r = 0; r < 4; r++) { acch[i][j][r] = 0.f; accl[i][j][r] = 0.f; }

    load_stage(0, 0);
    load_stage(1, 1);
    load_stage(2, 2);

    for (int kt = 0; kt < NT_IT; kt++) {
        const int s = kt % 3;
        if (kt + 2 >= NT_IT) cp_wait<0>(); else cp_wait<2>();
        __syncthreads();

        const uint4* sa_v = reinterpret_cast<const uint4*>(dsm + (size_t)s * STAGE_B);
        const uint4* sb_v = reinterpret_cast<const uint4*>(dsm + (size_t)s * STAGE_B + 16384);

        #pragma unroll
        for (int ks = 0; ks < 2; ks++) {
            uint4 ah[4], al[4], bf[4];
            #pragma unroll
            for (int mt = 0; mt < 4; mt++) {
                int base = (((warp_m * 4 + mt) * 2 + ks) * 32 + lane) * 2;
                ah[mt] = sa_v[base];
                al[mt] = sa_v[base + 1];
            }
            #pragma unroll
            for (int nt = 0; nt < 4; nt++)
                bf[nt] = sb_v[((warp_n * 4 + nt) * 2 + ks) * 32 + lane];
            #pragma unroll
            for (int mt = 0; mt < 4; mt++)
                #pragma unroll
                for (int nt = 0; nt < 4; nt++)
                    mma_f16(acch[mt][nt], ah[mt], bf[nt].x, bf[nt].y);
            #pragma unroll
            for (int mt = 0; mt < 4; mt++)
                #pragma unroll
                for (int nt = 0; nt < 4; nt++)
                    mma_f16(accl[mt][nt], al[mt], bf[nt].x, bf[nt].y);
        }
        __syncthreads();
        if (kt + 3 < NT_IT) load_stage(kt + 3, s);
    }
}

// ---------------------------------------------------------------------------
// Fused QKV GEMM: 2-pass mainloop, then epilogue writes acc+bias to an fp32
// smem tile, applies RoPE (Q,K) there, and emits attention fragment packs
// directly. Each CTA tile = 128 rows x one full head (128 dims).
// ---------------------------------------------------------------------------
__global__ void __launch_bounds__(256, 1)
gemm_qkv_fused(const __half* __restrict__ Apack, const __half* __restrict__ Bpack,
               const float* __restrict__ bq, const float* __restrict__ bk,
               const float* __restrict__ bv, const int* __restrict__ pos,
               __half* __restrict__ Qout, __half* __restrict__ Kout,
               __half* __restrict__ Vout) {
    extern __shared__ __align__(16) char dsm[];
    const int z = blockIdx.z;
    const size_t BPSZ = (size_t)HID_ * HID_ * 2;
    const int row0 = blockIdx.y * 128;
    const int col0 = blockIdx.x * 128;

    float acch[4][4][4], accl[4][4][4];
    gemm_mainloop(Apack, Bpack + (size_t)z * BPSZ, dsm, row0, col0, acch, accl);

    // Epilogue stage 1: acc + bias -> fp32 smem tile [128][132]
    const int tid = threadIdx.x;
    const int lane = tid & 31;
    const int wid = tid >> 5;
    const int warp_m = wid & 1;
    const int warp_n = wid >> 1;
    const int lg = lane >> 2, lc = lane & 3;
    const float* bias = (z == 0) ? bq : (z == 1) ? bk : bv;
    float* tile = reinterpret_cast<float*>(dsm);

    #pragma unroll
    for (int mt = 0; mt < 4; mt++) {
        int rl = warp_m * 64 + mt * 16 + lg;
        #pragma unroll
        for (int nt = 0; nt < 4; nt++) {
            int cl_ = warp_n * 32 + nt * 8 + lc * 2;
            float b0 = bias[col0 + cl_], b1 = bias[col0 + cl_ + 1];
            float* ch = acch[mt][nt];
            float* cl2 = accl[mt][nt];
            tile[rl * 132 + cl_]           = ch[0] + cl2[0] * INV_LO + b0;
            tile[rl * 132 + cl_ + 1]       = ch[1] + cl2[1] * INV_LO + b1;
            tile[(rl + 8) * 132 + cl_]     = ch[2] + cl2[2] * INV_LO + b0;
            tile[(rl + 8) * 132 + cl_ + 1] = ch[3] + cl2[3] * INV_LO + b1;
        }
    }
    __syncthreads();

    const int b = row0 >> 11;
    const int s0 = row0 & 2047;
    const int h = col0 >> 7;
    const int bh = b * 16 + h;

    if (z == 0) {
        // Q: A-frag pack, rope + scaling. 2048 units of 16 halfs.
        #pragma unroll
        for (int u = 0; u < 8; u++) {
            int unit = tid + u * 256;
            int lane_u = unit & 31, ks = (unit >> 5) & 7, mt_l = unit >> 8;
            int lgu = lane_u >> 2, lcu = lane_u & 3;
            int r0l = mt_l * 16 + lgu;
            int p0 = pos[b * S_ + s0 + r0l];
            int p1 = pos[b * S_ + s0 + r0l + 8];
            int c0 = ks * 16 + 2 * lcu;
            int cols[4] = { c0, c0 + 1, c0 + 8, c0 + 9 };
            int i0[4] = { 0, 1, 4, 5 }, i1[4] = { 2, 3, 6, 7 };
            float vals[8];
            #pragma unroll
            for (int i = 0; i < 4; i++) {
                int d = cols[i];
                vals[i0[i]] = rope_val(tile[r0l * 132 + d],
                                       tile[r0l * 132 + (d ^ 64)], d, p0) * SCALING_;
                vals[i1[i]] = rope_val(tile[(r0l + 8) * 132 + d],
                                       tile[(r0l + 8) * 132 + (d ^ 64)], d, p1) * SCALING_;
            }
            __half out[16];
            #pragma unroll
            for (int i = 0; i < 8; i++) h_split_ns(vals[i], out[i], out[8 + i]);
            uint4* dst = reinterpret_cast<uint4*>(
                Qout + (((size_t)(bh * 128 + (s0 >> 4) + mt_l) * 8 + ks) * 32 + lane_u) * 16);
            dst[0] = *reinterpret_cast<uint4*>(&out[0]);
            dst[1] = *reinterpret_cast<uint4*>(&out[8]);
        }
    } else if (z == 1) {
        // K: B-frag pack, rope. 4096 units of 8 halfs.
        #pragma unroll
        for (int u = 0; u < 16; u++) {
            int unit = tid + u * 256;
            int lane_u = unit & 31, ks = (unit >> 5) & 7, nt_l = unit >> 8;
            int lgu = lane_u >> 2, lcu = lane_u & 3;
            int tl = nt_l * 8 + lgu;
            int p = pos[b * S_ + s0 + tl];
            int c0 = ks * 16 + 2 * lcu;
            int cols[4] = { c0, c0 + 1, c0 + 8, c0 + 9 };
            __half out[8];
            #pragma unroll
            for (int i = 0; i < 4; i++) {
                int d = cols[i];
                float v = rope_val(tile[tl * 132 + d], tile[tl * 132 + (d ^ 64)], d, p);
                h_split_ns(v, out[i], out[4 + i]);
            }
            *reinterpret_cast<uint4*>(
                Kout + (((size_t)(bh * 256 + (s0 >> 3) + nt_l) * 8 + ks) * 32 + lane_u) * 8) =
                *reinterpret_cast<uint4*>(&out[0]);
        }
    } else {
        // V: B-frag pack over tokens. 4096 units of 8 halfs.
        #pragma unroll
        for (int u = 0; u < 16; u++) {
            int unit = tid + u * 256;
            int lane_u = unit & 31, ks_l = (unit >> 5) & 7, nt = unit >> 8;
            int lgu = lane_u >> 2, lcu = lane_u & 3;
            int n = nt * 8 + lgu;
            int k0 = ks_l * 16 + 2 * lcu;
            int toks[4] = { k0, k0 + 1, k0 + 8, k0 + 9 };
            __half out[8];
            #pragma unroll
            for (int i = 0; i < 4; i++)
                h_split_ns(tile[toks[i] * 132 + n], out[i], out[4 + i]);
            *reinterpret_cast<uint4*>(
                Vout + (((size_t)(bh * 16 + nt) * 128 + (s0 >> 4) + ks_l) * 32 + lane_u) * 8) =
                *reinterpret_cast<uint4*>(&out[0]);
        }
    }
}

// Out-projection GEMM (2-pass, fp32 gmem epilogue)
__global__ void __launch_bounds__(256, 1)
gemm_tc_kernel(const __half* __restrict__ Apack, const __half* __restrict__ Bpack,
               float* __restrict__ C) {
    extern __shared__ __align__(16) char dsm[];
    const int row0 = blockIdx.y * 128;
    const int col0 = blockIdx.x * 128;
    float acch[4][4][4], accl[4][4][4];
    gemm_mainloop(Apack, Bpack, dsm, row0, col0, acch, accl);

    const int tid = threadIdx.x;
    const int lane = tid & 31;
    const int wid = tid >> 5;
    const int warp_m = wid & 1;
    const int warp_n = wid >> 1;
    const int lg = lane >> 2, lc = lane & 3;
    #pragma unroll
    for (int mt = 0; mt < 4; mt++) {
        int grow = row0 + (warp_m * 4 + mt) * 16 + lg;
        #pragma unroll
        for (int nt = 0; nt < 4; nt++) {
            int gcol = col0 + (warp_n * 4 + nt) * 8 + lc * 2;
            float* ch = acch[mt][nt];
            float* cl = accl[mt][nt];
            float2 r0 = make_float2(ch[0] + cl[0] * INV_LO, ch[1] + cl[1] * INV_LO);
            float2 r1 = make_float2(ch[2] + cl[2] * INV_LO, ch[3] + cl[3] * INV_LO);
            *reinterpret_cast<float2*>(C + (size_t)grow * HID_ + gcol) = r0;
            *reinterpret_cast<float2*>(C + (size_t)(grow + 8) * HID_ + gcol) = r1;
        }
    }
}

// ---------------------------------------------------------------------------
// Tensor-core causal flash attention (QK 3-pass, PV 2-pass, heavy-first).
// ---------------------------------------------------------------------------
constexpr int AT2_SMEM = 65536 + 2 * 65536;   // 196608

__global__ void __launch_bounds__(256, 1)
attn_tc_kernel(const __half* __restrict__ Qp, const __half* __restrict__ Kp,
               const __half* __restrict__ Vp, __half* __restrict__ APout) {
    extern __shared__ __align__(16) char smem_raw[];
    const uint32_t sb = (uint32_t)__cvta_generic_to_shared(smem_raw);
    const int tid = threadIdx.x;
    const int lane = tid & 31;
    const int warp = tid >> 5;
    const int lg = lane >> 2, lc = lane & 3;
    const int qi = 15 - (int)(blockIdx.x >> 5);
    const int bh = blockIdx.x & 31;
    const int b = bh >> 4, h = bh & 15;
    const int q0 = qi * 128;
    const int ntiles = 2 * qi + 2;

    const __half* Qb = Qp + ((size_t)bh * 128 + (size_t)qi * 8) * 4096;
    const __half* Kb = Kp + (size_t)bh * 256 * 2048;
    const __half* Vb = Vp + (size_t)bh * 16 * 32768;

    #pragma unroll
    for (int i = 0; i < 16; i++) {
        int c = tid + i * 256;
        cp_async16(sb + (uint32_t)c * 16, Qb + (size_t)c * 8);
    }
    cp_commit();

    auto load_KV = [&](int t, int s) {
        uint32_t base = sb + 65536 + (uint32_t)s * 65536;
        const __half* Ksrc = Kb + (size_t)t * 16384;
        #pragma unroll
        for (int i = 0; i < 8; i++) {
            int c = tid + i * 256;
            cp_async16(base + (uint32_t)c * 16, Ksrc + (size_t)c * 8);
        }
        #pragma unroll
        for (int i = 0; i < 8; i++) {
            int c = tid + i * 256;
            int nt = c >> 7, inner = c & 127;
            cp_async16(base + 32768 + (uint32_t)c * 16,
                       Vb + (size_t)nt * 32768 + (size_t)t * 1024 + inner * 8);
        }
        cp_commit();
    };
    load_KV(0, 0);
    load_KV(1, 1);

    float oacc[16][4];
    #pragma unroll
    for (int i = 0; i < 16; i++)
        #pragma unroll
        for (int r = 0; r < 4; r++) oacc[i][r] = 0.f;
    float m0 = -1e30f, m1 = -1e30f, l0 = 0.f, l1 = 0.f;

    const uint4* Qv = reinterpret_cast<const uint4*>(smem_raw);

    for (int t = 0; t < ntiles; t++) {
        if (t + 1 >= ntiles) cp_wait<0>(); else cp_wait<1>();
        __syncthreads();
        const int s = t & 1;
        const uint4* Kv = reinterpret_cast<const uint4*>(smem_raw + 65536 + (size_t)s * 65536);
        const uint4* Vv = Kv + 2048;

        // S = Q @ K^T (3-pass)
        float sacc[8][4];
        #pragma unroll
        for (int nt = 0; nt < 8; nt++)
            #pragma unroll
            for (int r = 0; r < 4; r++) sacc[nt][r] = 0.f;
        #pragma unroll
        for (int ks = 0; ks < 8; ks++) {
            int qbase = ((warp * 8 + ks) * 32 + lane) * 2;
            uint4 ahi = Qv[qbase];
            uint4 alo = Qv[qbase + 1];
            uint4 kf[8];
            #pragma unroll
            for (int nt = 0; nt < 8; nt++)
                kf[nt] = Kv[(nt * 8 + ks) * 32 + lane];
            #pragma unroll
            for (int nt = 0; nt < 8; nt++)
                mma_f16(sacc[nt], ahi, kf[nt].x, kf[nt].y);
            #pragma unroll
            for (int nt = 0; nt < 8; nt++)
                mma_f16(sacc[nt], ahi, kf[nt].z, kf[nt].w);
            #pragma unroll
            for (int nt = 0; nt < 8; nt++)
                mma_f16(sacc[nt], alo, kf[nt].x, kf[nt].y);
        }

        if (t >= ntiles - 2) {
            int gr0 = q0 + warp * 16 + lg;
            int gr1 = gr0 + 8;
            #pragma unroll
            for (int nt = 0; nt < 8; nt++) {
                int gc = t * 64 + nt * 8 + 2 * lc;
                if (gc > gr0)     sacc[nt][0] = -1e30f;
                if (gc + 1 > gr0) sacc[nt][1] = -1e30f;
                if (gc > gr1)     sacc[nt][2] = -1e30f;
                if (gc + 1 > gr1) sacc[nt][3] = -1e30f;
            }
        }

        // Online softmax
        float mx0 = -1e30f, mx1 = -1e30f;
        #pragma unroll
        for (int nt = 0; nt < 8; nt++) {
            mx0 = fmaxf(mx0, fmaxf(sacc[nt][0], sacc[nt][1]));
            mx1 = fmaxf(mx1, fmaxf(sacc[nt][2], sacc[nt][3]));
        }
        mx0 = fmaxf(mx0, __shfl_xor_sync(0xFFFFFFFFu, mx0, 1));
        mx0 = fmaxf(mx0, __shfl_xor_sync(0xFFFFFFFFu, mx0, 2));
        mx1 = fmaxf(mx1, __shfl_xor_sync(0xFFFFFFFFu, mx1, 1));
        mx1 = fmaxf(mx1, __shfl_xor_sync(0xFFFFFFFFu, mx1, 2));
        float mn0 = fmaxf(m0, mx0), mn1 = fmaxf(m1, mx1);
        float c0 = __expf(m0 - mn0), c1 = __expf(m1 - mn1);
        m0 = mn0; m1 = mn1;
        float sum0 = 0.f, sum1 = 0.f;
        #pragma unroll
        for (int nt = 0; nt < 8; nt++) {
            sacc[nt][0] = __expf(sacc[nt][0] - mn0); sum0 += sacc[nt][0];
            sacc[nt][1] = __expf(sacc[nt][1] - mn0); sum0 += sacc[nt][1];
            sacc[nt][2] = __expf(sacc[nt][2] - mn1); sum1 += sacc[nt][2];
            sacc[nt][3] = __expf(sacc[nt][3] - mn1); sum1 += sacc[nt][3];
        }
        sum0 += __shfl_xor_sync(0xFFFFFFFFu, sum0, 1);
        sum0 += __shfl_xor_sync(0xFFFFFFFFu, sum0, 2);
        sum1 += __shfl_xor_sync(0xFFFFFFFFu, sum1, 1);
        sum1 += __shfl_xor_sync(0xFFFFFFFFu, sum1, 2);
        l0 = l0 * c0 + sum0;
        l1 = l1 * c1 + sum1;
        #pragma unroll
        for (int nt = 0; nt < 16; nt++) {
            oacc[nt][0] *= c0; oacc[nt][1] *= c0;
            oacc[nt][2] *= c1; oacc[nt][3] *= c1;
        }

        // O += P @ V (2-pass)
        #pragma unroll
        for (int j = 0; j < 4; j++) {
            const float* pa = sacc[2 * j];
            const float* pb = sacc[2 * j + 1];
            __half2 h01 = __floats2half2_rn(pa[0], pa[1]);
            __half2 h23 = __floats2half2_rn(pa[2], pa[3]);
            __half2 h45 = __floats2half2_rn(pb[0], pb[1]);
            __half2 h67 = __floats2half2_rn(pb[2], pb[3]);
            uint4 phi = make_uint4(h2u(h01), h2u(h23), h2u(h45), h2u(h67));
            #pragma unroll
            for (int blk = 0; blk < 2; blk++) {
                uint4 vf[8];
                #pragma unroll
                for (int i = 0; i < 8; i++)
                    vf[i] = Vv[((blk * 8 + i) * 4 + j) * 32 + lane];
                #pragma unroll
                for (int i = 0; i < 8; i++)
                    mma_f16(oacc[blk * 8 + i], phi, vf[i].x, vf[i].y);
                #pragma unroll
                for (int i = 0; i < 8; i++)
                    mma_f16(oacc[blk * 8 + i], phi, vf[i].z, vf[i].w);
            }
        }

        __syncthreads();
        if (t + 2 < ntiles) load_KV(t + 2, s);
    }

    // Epilogue: normalize + write out-proj A-frag pack directly (scaled split)
    float inv0 = 1.f / l0, inv1 = 1.f / l1;
    const int mtg = b * 128 + qi * 8 + warp;
    #pragma unroll
    for (int j = 0; j < 8; j++) {
        const int ksg = h * 8 + j;
        float x[8] = {
            oacc[2 * j][0] * inv0,     oacc[2 * j][1] * inv0,
            oacc[2 * j][2] * inv1,     oacc[2 * j][3] * inv1,
            oacc[2 * j + 1][0] * inv0, oacc[2 * j + 1][1] * inv0,
            oacc[2 * j + 1][2] * inv1, oacc[2 * j + 1][3] * inv1
        };
        __half out[16];
        #pragma unroll
        for (int i = 0; i < 8; i++) h_split(x[i], out[i], out[8 + i]);
        uint4* dst = reinterpret_cast<uint4*>(
            APout + (((size_t)mtg * KS16_ + ksg) * 32 + lane) * 16);
        dst[0] = *reinterpret_cast<uint4*>(&out[0]);
        dst[1] = *reinterpret_cast<uint4*>(&out[8]);
    }
}

// ---------------------------------------------------------------------------
// Launch
// ---------------------------------------------------------------------------
extern "C" void kernel_launch(void* const* d_in, const int* in_sizes, int n_in,
                              void* d_out, int out_size) {
    const float* hs  = (const float*)d_in[0];
    const int*   pos = (const int*)  d_in[1];
    const float* wq  = (const float*)d_in[2];
    const float* bq  = (const float*)d_in[3];
    const float* wk  = (const float*)d_in[4];
    const float* bk  = (const float*)d_in[5];
    const float* wv  = (const float*)d_in[6];
    const float* bv  = (const float*)d_in[7];
    const float* wc  = (const float*)d_in[8];
    float* out = (float*)d_out;

    __half *apack, *bpack, *qpk, *kpk, *vpk;
    cudaGetSymbolAddress((void**)&apack, g_apack);
    cudaGetSymbolAddress((void**)&bpack, g_bpack);
    cudaGetSymbolAddress((void**)&qpk, g_qpack);
    cudaGetSymbolAddress((void**)&kpk, g_kpack);
    cudaGetSymbolAddress((void**)&vpk, g_vpack);

    const size_t BPSZ = (size_t)HID_ * HID_ * 2;

    cudaFuncSetAttribute(gemm_qkv_fused,
                         cudaFuncAttributeMaxDynamicSharedMemorySize, GEMM_DSMEM);
    cudaFuncSetAttribute(gemm_tc_kernel,
                         cudaFuncAttributeMaxDynamicSharedMemorySize, GEMM_DSMEM);
    cudaFuncSetAttribute(attn_tc_kernel,
                         cudaFuncAttributeMaxDynamicSharedMemorySize, AT2_SMEM);

    // Weight + activation packs
    dim3 pbgrid((HID_ / 8) * KS16_ * 32 / 256, 4);   // (4096, 4)
    pack_b4_kernel<<<pbgrid, 256>>>(wq, wk, wv, wc, bpack);
    const int pa_blocks = (M_ / 16) * KS16_ * 32 / 256;    // 4096
    pack_a_kernel<<<pa_blocks, 256>>>(hs, apack);

    // Fused QKV projections + rope + attention packing (one launch)
    dim3 qkv_grid(HID_ / 128, M_ / 128, 3);   // (16, 32, 3)
    gemm_qkv_fused<<<qkv_grid, 256, GEMM_DSMEM>>>(apack, bpack, bq, bk, bv, pos,
                                                  qpk, kpk, vpk);

    // Tensor-core attention (writes out-proj A-pack directly)
    attn_tc_kernel<<<512, 256, AT2_SMEM>>>(qpk, kpk, vpk, apack);

    // Output projection (2-pass)
    dim3 ggrid(HID_ / 128, M_ / 128);   // (16, 32)
    gemm_tc_kernel<<<ggrid, 256, GEMM_DSMEM>>>(apack, bpack + 3 * BPSZ, out);
}

// round 10
// speedup vs baseline: 5.2061x; 1.2265x over previous
#include <cuda_runtime.h>
#include <cuda_fp16.h>
#include <cstdint>

// Problem constants
constexpr int B_  = 2;
constexpr int S_  = 2048;
constexpr int HID_ = 2048;
constexpr int NH_ = 16;
constexpr int HD_ = 128;
constexpr float SCALING_ = 0.08838834764831845f; // 128^-0.5
constexpr int M_ = B_ * S_;      // 4096
constexpr int KS16_ = HID_ / 16; // 128 k16-steps across K
constexpr float LO_SCALE = 4096.f;
constexpr float INV_LO  = 1.f / 4096.f;

// Scratch (allocation-free rule: __device__ globals)
__device__ __half g_apack[(size_t)M_ * HID_ * 2];
// B packs are hi-only now (2-pass scheme never reads B-lo)
__device__ __half g_bpack[(size_t)4 * HID_ * HID_];
// Attention fragment-packed operands
__device__ __half g_qpack[(size_t)32 * 128 * 8 * 32 * 16];  // hi+lo
__device__ __half g_kpack[(size_t)32 * 256 * 8 * 32 * 4];   // hi only
__device__ __half g_vpack[(size_t)32 * 16 * 128 * 32 * 8];  // hi+lo

// ---------------------------------------------------------------------------
// PTX helpers
// ---------------------------------------------------------------------------
__device__ __forceinline__ void cp_async16(uint32_t s, const void* g) {
    asm volatile("cp.async.cg.shared.global [%0], [%1], 16;" :: "r"(s), "l"(g));
}
__device__ __forceinline__ void cp_commit() {
    asm volatile("cp.async.commit_group;");
}
template <int N>
__device__ __forceinline__ void cp_wait() {
    asm volatile("cp.async.wait_group %0;" :: "n"(N));
}
__device__ __forceinline__ void mma_f16(float* c, uint4 a, uint32_t b0, uint32_t b1) {
    asm volatile(
        "mma.sync.aligned.m16n8k16.row.col.f32.f16.f16.f32 "
        "{%0,%1,%2,%3}, {%4,%5,%6,%7}, {%8,%9}, {%0,%1,%2,%3};"
        : "+f"(c[0]), "+f"(c[1]), "+f"(c[2]), "+f"(c[3])
        : "r"(a.x), "r"(a.y), "r"(a.z), "r"(a.w), "r"(b0), "r"(b1));
}
__device__ __forceinline__ void h_split(float x, __half& hi, __half& lo) {
    hi = __float2half_rn(x);
    lo = __float2half_rn((x - __half2float(hi)) * LO_SCALE);
}
__device__ __forceinline__ void h_split_ns(float x, __half& hi, __half& lo) {
    hi = __float2half_rn(x);
    lo = __float2half_rn(x - __half2float(hi));
}
__device__ __forceinline__ uint32_t h2u(__half2 v) {
    return *reinterpret_cast<uint32_t*>(&v);
}
__device__ __forceinline__ float rope_val(float x, float y, int d, int p) {
    int dj = d & 63;
    float inv_freq = exp2f((float)dj * -0.2076205f);
    float f = (float)p * inv_freq;
    float sn, cs;
    sincosf(f, &sn, &cs);
    return (d < 64) ? (x * cs - y * sn) : (x * cs + y * sn);
}

// ---------------------------------------------------------------------------
// Pack kernels
// ---------------------------------------------------------------------------
__global__ void pack_a_kernel(const float* __restrict__ A, __half* __restrict__ P) {
    int idx = blockIdx.x * blockDim.x + threadIdx.x;
    int lane = idx & 31;
    int t = idx >> 5;
    int ks = t & (KS16_ - 1);
    int mt = t >> 7;
    int lg = lane >> 2, lc = lane & 3;
    int row = mt * 16 + lg;
    int col = ks * 16 + lc * 2;
    const float* r0 = A + (size_t)row * HID_ + col;
    const float* r1 = A + (size_t)(row + 8) * HID_ + col;
    float x[8] = { r0[0], r0[1], r1[0], r1[1], r0[8], r0[9], r1[8], r1[9] };
    __half out[16];
    #pragma unroll
    for (int i = 0; i < 8; i++) h_split(x[i], out[i], out[8 + i]);
    uint4* dst = reinterpret_cast<uint4*>(P + (size_t)idx * 16);
    dst[0] = *reinterpret_cast<uint4*>(&out[0]);
    dst[1] = *reinterpret_cast<uint4*>(&out[8]);
}

// Hi-only B pack (4 weights, one launch)
__global__ void pack_b4_kernel(const float* __restrict__ w0, const float* __restrict__ w1,
                               const float* __restrict__ w2, const float* __restrict__ w3,
                               __half* __restrict__ P) {
    const int z = blockIdx.y;
    const float* W = (z == 0) ? w0 : (z == 1) ? w1 : (z == 2) ? w2 : w3;
    __half* Pz = P + (size_t)z * HID_ * HID_;
    int idx = blockIdx.x * blockDim.x + threadIdx.x;
    int lane = idx & 31;
    int t = idx >> 5;
    int ks = t & (KS16_ - 1);
    int nt = t >> 7;
    int lg = lane >> 2, lc = lane & 3;
    int n = nt * 8 + lg;
    int k = ks * 16 + lc * 2;
    __half out[4];
    out[0] = __float2half_rn(W[(size_t)k * HID_ + n]);
    out[1] = __float2half_rn(W[(size_t)(k + 1) * HID_ + n]);
    out[2] = __float2half_rn(W[(size_t)(k + 8) * HID_ + n]);
    out[3] = __float2half_rn(W[(size_t)(k + 9) * HID_ + n]);
    *reinterpret_cast<uint2*>(Pz + (size_t)idx * 4) = *reinterpret_cast<uint2*>(&out[0]);
}

// ---------------------------------------------------------------------------
// fp16 2-pass GEMM mainloop, BK=64 (4 k16-steps per barrier).
// Stage = A 32KB (hi+lo) + B 16KB (hi only) = 48KB; 3 stages.
// ---------------------------------------------------------------------------
constexpr int NT64 = HID_ / 64;           // 32 iterations
constexpr uint32_t STAGE_B = 49152;       // 48KB
constexpr int GEMM_DSMEM = 3 * STAGE_B;   // 147456

__device__ __forceinline__ void gemm_mainloop(
    const __half* __restrict__ Apack, const __half* __restrict__ Bpack,
    char* dsm, int row0, int col0,
    float acch[4][4][4], float accl[4][4][4])
{
    const uint32_t sb = (uint32_t)__cvta_generic_to_shared(dsm);
    const int tid = threadIdx.x;
    const int lane = tid & 31;
    const int wid = tid >> 5;
    const int warp_m = wid & 1;
    const int warp_n = wid >> 1;

    const __half* Ab = Apack + (size_t)(row0 >> 4) * (KS16_ * 32 * 16);
    const __half* Bb = Bpack + (size_t)(col0 >> 3) * (KS16_ * 32 * 4);

    auto load_stage = [&](int kt64, int s) {
        uint32_t sa = sb + (uint32_t)s * STAGE_B;
        uint32_t sbm = sa + 32768;
        const __half* Abase = Ab + (size_t)kt64 * 2048;   // 4 ks16 * 512 halfs
        const __half* Bbase = Bb + (size_t)kt64 * 512;    // 4 ks16 * 128 halfs
        #pragma unroll
        for (int i = 0; i < 8; i++) {          // A: 2048 x 16B chunks
            int c = tid + i * 256;
            int mt = c >> 8, inner = c & 255;
            cp_async16(sa + (uint32_t)c * 16, Abase + (size_t)mt * 65536 + inner * 8);
        }
        #pragma unroll
        for (int i = 0; i < 4; i++) {          // B: 1024 x 16B chunks
            int c = tid + i * 256;
            int nt = c >> 6, inner = c & 63;
            cp_async16(sbm + (uint32_t)c * 16, Bbase + (size_t)nt * 16384 + inner * 8);
        }
        cp_commit();
    };

    #pragma unroll
    for (int i = 0; i < 4; i++)
        #pragma unroll
        for (int j = 0; j < 4; j++)
            #pragma unroll
            for (int r = 0; r < 4; r++) { acch[i][j][r] = 0.f; accl[i][j][r] = 0.f; }

    load_stage(0, 0);
    load_stage(1, 1);
    load_stage(2, 2);

    for (int kt = 0; kt < NT64; kt++) {
        const int s = kt % 3;
        if (kt + 2 >= NT64) cp_wait<0>(); else cp_wait<2>();
        __syncthreads();

        const uint4* sa_v = reinterpret_cast<const uint4*>(dsm + (size_t)s * STAGE_B);
        const uint2* sb_v = reinterpret_cast<const uint2*>(dsm + (size_t)s * STAGE_B + 32768);

        #pragma unroll
        for (int ks = 0; ks < 4; ks++) {
            uint4 ah[4], al[4];
            uint2 bf[4];
            #pragma unroll
            for (int mt = 0; mt < 4; mt++) {
                int base = (((warp_m * 4 + mt) * 4 + ks) * 32 + lane) * 2;
                ah[mt] = sa_v[base];
                al[mt] = sa_v[base + 1];
            }
            #pragma unroll
            for (int nt = 0; nt < 4; nt++)
                bf[nt] = sb_v[((warp_n * 4 + nt) * 4 + ks) * 32 + lane];
            #pragma unroll
            for (int mt = 0; mt < 4; mt++)
                #pragma unroll
                for (int nt = 0; nt < 4; nt++)
                    mma_f16(acch[mt][nt], ah[mt], bf[nt].x, bf[nt].y);
            #pragma unroll
            for (int mt = 0; mt < 4; mt++)
                #pragma unroll
                for (int nt = 0; nt < 4; nt++)
                    mma_f16(accl[mt][nt], al[mt], bf[nt].x, bf[nt].y);
        }
        __syncthreads();
        if (kt + 3 < NT64) load_stage(kt + 3, s);
    }
}

// ---------------------------------------------------------------------------
// Fused QKV GEMM + bias + RoPE + attention-fragment packing.
// ---------------------------------------------------------------------------
__global__ void __launch_bounds__(256, 1)
gemm_qkv_fused(const __half* __restrict__ Apack, const __half* __restrict__ Bpack,
               const float* __restrict__ bq, const float* __restrict__ bk,
               const float* __restrict__ bv, const int* __restrict__ pos,
               __half* __restrict__ Qout, __half* __restrict__ Kout,
               __half* __restrict__ Vout) {
    extern __shared__ __align__(16) char dsm[];
    const int z = blockIdx.z;
    const size_t BPSZ = (size_t)HID_ * HID_;
    const int row0 = blockIdx.y * 128;
    const int col0 = blockIdx.x * 128;

    float acch[4][4][4], accl[4][4][4];
    gemm_mainloop(Apack, Bpack + (size_t)z * BPSZ, dsm, row0, col0, acch, accl);

    // Epilogue stage 1: acc + bias -> fp32 smem tile [128][132]
    const int tid = threadIdx.x;
    const int lane = tid & 31;
    const int wid = tid >> 5;
    const int warp_m = wid & 1;
    const int warp_n = wid >> 1;
    const int lg = lane >> 2, lc = lane & 3;
    const float* bias = (z == 0) ? bq : (z == 1) ? bk : bv;
    float* tile = reinterpret_cast<float*>(dsm);

    #pragma unroll
    for (int mt = 0; mt < 4; mt++) {
        int rl = warp_m * 64 + mt * 16 + lg;
        #pragma unroll
        for (int nt = 0; nt < 4; nt++) {
            int cl_ = warp_n * 32 + nt * 8 + lc * 2;
            float b0 = bias[col0 + cl_], b1 = bias[col0 + cl_ + 1];
            float* ch = acch[mt][nt];
            float* cl2 = accl[mt][nt];
            tile[rl * 132 + cl_]           = ch[0] + cl2[0] * INV_LO + b0;
            tile[rl * 132 + cl_ + 1]       = ch[1] + cl2[1] * INV_LO + b1;
            tile[(rl + 8) * 132 + cl_]     = ch[2] + cl2[2] * INV_LO + b0;
            tile[(rl + 8) * 132 + cl_ + 1] = ch[3] + cl2[3] * INV_LO + b1;
        }
    }
    __syncthreads();

    const int b = row0 >> 11;
    const int s0 = row0 & 2047;
    const int h = col0 >> 7;
    const int bh = b * 16 + h;

    if (z == 0) {
        // Q: A-frag pack (hi+lo), rope + scaling.
        #pragma unroll
        for (int u = 0; u < 8; u++) {
            int unit = tid + u * 256;
            int lane_u = unit & 31, ks = (unit >> 5) & 7, mt_l = unit >> 8;
            int lgu = lane_u >> 2, lcu = lane_u & 3;
            int r0l = mt_l * 16 + lgu;
            int p0 = pos[b * S_ + s0 + r0l];
            int p1 = pos[b * S_ + s0 + r0l + 8];
            int c0 = ks * 16 + 2 * lcu;
            int cols[4] = { c0, c0 + 1, c0 + 8, c0 + 9 };
            int i0[4] = { 0, 1, 4, 5 }, i1[4] = { 2, 3, 6, 7 };
            float vals[8];
            #pragma unroll
            for (int i = 0; i < 4; i++) {
                int d = cols[i];
                vals[i0[i]] = rope_val(tile[r0l * 132 + d],
                                       tile[r0l * 132 + (d ^ 64)], d, p0) * SCALING_;
                vals[i1[i]] = rope_val(tile[(r0l + 8) * 132 + d],
                                       tile[(r0l + 8) * 132 + (d ^ 64)], d, p1) * SCALING_;
            }
            __half out[16];
            #pragma unroll
            for (int i = 0; i < 8; i++) h_split_ns(vals[i], out[i], out[8 + i]);
            uint4* dst = reinterpret_cast<uint4*>(
                Qout + (((size_t)(bh * 128 + (s0 >> 4) + mt_l) * 8 + ks) * 32 + lane_u) * 16);
            dst[0] = *reinterpret_cast<uint4*>(&out[0]);
            dst[1] = *reinterpret_cast<uint4*>(&out[8]);
        }
    } else if (z == 1) {
        // K: B-frag pack (hi only), rope.
        #pragma unroll
        for (int u = 0; u < 16; u++) {
            int unit = tid + u * 256;
            int lane_u = unit & 31, ks = (unit >> 5) & 7, nt_l = unit >> 8;
            int lgu = lane_u >> 2, lcu = lane_u & 3;
            int tl = nt_l * 8 + lgu;
            int p = pos[b * S_ + s0 + tl];
            int c0 = ks * 16 + 2 * lcu;
            int cols[4] = { c0, c0 + 1, c0 + 8, c0 + 9 };
            __half out[4];
            #pragma unroll
            for (int i = 0; i < 4; i++) {
                int d = cols[i];
                out[i] = __float2half_rn(
                    rope_val(tile[tl * 132 + d], tile[tl * 132 + (d ^ 64)], d, p));
            }
            *reinterpret_cast<uint2*>(
                Kout + (((size_t)(bh * 256 + (s0 >> 3) + nt_l) * 8 + ks) * 32 + lane_u) * 4) =
                *reinterpret_cast<uint2*>(&out[0]);
        }
    } else {
        // V: B-frag pack (hi+lo) over tokens.
        #pragma unroll
        for (int u = 0; u < 16; u++) {
            int unit = tid + u * 256;
            int lane_u = unit & 31, ks_l = (unit >> 5) & 7, nt = unit >> 8;
            int lgu = lane_u >> 2, lcu = lane_u & 3;
            int n = nt * 8 + lgu;
            int k0 = ks_l * 16 + 2 * lcu;
            int toks[4] = { k0, k0 + 1, k0 + 8, k0 + 9 };
            __half out[8];
            #pragma unroll
            for (int i = 0; i < 4; i++)
                h_split_ns(tile[toks[i] * 132 + n], out[i], out[4 + i]);
            *reinterpret_cast<uint4*>(
                Vout + (((size_t)(bh * 16 + nt) * 128 + (s0 >> 4) + ks_l) * 32 + lane_u) * 8) =
                *reinterpret_cast<uint4*>(&out[0]);
        }
    }
}

// Out-projection GEMM (2-pass, fp32 gmem epilogue)
__global__ void __launch_bounds__(256, 1)
gemm_tc_kernel(const __half* __restrict__ Apack, const __half* __restrict__ Bpack,
               float* __restrict__ C) {
    extern __shared__ __align__(16) char dsm[];
    const int row0 = blockIdx.y * 128;
    const int col0 = blockIdx.x * 128;
    float acch[4][4][4], accl[4][4][4];
    gemm_mainloop(Apack, Bpack, dsm, row0, col0, acch, accl);

    const int tid = threadIdx.x;
    const int lane = tid & 31;
    const int wid = tid >> 5;
    const int warp_m = wid & 1;
    const int warp_n = wid >> 1;
    const int lg = lane >> 2, lc = lane & 3;
    #pragma unroll
    for (int mt = 0; mt < 4; mt++) {
        int grow = row0 + (warp_m * 4 + mt) * 16 + lg;
        #pragma unroll
        for (int nt = 0; nt < 4; nt++) {
            int gcol = col0 + (warp_n * 4 + nt) * 8 + lc * 2;
            float* ch = acch[mt][nt];
            float* cl = accl[mt][nt];
            float2 r0 = make_float2(ch[0] + cl[0] * INV_LO, ch[1] + cl[1] * INV_LO);
            float2 r1 = make_float2(ch[2] + cl[2] * INV_LO, ch[3] + cl[3] * INV_LO);
            *reinterpret_cast<float2*>(C + (size_t)grow * HID_ + gcol) = r0;
            *reinterpret_cast<float2*>(C + (size_t)(grow + 8) * HID_ + gcol) = r1;
        }
    }
}

// ---------------------------------------------------------------------------
// Tensor-core causal flash attention. QK 2-pass (K hi-only), PV 2-pass.
// smem: Q 64KB + 2 x (K 16KB + V 32KB) = 160KB.
// ---------------------------------------------------------------------------
constexpr uint32_t KV_STAGE = 49152;            // 16KB K + 32KB V
constexpr int AT2_SMEM = 65536 + 2 * 49152;     // 163840

__global__ void __launch_bounds__(256, 1)
attn_tc_kernel(const __half* __restrict__ Qp, const __half* __restrict__ Kp,
               const __half* __restrict__ Vp, __half* __restrict__ APout) {
    extern __shared__ __align__(16) char smem_raw[];
    const uint32_t sb = (uint32_t)__cvta_generic_to_shared(smem_raw);
    const int tid = threadIdx.x;
    const int lane = tid & 31;
    const int warp = tid >> 5;
    const int lg = lane >> 2, lc = lane & 3;
    const int qi = 15 - (int)(blockIdx.x >> 5);
    const int bh = blockIdx.x & 31;
    const int b = bh >> 4, h = bh & 15;
    const int q0 = qi * 128;
    const int ntiles = 2 * qi + 2;

    const __half* Qb = Qp + ((size_t)bh * 128 + (size_t)qi * 8) * 4096;
    const __half* Kb = Kp + (size_t)bh * 256 * 1024;     // hi-only: 1024 halfs/nt
    const __half* Vb = Vp + (size_t)bh * 16 * 32768;

    #pragma unroll
    for (int i = 0; i < 16; i++) {
        int c = tid + i * 256;
        cp_async16(sb + (uint32_t)c * 16, Qb + (size_t)c * 8);
    }
    cp_commit();

    auto load_KV = [&](int t, int s) {
        uint32_t base = sb + 65536 + (uint32_t)s * KV_STAGE;
        const __half* Ksrc = Kb + (size_t)t * 8192;      // 8 nt x 1024 halfs
        #pragma unroll
        for (int i = 0; i < 4; i++) {                    // K: 1024 chunks
            int c = tid + i * 256;
            cp_async16(base + (uint32_t)c * 16, Ksrc + (size_t)c * 8);
        }
        #pragma unroll
        for (int i = 0; i < 8; i++) {                    // V: 2048 chunks
            int c = tid + i * 256;
            int nt = c >> 7, inner = c & 127;
            cp_async16(base + 16384 + (uint32_t)c * 16,
                       Vb + (size_t)nt * 32768 + (size_t)t * 1024 + inner * 8);
        }
        cp_commit();
    };
    load_KV(0, 0);
    load_KV(1, 1);

    float oacc[16][4];
    #pragma unroll
    for (int i = 0; i < 16; i++)
        #pragma unroll
        for (int r = 0; r < 4; r++) oacc[i][r] = 0.f;
    float m0 = -1e30f, m1 = -1e30f, l0 = 0.f, l1 = 0.f;

    const uint4* Qv = reinterpret_cast<const uint4*>(smem_raw);

    for (int t = 0; t < ntiles; t++) {
        if (t + 1 >= ntiles) cp_wait<0>(); else cp_wait<1>();
        __syncthreads();
        const int s = t & 1;
        const uint2* Kv = reinterpret_cast<const uint2*>(smem_raw + 65536 + (size_t)s * KV_STAGE);
        const uint4* Vv = reinterpret_cast<const uint4*>(smem_raw + 65536 + (size_t)s * KV_STAGE + 16384);

        // S = Q @ K^T (2-pass: q-hi*k-hi + q-lo*k-hi)
        float sacc[8][4];
        #pragma unroll
        for (int nt = 0; nt < 8; nt++)
            #pragma unroll
            for (int r = 0; r < 4; r++) sacc[nt][r] = 0.f;
        #pragma unroll
        for (int ks = 0; ks < 8; ks++) {
            int qbase = ((warp * 8 + ks) * 32 + lane) * 2;
            uint4 ahi = Qv[qbase];
            uint4 alo = Qv[qbase + 1];
            uint2 kf[8];
            #pragma unroll
            for (int nt = 0; nt < 8; nt++)
                kf[nt] = Kv[(nt * 8 + ks) * 32 + lane];
            #pragma unroll
            for (int nt = 0; nt < 8; nt++)
                mma_f16(sacc[nt], ahi, kf[nt].x, kf[nt].y);
            #pragma unroll
            for (int nt = 0; nt < 8; nt++)
                mma_f16(sacc[nt], alo, kf[nt].x, kf[nt].y);
        }

        if (t >= ntiles - 2) {
            int gr0 = q0 + warp * 16 + lg;
            int gr1 = gr0 + 8;
            #pragma unroll
            for (int nt = 0; nt < 8; nt++) {
                int gc = t * 64 + nt * 8 + 2 * lc;
                if (gc > gr0)     sacc[nt][0] = -1e30f;
                if (gc + 1 > gr0) sacc[nt][1] = -1e30f;
                if (gc > gr1)     sacc[nt][2] = -1e30f;
                if (gc + 1 > gr1) sacc[nt][3] = -1e30f;
            }
        }

        // Online softmax
        float mx0 = -1e30f, mx1 = -1e30f;
        #pragma unroll
        for (int nt = 0; nt < 8; nt++) {
            mx0 = fmaxf(mx0, fmaxf(sacc[nt][0], sacc[nt][1]));
            mx1 = fmaxf(mx1, fmaxf(sacc[nt][2], sacc[nt][3]));
        }
        mx0 = fmaxf(mx0, __shfl_xor_sync(0xFFFFFFFFu, mx0, 1));
        mx0 = fmaxf(mx0, __shfl_xor_sync(0xFFFFFFFFu, mx0, 2));
        mx1 = fmaxf(mx1, __shfl_xor_sync(0xFFFFFFFFu, mx1, 1));
        mx1 = fmaxf(mx1, __shfl_xor_sync(0xFFFFFFFFu, mx1, 2));
        float mn0 = fmaxf(m0, mx0), mn1 = fmaxf(m1, mx1);
        float c0 = __expf(m0 - mn0), c1 = __expf(m1 - mn1);
        m0 = mn0; m1 = mn1;
        float sum0 = 0.f, sum1 = 0.f;
        #pragma unroll
        for (int nt = 0; nt < 8; nt++) {
            sacc[nt][0] = __expf(sacc[nt][0] - mn0); sum0 += sacc[nt][0];
            sacc[nt][1] = __expf(sacc[nt][1] - mn0); sum0 += sacc[nt][1];
            sacc[nt][2] = __expf(sacc[nt][2] - mn1); sum1 += sacc[nt][2];
            sacc[nt][3] = __expf(sacc[nt][3] - mn1); sum1 += sacc[nt][3];
        }
        sum0 += __shfl_xor_sync(0xFFFFFFFFu, sum0, 1);
        sum0 += __shfl_xor_sync(0xFFFFFFFFu, sum0, 2);
        sum1 += __shfl_xor_sync(0xFFFFFFFFu, sum1, 1);
        sum1 += __shfl_xor_sync(0xFFFFFFFFu, sum1, 2);
        l0 = l0 * c0 + sum0;
        l1 = l1 * c1 + sum1;
        #pragma unroll
        for (int nt = 0; nt < 16; nt++) {
            oacc[nt][0] *= c0; oacc[nt][1] *= c0;
            oacc[nt][2] *= c1; oacc[nt][3] *= c1;
        }

        // O += P @ V (2-pass: P-hi x V-hi + P-hi x V-lo)
        #pragma unroll
        for (int j = 0; j < 4; j++) {
            const float* pa = sacc[2 * j];
            const float* pb = sacc[2 * j + 1];
            __half2 h01 = __floats2half2_rn(pa[0], pa[1]);
            __half2 h23 = __floats2half2_rn(pa[2], pa[3]);
            __half2 h45 = __floats2half2_rn(pb[0], pb[1]);
            __half2 h67 = __floats2half2_rn(pb[2], pb[3]);
            uint4 phi = make_uint4(h2u(h01), h2u(h23), h2u(h45), h2u(h67));
            #pragma unroll
            for (int blk = 0; blk < 2; blk++) {
                uint4 vf[8];
                #pragma unroll
                for (int i = 0; i < 8; i++)
                    vf[i] = Vv[((blk * 8 + i) * 4 + j) * 32 + lane];
                #pragma unroll
                for (int i = 0; i < 8; i++)
                    mma_f16(oacc[blk * 8 + i], phi, vf[i].x, vf[i].y);
                #pragma unroll
                for (int i = 0; i < 8; i++)
                    mma_f16(oacc[blk * 8 + i], phi, vf[i].z, vf[i].w);
            }
        }

        __syncthreads();
        if (t + 2 < ntiles) load_KV(t + 2, s);
    }

    // Epilogue: normalize + write out-proj A-frag pack directly (scaled split)
    float inv0 = 1.f / l0, inv1 = 1.f / l1;
    const int mtg = b * 128 + qi * 8 + warp;
    #pragma unroll
    for (int j = 0; j < 8; j++) {
        const int ksg = h * 8 + j;
        float x[8] = {
            oacc[2 * j][0] * inv0,     oacc[2 * j][1] * inv0,
            oacc[2 * j][2] * inv1,     oacc[2 * j][3] * inv1,
            oacc[2 * j + 1][0] * inv0, oacc[2 * j + 1][1] * inv0,
            oacc[2 * j + 1][2] * inv1, oacc[2 * j + 1][3] * inv1
        };
        __half out[16];
        #pragma unroll
        for (int i = 0; i < 8; i++) h_split(x[i], out[i], out[8 + i]);
        uint4* dst = reinterpret_cast<uint4*>(
            APout + (((size_t)mtg * KS16_ + ksg) * 32 + lane) * 16);
        dst[0] = *reinterpret_cast<uint4*>(&out[0]);
        dst[1] = *reinterpret_cast<uint4*>(&out[8]);
    }
}

// ---------------------------------------------------------------------------
// Launch
// ---------------------------------------------------------------------------
extern "C" void kernel_launch(void* const* d_in, const int* in_sizes, int n_in,
                              void* d_out, int out_size) {
    const float* hs  = (const float*)d_in[0];
    const int*   pos = (const int*)  d_in[1];
    const float* wq  = (const float*)d_in[2];
    const float* bq  = (const float*)d_in[3];
    const float* wk  = (const float*)d_in[4];
    const float* bk  = (const float*)d_in[5];
    const float* wv  = (const float*)d_in[6];
    const float* bv  = (const float*)d_in[7];
    const float* wc  = (const float*)d_in[8];
    float* out = (float*)d_out;

    __half *apack, *bpack, *qpk, *kpk, *vpk;
    cudaGetSymbolAddress((void**)&apack, g_apack);
    cudaGetSymbolAddress((void**)&bpack, g_bpack);
    cudaGetSymbolAddress((void**)&qpk, g_qpack);
    cudaGetSymbolAddress((void**)&kpk, g_kpack);
    cudaGetSymbolAddress((void**)&vpk, g_vpack);

    const size_t BPSZ = (size_t)HID_ * HID_;   // hi-only pack size

    cudaFuncSetAttribute(gemm_qkv_fused,
                         cudaFuncAttributeMaxDynamicSharedMemorySize, GEMM_DSMEM);
    cudaFuncSetAttribute(gemm_tc_kernel,
                         cudaFuncAttributeMaxDynamicSharedMemorySize, GEMM_DSMEM);
    cudaFuncSetAttribute(attn_tc_kernel,
                         cudaFuncAttributeMaxDynamicSharedMemorySize, AT2_SMEM);

    // Weight + activation packs
    dim3 pbgrid((HID_ / 8) * KS16_ * 32 / 256, 4);   // (4096, 4)
    pack_b4_kernel<<<pbgrid, 256>>>(wq, wk, wv, wc, bpack);
    const int pa_blocks = (M_ / 16) * KS16_ * 32 / 256;    // 4096
    pack_a_kernel<<<pa_blocks, 256>>>(hs, apack);

    // Fused QKV projections + rope + attention packing
    dim3 qkv_grid(HID_ / 128, M_ / 128, 3);   // (16, 32, 3)
    gemm_qkv_fused<<<qkv_grid, 256, GEMM_DSMEM>>>(apack, bpack, bq, bk, bv, pos,
                                                  qpk, kpk, vpk);

    // Tensor-core attention (writes out-proj A-pack directly)
    attn_tc_kernel<<<512, 256, AT2_SMEM>>>(qpk, kpk, vpk, apack);

    // Output projection (2-pass)
    dim3 ggrid(HID_ / 128, M_ / 128);   // (16, 32)
    gemm_tc_kernel<<<ggrid, 256, GEMM_DSMEM>>>(apack, bpack + 3 * BPSZ, out);
}

// round 11
// speedup vs baseline: 9.6409x; 1.8519x over previous
#include <cuda_runtime.h>
#include <cuda_fp16.h>
#include <cstdint>

// Problem constants
constexpr int B_  = 2;
constexpr int S_  = 2048;
constexpr int HID_ = 2048;
constexpr int NH_ = 16;
constexpr int HD_ = 128;
constexpr float SCALING_ = 0.08838834764831845f; // 128^-0.5
constexpr int M_ = B_ * S_;      // 4096
constexpr int KS16_ = HID_ / 16; // 128 k16-steps across K

// Scratch (allocation-free rule: __device__ globals)
// A pack: hi-only fp16 fragments [mt][ks16][lane][8]
__device__ __half g_apack[(size_t)M_ * HID_];
// B packs: hi-only [nt][ks16][lane][4], 4 weights
__device__ __half g_bpack[(size_t)4 * HID_ * HID_];
// Attention fragment-packed operands
__device__ __half g_qpack[(size_t)32 * 128 * 8 * 32 * 16];  // Q: hi+lo (QK 2-pass)
__device__ __half g_kpack[(size_t)32 * 256 * 8 * 32 * 4];   // K: hi only
__device__ __half g_vpack[(size_t)32 * 16 * 128 * 32 * 4];  // V: hi only

// ---------------------------------------------------------------------------
// PTX helpers
// ---------------------------------------------------------------------------
__device__ __forceinline__ void cp_async16(uint32_t s, const void* g) {
    asm volatile("cp.async.cg.shared.global [%0], [%1], 16;" :: "r"(s), "l"(g));
}
__device__ __forceinline__ void cp_commit() {
    asm volatile("cp.async.commit_group;");
}
template <int N>
__device__ __forceinline__ void cp_wait() {
    asm volatile("cp.async.wait_group %0;" :: "n"(N));
}
__device__ __forceinline__ void mma_f16(float* c, uint4 a, uint32_t b0, uint32_t b1) {
    asm volatile(
        "mma.sync.aligned.m16n8k16.row.col.f32.f16.f16.f32 "
        "{%0,%1,%2,%3}, {%4,%5,%6,%7}, {%8,%9}, {%0,%1,%2,%3};"
        : "+f"(c[0]), "+f"(c[1]), "+f"(c[2]), "+f"(c[3])
        : "r"(a.x), "r"(a.y), "r"(a.z), "r"(a.w), "r"(b0), "r"(b1));
}
__device__ __forceinline__ void h_split_ns(float x, __half& hi, __half& lo) {
    hi = __float2half_rn(x);
    lo = __float2half_rn(x - __half2float(hi));
}
__device__ __forceinline__ uint32_t h2u(__half2 v) {
    return *reinterpret_cast<uint32_t*>(&v);
}
__device__ __forceinline__ float rope_val(float x, float y, int d, int p) {
    int dj = d & 63;
    float inv_freq = exp2f((float)dj * -0.2076205f);
    float f = (float)p * inv_freq;
    float sn, cs;
    sincosf(f, &sn, &cs);
    return (d < 64) ? (x * cs - y * sn) : (x * cs + y * sn);
}

// ---------------------------------------------------------------------------
// Pack kernels (hi-only)
// ---------------------------------------------------------------------------
__global__ void pack_a_kernel(const float* __restrict__ A, __half* __restrict__ P) {
    int idx = blockIdx.x * blockDim.x + threadIdx.x;
    int lane = idx & 31;
    int t = idx >> 5;
    int ks = t & (KS16_ - 1);
    int mt = t >> 7;
    int lg = lane >> 2, lc = lane & 3;
    int row = mt * 16 + lg;
    int col = ks * 16 + lc * 2;
    const float* r0 = A + (size_t)row * HID_ + col;
    const float* r1 = A + (size_t)(row + 8) * HID_ + col;
    __half out[8];
    out[0] = __float2half_rn(r0[0]);
    out[1] = __float2half_rn(r0[1]);
    out[2] = __float2half_rn(r1[0]);
    out[3] = __float2half_rn(r1[1]);
    out[4] = __float2half_rn(r0[8]);
    out[5] = __float2half_rn(r0[9]);
    out[6] = __float2half_rn(r1[8]);
    out[7] = __float2half_rn(r1[9]);
    *reinterpret_cast<uint4*>(P + (size_t)idx * 8) = *reinterpret_cast<uint4*>(&out[0]);
}

__global__ void pack_b4_kernel(const float* __restrict__ w0, const float* __restrict__ w1,
                               const float* __restrict__ w2, const float* __restrict__ w3,
                               __half* __restrict__ P) {
    const int z = blockIdx.y;
    const float* W = (z == 0) ? w0 : (z == 1) ? w1 : (z == 2) ? w2 : w3;
    __half* Pz = P + (size_t)z * HID_ * HID_;
    int idx = blockIdx.x * blockDim.x + threadIdx.x;
    int lane = idx & 31;
    int t = idx >> 5;
    int ks = t & (KS16_ - 1);
    int nt = t >> 7;
    int lg = lane >> 2, lc = lane & 3;
    int n = nt * 8 + lg;
    int k = ks * 16 + lc * 2;
    __half out[4];
    out[0] = __float2half_rn(W[(size_t)k * HID_ + n]);
    out[1] = __float2half_rn(W[(size_t)(k + 1) * HID_ + n]);
    out[2] = __float2half_rn(W[(size_t)(k + 8) * HID_ + n]);
    out[3] = __float2half_rn(W[(size_t)(k + 9) * HID_ + n]);
    *reinterpret_cast<uint2*>(Pz + (size_t)idx * 4) = *reinterpret_cast<uint2*>(&out[0]);
}

// ---------------------------------------------------------------------------
// fp16 1-pass GEMM mainloop, BK=64. Stage = A 16KB + B 16KB = 32KB; 3 stages.
// ---------------------------------------------------------------------------
constexpr int NT64 = HID_ / 64;           // 32 iterations
constexpr uint32_t STAGE_B = 32768;
constexpr int GEMM_DSMEM = 3 * STAGE_B;   // 98304

__device__ __forceinline__ void gemm_mainloop(
    const __half* __restrict__ Apack, const __half* __restrict__ Bpack,
    char* dsm, int row0, int col0, float acc[4][4][4])
{
    const uint32_t sb = (uint32_t)__cvta_generic_to_shared(dsm);
    const int tid = threadIdx.x;
    const int lane = tid & 31;
    const int wid = tid >> 5;
    const int warp_m = wid & 1;
    const int warp_n = wid >> 1;

    const __half* Ab = Apack + (size_t)(row0 >> 4) * (KS16_ * 32 * 8);
    const __half* Bb = Bpack + (size_t)(col0 >> 3) * (KS16_ * 32 * 4);

    auto load_stage = [&](int kt64, int s) {
        uint32_t sa = sb + (uint32_t)s * STAGE_B;
        uint32_t sbm = sa + 16384;
        const __half* Abase = Ab + (size_t)kt64 * 1024;   // 4 ks16 * 256 halfs
        const __half* Bbase = Bb + (size_t)kt64 * 512;    // 4 ks16 * 128 halfs
        #pragma unroll
        for (int i = 0; i < 4; i++) {          // A: 1024 x 16B chunks
            int c = tid + i * 256;
            int mt = c >> 7, inner = c & 127;
            cp_async16(sa + (uint32_t)c * 16, Abase + (size_t)mt * 32768 + inner * 8);
        }
        #pragma unroll
        for (int i = 0; i < 4; i++) {          // B: 1024 x 16B chunks
            int c = tid + i * 256;
            int nt = c >> 6, inner = c & 63;
            cp_async16(sbm + (uint32_t)c * 16, Bbase + (size_t)nt * 16384 + inner * 8);
        }
        cp_commit();
    };

    #pragma unroll
    for (int i = 0; i < 4; i++)
        #pragma unroll
        for (int j = 0; j < 4; j++)
            #pragma unroll
            for (int r = 0; r < 4; r++) acc[i][j][r] = 0.f;

    load_stage(0, 0);
    load_stage(1, 1);
    load_stage(2, 2);

    for (int kt = 0; kt < NT64; kt++) {
        const int s = kt % 3;
        if (kt + 2 >= NT64) cp_wait<0>(); else cp_wait<2>();
        __syncthreads();

        const uint4* sa_v = reinterpret_cast<const uint4*>(dsm + (size_t)s * STAGE_B);
        const uint2* sb_v = reinterpret_cast<const uint2*>(dsm + (size_t)s * STAGE_B + 16384);

        #pragma unroll
        for (int ks = 0; ks < 4; ks++) {
            uint4 ah[4];
            uint2 bf[4];
            #pragma unroll
            for (int mt = 0; mt < 4; mt++)
                ah[mt] = sa_v[(((warp_m * 4 + mt) * 4 + ks) * 32 + lane)];
            #pragma unroll
            for (int nt = 0; nt < 4; nt++)
                bf[nt] = sb_v[((warp_n * 4 + nt) * 4 + ks) * 32 + lane];
            #pragma unroll
            for (int mt = 0; mt < 4; mt++)
                #pragma unroll
                for (int nt = 0; nt < 4; nt++)
                    mma_f16(acc[mt][nt], ah[mt], bf[nt].x, bf[nt].y);
        }
        __syncthreads();
        if (kt + 3 < NT64) load_stage(kt + 3, s);
    }
}

// ---------------------------------------------------------------------------
// Fused QKV GEMM + bias + RoPE + attention-fragment packing.
// ---------------------------------------------------------------------------
__global__ void __launch_bounds__(256, 2)
gemm_qkv_fused(const __half* __restrict__ Apack, const __half* __restrict__ Bpack,
               const float* __restrict__ bq, const float* __restrict__ bk,
               const float* __restrict__ bv, const int* __restrict__ pos,
               __half* __restrict__ Qout, __half* __restrict__ Kout,
               __half* __restrict__ Vout) {
    extern __shared__ __align__(16) char dsm[];
    const int z = blockIdx.z;
    const size_t BPSZ = (size_t)HID_ * HID_;
    const int row0 = blockIdx.y * 128;
    const int col0 = blockIdx.x * 128;

    float acc[4][4][4];
    gemm_mainloop(Apack, Bpack + (size_t)z * BPSZ, dsm, row0, col0, acc);

    // Epilogue stage 1: acc + bias -> fp32 smem tile [128][132]
    const int tid = threadIdx.x;
    const int lane = tid & 31;
    const int wid = tid >> 5;
    const int warp_m = wid & 1;
    const int warp_n = wid >> 1;
    const int lg = lane >> 2, lc = lane & 3;
    const float* bias = (z == 0) ? bq : (z == 1) ? bk : bv;
    float* tile = reinterpret_cast<float*>(dsm);

    #pragma unroll
    for (int mt = 0; mt < 4; mt++) {
        int rl = warp_m * 64 + mt * 16 + lg;
        #pragma unroll
        for (int nt = 0; nt < 4; nt++) {
            int cl_ = warp_n * 32 + nt * 8 + lc * 2;
            float b0 = bias[col0 + cl_], b1 = bias[col0 + cl_ + 1];
            float* ch = acc[mt][nt];
            tile[rl * 132 + cl_]           = ch[0] + b0;
            tile[rl * 132 + cl_ + 1]       = ch[1] + b1;
            tile[(rl + 8) * 132 + cl_]     = ch[2] + b0;
            tile[(rl + 8) * 132 + cl_ + 1] = ch[3] + b1;
        }
    }
    __syncthreads();

    const int b = row0 >> 11;
    const int s0 = row0 & 2047;
    const int h = col0 >> 7;
    const int bh = b * 16 + h;

    if (z == 0) {
        // Q: A-frag pack (hi+lo), rope + scaling.
        #pragma unroll
        for (int u = 0; u < 8; u++) {
            int unit = tid + u * 256;
            int lane_u = unit & 31, ks = (unit >> 5) & 7, mt_l = unit >> 8;
            int lgu = lane_u >> 2, lcu = lane_u & 3;
            int r0l = mt_l * 16 + lgu;
            int p0 = pos[b * S_ + s0 + r0l];
            int p1 = pos[b * S_ + s0 + r0l + 8];
            int c0 = ks * 16 + 2 * lcu;
            int cols[4] = { c0, c0 + 1, c0 + 8, c0 + 9 };
            int i0[4] = { 0, 1, 4, 5 }, i1[4] = { 2, 3, 6, 7 };
            float vals[8];
            #pragma unroll
            for (int i = 0; i < 4; i++) {
                int d = cols[i];
                vals[i0[i]] = rope_val(tile[r0l * 132 + d],
                                       tile[r0l * 132 + (d ^ 64)], d, p0) * SCALING_;
                vals[i1[i]] = rope_val(tile[(r0l + 8) * 132 + d],
                                       tile[(r0l + 8) * 132 + (d ^ 64)], d, p1) * SCALING_;
            }
            __half out[16];
            #pragma unroll
            for (int i = 0; i < 8; i++) h_split_ns(vals[i], out[i], out[8 + i]);
            uint4* dst = reinterpret_cast<uint4*>(
                Qout + (((size_t)(bh * 128 + (s0 >> 4) + mt_l) * 8 + ks) * 32 + lane_u) * 16);
            dst[0] = *reinterpret_cast<uint4*>(&out[0]);
            dst[1] = *reinterpret_cast<uint4*>(&out[8]);
        }
    } else if (z == 1) {
        // K: B-frag pack (hi only), rope.
        #pragma unroll
        for (int u = 0; u < 16; u++) {
            int unit = tid + u * 256;
            int lane_u = unit & 31, ks = (unit >> 5) & 7, nt_l = unit >> 8;
            int lgu = lane_u >> 2, lcu = lane_u & 3;
            int tl = nt_l * 8 + lgu;
            int p = pos[b * S_ + s0 + tl];
            int c0 = ks * 16 + 2 * lcu;
            int cols[4] = { c0, c0 + 1, c0 + 8, c0 + 9 };
            __half out[4];
            #pragma unroll
            for (int i = 0; i < 4; i++) {
                int d = cols[i];
                out[i] = __float2half_rn(
                    rope_val(tile[tl * 132 + d], tile[tl * 132 + (d ^ 64)], d, p));
            }
            *reinterpret_cast<uint2*>(
                Kout + (((size_t)(bh * 256 + (s0 >> 3) + nt_l) * 8 + ks) * 32 + lane_u) * 4) =
                *reinterpret_cast<uint2*>(&out[0]);
        }
    } else {
        // V: B-frag pack (hi only) over tokens.
        #pragma unroll
        for (int u = 0; u < 16; u++) {
            int unit = tid + u * 256;
            int lane_u = unit & 31, ks_l = (unit >> 5) & 7, nt = unit >> 8;
            int lgu = lane_u >> 2, lcu = lane_u & 3;
            int n = nt * 8 + lgu;
            int k0 = ks_l * 16 + 2 * lcu;
            __half out[4];
            out[0] = __float2half_rn(tile[k0 * 132 + n]);
            out[1] = __float2half_rn(tile[(k0 + 1) * 132 + n]);
            out[2] = __float2half_rn(tile[(k0 + 8) * 132 + n]);
            out[3] = __float2half_rn(tile[(k0 + 9) * 132 + n]);
            *reinterpret_cast<uint2*>(
                Vout + (((size_t)(bh * 16 + nt) * 128 + (s0 >> 4) + ks_l) * 32 + lane_u) * 4) =
                *reinterpret_cast<uint2*>(&out[0]);
        }
    }
}

// Out-projection GEMM (1-pass, fp32 gmem epilogue)
__global__ void __launch_bounds__(256, 2)
gemm_tc_kernel(const __half* __restrict__ Apack, const __half* __restrict__ Bpack,
               float* __restrict__ C) {
    extern __shared__ __align__(16) char dsm[];
    const int row0 = blockIdx.y * 128;
    const int col0 = blockIdx.x * 128;
    float acc[4][4][4];
    gemm_mainloop(Apack, Bpack, dsm, row0, col0, acc);

    const int tid = threadIdx.x;
    const int lane = tid & 31;
    const int wid = tid >> 5;
    const int warp_m = wid & 1;
    const int warp_n = wid >> 1;
    const int lg = lane >> 2, lc = lane & 3;
    #pragma unroll
    for (int mt = 0; mt < 4; mt++) {
        int grow = row0 + (warp_m * 4 + mt) * 16 + lg;
        #pragma unroll
        for (int nt = 0; nt < 4; nt++) {
            int gcol = col0 + (warp_n * 4 + nt) * 8 + lc * 2;
            float* ch = acc[mt][nt];
            *reinterpret_cast<float2*>(C + (size_t)grow * HID_ + gcol) =
                make_float2(ch[0], ch[1]);
            *reinterpret_cast<float2*>(C + (size_t)(grow + 8) * HID_ + gcol) =
                make_float2(ch[2], ch[3]);
        }
    }
}

// ---------------------------------------------------------------------------
// Tensor-core causal flash attention. QK 2-pass (q hi+lo x k hi), PV 1-pass.
// smem: Q 64KB + 2 x (K 16KB + V 16KB) = 128KB.
// ---------------------------------------------------------------------------
constexpr uint32_t KV_STAGE = 32768;            // 16KB K + 16KB V
constexpr int AT2_SMEM = 65536 + 2 * 32768;     // 131072

__global__ void __launch_bounds__(256, 1)
attn_tc_kernel(const __half* __restrict__ Qp, const __half* __restrict__ Kp,
               const __half* __restrict__ Vp, __half* __restrict__ APout) {
    extern __shared__ __align__(16) char smem_raw[];
    const uint32_t sb = (uint32_t)__cvta_generic_to_shared(smem_raw);
    const int tid = threadIdx.x;
    const int lane = tid & 31;
    const int warp = tid >> 5;
    const int lg = lane >> 2, lc = lane & 3;
    const int qi = 15 - (int)(blockIdx.x >> 5);
    const int bh = blockIdx.x & 31;
    const int b = bh >> 4, h = bh & 15;
    const int q0 = qi * 128;
    const int ntiles = 2 * qi + 2;

    const __half* Qb = Qp + ((size_t)bh * 128 + (size_t)qi * 8) * 4096;
    const __half* Kb = Kp + (size_t)bh * 256 * 1024;
    const __half* Vb = Vp + (size_t)bh * 16 * 16384;   // hi-only

    #pragma unroll
    for (int i = 0; i < 16; i++) {
        int c = tid + i * 256;
        cp_async16(sb + (uint32_t)c * 16, Qb + (size_t)c * 8);
    }
    cp_commit();

    auto load_KV = [&](int t, int s) {
        uint32_t base = sb + 65536 + (uint32_t)s * KV_STAGE;
        const __half* Ksrc = Kb + (size_t)t * 8192;
        #pragma unroll
        for (int i = 0; i < 4; i++) {                    // K: 1024 chunks
            int c = tid + i * 256;
            cp_async16(base + (uint32_t)c * 16, Ksrc + (size_t)c * 8);
        }
        #pragma unroll
        for (int i = 0; i < 4; i++) {                    // V: 1024 chunks
            int c = tid + i * 256;
            int nt = c >> 6, inner = c & 63;
            cp_async16(base + 16384 + (uint32_t)c * 16,
                       Vb + (size_t)nt * 16384 + (size_t)t * 512 + inner * 8);
        }
        cp_commit();
    };
    load_KV(0, 0);
    load_KV(1, 1);

    float oacc[16][4];
    #pragma unroll
    for (int i = 0; i < 16; i++)
        #pragma unroll
        for (int r = 0; r < 4; r++) oacc[i][r] = 0.f;
    float m0 = -1e30f, m1 = -1e30f, l0 = 0.f, l1 = 0.f;

    const uint4* Qv = reinterpret_cast<const uint4*>(smem_raw);

    for (int t = 0; t < ntiles; t++) {
        if (t + 1 >= ntiles) cp_wait<0>(); else cp_wait<1>();
        __syncthreads();
        const int s = t & 1;
        const uint2* Kv = reinterpret_cast<const uint2*>(smem_raw + 65536 + (size_t)s * KV_STAGE);
        const uint2* Vv = reinterpret_cast<const uint2*>(smem_raw + 65536 + (size_t)s * KV_STAGE + 16384);

        // S = Q @ K^T (2-pass: q-hi*k-hi + q-lo*k-hi)
        float sacc[8][4];
        #pragma unroll
        for (int nt = 0; nt < 8; nt++)
            #pragma unroll
            for (int r = 0; r < 4; r++) sacc[nt][r] = 0.f;
        #pragma unroll
        for (int ks = 0; ks < 8; ks++) {
            int qbase = ((warp * 8 + ks) * 32 + lane) * 2;
            uint4 ahi = Qv[qbase];
            uint4 alo = Qv[qbase + 1];
            uint2 kf[8];
            #pragma unroll
            for (int nt = 0; nt < 8; nt++)
                kf[nt] = Kv[(nt * 8 + ks) * 32 + lane];
            #pragma unroll
            for (int nt = 0; nt < 8; nt++)
                mma_f16(sacc[nt], ahi, kf[nt].x, kf[nt].y);
            #pragma unroll
            for (int nt = 0; nt < 8; nt++)
                mma_f16(sacc[nt], alo, kf[nt].x, kf[nt].y);
        }

        if (t >= ntiles - 2) {
            int gr0 = q0 + warp * 16 + lg;
            int gr1 = gr0 + 8;
            #pragma unroll
            for (int nt = 0; nt < 8; nt++) {
                int gc = t * 64 + nt * 8 + 2 * lc;
                if (gc > gr0)     sacc[nt][0] = -1e30f;
                if (gc + 1 > gr0) sacc[nt][1] = -1e30f;
                if (gc > gr1)     sacc[nt][2] = -1e30f;
                if (gc + 1 > gr1) sacc[nt][3] = -1e30f;
            }
        }

        // Online softmax
        float mx0 = -1e30f, mx1 = -1e30f;
        #pragma unroll
        for (int nt = 0; nt < 8; nt++) {
            mx0 = fmaxf(mx0, fmaxf(sacc[nt][0], sacc[nt][1]));
            mx1 = fmaxf(mx1, fmaxf(sacc[nt][2], sacc[nt][3]));
        }
        mx0 = fmaxf(mx0, __shfl_xor_sync(0xFFFFFFFFu, mx0, 1));
        mx0 = fmaxf(mx0, __shfl_xor_sync(0xFFFFFFFFu, mx0, 2));
        mx1 = fmaxf(mx1, __shfl_xor_sync(0xFFFFFFFFu, mx1, 1));
        mx1 = fmaxf(mx1, __shfl_xor_sync(0xFFFFFFFFu, mx1, 2));
        float mn0 = fmaxf(m0, mx0), mn1 = fmaxf(m1, mx1);
        float c0 = __expf(m0 - mn0), c1 = __expf(m1 - mn1);
        m0 = mn0; m1 = mn1;
        float sum0 = 0.f, sum1 = 0.f;
        #pragma unroll
        for (int nt = 0; nt < 8; nt++) {
            sacc[nt][0] = __expf(sacc[nt][0] - mn0); sum0 += sacc[nt][0];
            sacc[nt][1] = __expf(sacc[nt][1] - mn0); sum0 += sacc[nt][1];
            sacc[nt][2] = __expf(sacc[nt][2] - mn1); sum1 += sacc[nt][2];
            sacc[nt][3] = __expf(sacc[nt][3] - mn1); sum1 += sacc[nt][3];
        }
        sum0 += __shfl_xor_sync(0xFFFFFFFFu, sum0, 1);
        sum0 += __shfl_xor_sync(0xFFFFFFFFu, sum0, 2);
        sum1 += __shfl_xor_sync(0xFFFFFFFFu, sum1, 1);
        sum1 += __shfl_xor_sync(0xFFFFFFFFu, sum1, 2);
        l0 = l0 * c0 + sum0;
        l1 = l1 * c1 + sum1;
        #pragma unroll
        for (int nt = 0; nt < 16; nt++) {
            oacc[nt][0] *= c0; oacc[nt][1] *= c0;
            oacc[nt][2] *= c1; oacc[nt][3] *= c1;
        }

        // O += P @ V (1-pass: P-hi x V-hi)
        #pragma unroll
        for (int j = 0; j < 4; j++) {
            const float* pa = sacc[2 * j];
            const float* pb = sacc[2 * j + 1];
            __half2 h01 = __floats2half2_rn(pa[0], pa[1]);
            __half2 h23 = __floats2half2_rn(pa[2], pa[3]);
            __half2 h45 = __floats2half2_rn(pb[0], pb[1]);
            __half2 h67 = __floats2half2_rn(pb[2], pb[3]);
            uint4 phi = make_uint4(h2u(h01), h2u(h23), h2u(h45), h2u(h67));
            #pragma unroll
            for (int blk = 0; blk < 2; blk++) {
                uint2 vf[8];
                #pragma unroll
                for (int i = 0; i < 8; i++)
                    vf[i] = Vv[((blk * 8 + i) * 4 + j) * 32 + lane];
                #pragma unroll
                for (int i = 0; i < 8; i++)
                    mma_f16(oacc[blk * 8 + i], phi, vf[i].x, vf[i].y);
            }
        }

        __syncthreads();
        if (t + 2 < ntiles) load_KV(t + 2, s);
    }

    // Epilogue: normalize + write out-proj A-frag pack (hi-only)
    float inv0 = 1.f / l0, inv1 = 1.f / l1;
    const int mtg = b * 128 + qi * 8 + warp;
    #pragma unroll
    for (int j = 0; j < 8; j++) {
        const int ksg = h * 8 + j;
        __half out[8];
        out[0] = __float2half_rn(oacc[2 * j][0] * inv0);
        out[1] = __float2half_rn(oacc[2 * j][1] * inv0);
        out[2] = __float2half_rn(oacc[2 * j][2] * inv1);
        out[3] = __float2half_rn(oacc[2 * j][3] * inv1);
        out[4] = __float2half_rn(oacc[2 * j + 1][0] * inv0);
        out[5] = __float2half_rn(oacc[2 * j + 1][1] * inv0);
        out[6] = __float2half_rn(oacc[2 * j + 1][2] * inv1);
        out[7] = __float2half_rn(oacc[2 * j + 1][3] * inv1);
        *reinterpret_cast<uint4*>(
            APout + (((size_t)mtg * KS16_ + ksg) * 32 + lane) * 8) =
            *reinterpret_cast<uint4*>(&out[0]);
    }
}

// ---------------------------------------------------------------------------
// Launch
// ---------------------------------------------------------------------------
extern "C" void kernel_launch(void* const* d_in, const int* in_sizes, int n_in,
                              void* d_out, int out_size) {
    const float* hs  = (const float*)d_in[0];
    const int*   pos = (const int*)  d_in[1];
    const float* wq  = (const float*)d_in[2];
    const float* bq  = (const float*)d_in[3];
    const float* wk  = (const float*)d_in[4];
    const float* bk  = (const float*)d_in[5];
    const float* wv  = (const float*)d_in[6];
    const float* bv  = (const float*)d_in[7];
    const float* wc  = (const float*)d_in[8];
    float* out = (float*)d_out;

    __half *apack, *bpack, *qpk, *kpk, *vpk;
    cudaGetSymbolAddress((void**)&apack, g_apack);
    cudaGetSymbolAddress((void**)&bpack, g_bpack);
    cudaGetSymbolAddress((void**)&qpk, g_qpack);
    cudaGetSymbolAddress((void**)&kpk, g_kpack);
    cudaGetSymbolAddress((void**)&vpk, g_vpack);

    const size_t BPSZ = (size_t)HID_ * HID_;

    cudaFuncSetAttribute(gemm_qkv_fused,
                         cudaFuncAttributeMaxDynamicSharedMemorySize, GEMM_DSMEM);
    cudaFuncSetAttribute(gemm_tc_kernel,
                         cudaFuncAttributeMaxDynamicSharedMemorySize, GEMM_DSMEM);
    cudaFuncSetAttribute(attn_tc_kernel,
                         cudaFuncAttributeMaxDynamicSharedMemorySize, AT2_SMEM);

    // Weight + activation packs (hi-only)
    dim3 pbgrid((HID_ / 8) * KS16_ * 32 / 256, 4);   // (4096, 4)
    pack_b4_kernel<<<pbgrid, 256>>>(wq, wk, wv, wc, bpack);
    const int pa_blocks = (M_ / 16) * KS16_ * 32 / 256;    // 4096
    pack_a_kernel<<<pa_blocks, 256>>>(hs, apack);

    // Fused QKV projections + rope + attention packing (1-pass GEMM)
    dim3 qkv_grid(HID_ / 128, M_ / 128, 3);   // (16, 32, 3)
    gemm_qkv_fused<<<qkv_grid, 256, GEMM_DSMEM>>>(apack, bpack, bq, bk, bv, pos,
                                                  qpk, kpk, vpk);

    // Tensor-core attention (writes out-proj A-pack directly)
    attn_tc_kernel<<<512, 256, AT2_SMEM>>>(qpk, kpk, vpk, apack);

    // Output projection (1-pass)
    dim3 ggrid(HID_ / 128, M_ / 128);   // (16, 32)
    gemm_tc_kernel<<<ggrid, 256, GEMM_DSMEM>>>(apack, bpack + 3 * BPSZ, out);
}

// round 12
// speedup vs baseline: 10.1716x; 1.0550x over previous
#include <cuda_runtime.h>
#include <cuda_fp16.h>
#include <cstdint>

// Problem constants
constexpr int B_  = 2;
constexpr int S_  = 2048;
constexpr int HID_ = 2048;
constexpr int NH_ = 16;
constexpr int HD_ = 128;
constexpr float SCALING_ = 0.08838834764831845f; // 128^-0.5
constexpr int M_ = B_ * S_;      // 4096
constexpr int KS16_ = HID_ / 16; // 128 k16-steps across K

// Scratch (allocation-free rule: __device__ globals) — all packs hi-only fp16
__device__ __half g_apack[(size_t)M_ * HID_];
__device__ __half g_bpack[(size_t)4 * HID_ * HID_];
__device__ __half g_qpack[(size_t)32 * 128 * 8 * 32 * 8];   // Q: hi only
__device__ __half g_kpack[(size_t)32 * 256 * 8 * 32 * 4];   // K: hi only
__device__ __half g_vpack[(size_t)32 * 16 * 128 * 32 * 4];  // V: hi only

// ---------------------------------------------------------------------------
// PTX helpers
// ---------------------------------------------------------------------------
__device__ __forceinline__ void cp_async16(uint32_t s, const void* g) {
    asm volatile("cp.async.cg.shared.global [%0], [%1], 16;" :: "r"(s), "l"(g));
}
__device__ __forceinline__ void cp_commit() {
    asm volatile("cp.async.commit_group;");
}
template <int N>
__device__ __forceinline__ void cp_wait() {
    asm volatile("cp.async.wait_group %0;" :: "n"(N));
}
__device__ __forceinline__ void mma_f16(float* c, uint4 a, uint32_t b0, uint32_t b1) {
    asm volatile(
        "mma.sync.aligned.m16n8k16.row.col.f32.f16.f16.f32 "
        "{%0,%1,%2,%3}, {%4,%5,%6,%7}, {%8,%9}, {%0,%1,%2,%3};"
        : "+f"(c[0]), "+f"(c[1]), "+f"(c[2]), "+f"(c[3])
        : "r"(a.x), "r"(a.y), "r"(a.z), "r"(a.w), "r"(b0), "r"(b1));
}
__device__ __forceinline__ uint32_t h2u(__half2 v) {
    return *reinterpret_cast<uint32_t*>(&v);
}
__device__ __forceinline__ float rope_val(float x, float y, int d, int p) {
    int dj = d & 63;
    float inv_freq = exp2f((float)dj * -0.2076205f);
    float f = (float)p * inv_freq;
    float sn, cs;
    sincosf(f, &sn, &cs);
    return (d < 64) ? (x * cs - y * sn) : (x * cs + y * sn);
}

// ---------------------------------------------------------------------------
// Pack kernels (hi-only)
// ---------------------------------------------------------------------------
__global__ void pack_a_kernel(const float* __restrict__ A, __half* __restrict__ P) {
    int idx = blockIdx.x * blockDim.x + threadIdx.x;
    int lane = idx & 31;
    int t = idx >> 5;
    int ks = t & (KS16_ - 1);
    int mt = t >> 7;
    int lg = lane >> 2, lc = lane & 3;
    int row = mt * 16 + lg;
    int col = ks * 16 + lc * 2;
    const float* r0 = A + (size_t)row * HID_ + col;
    const float* r1 = A + (size_t)(row + 8) * HID_ + col;
    __half out[8];
    out[0] = __float2half_rn(r0[0]);
    out[1] = __float2half_rn(r0[1]);
    out[2] = __float2half_rn(r1[0]);
    out[3] = __float2half_rn(r1[1]);
    out[4] = __float2half_rn(r0[8]);
    out[5] = __float2half_rn(r0[9]);
    out[6] = __float2half_rn(r1[8]);
    out[7] = __float2half_rn(r1[9]);
    *reinterpret_cast<uint4*>(P + (size_t)idx * 8) = *reinterpret_cast<uint4*>(&out[0]);
}

__global__ void pack_b4_kernel(const float* __restrict__ w0, const float* __restrict__ w1,
                               const float* __restrict__ w2, const float* __restrict__ w3,
                               __half* __restrict__ P) {
    const int z = blockIdx.y;
    const float* W = (z == 0) ? w0 : (z == 1) ? w1 : (z == 2) ? w2 : w3;
    __half* Pz = P + (size_t)z * HID_ * HID_;
    int idx = blockIdx.x * blockDim.x + threadIdx.x;
    int lane = idx & 31;
    int t = idx >> 5;
    int ks = t & (KS16_ - 1);
    int nt = t >> 7;
    int lg = lane >> 2, lc = lane & 3;
    int n = nt * 8 + lg;
    int k = ks * 16 + lc * 2;
    __half out[4];
    out[0] = __float2half_rn(W[(size_t)k * HID_ + n]);
    out[1] = __float2half_rn(W[(size_t)(k + 1) * HID_ + n]);
    out[2] = __float2half_rn(W[(size_t)(k + 8) * HID_ + n]);
    out[3] = __float2half_rn(W[(size_t)(k + 9) * HID_ + n]);
    *reinterpret_cast<uint2*>(Pz + (size_t)idx * 4) = *reinterpret_cast<uint2*>(&out[0]);
}

// ---------------------------------------------------------------------------
// fp16 1-pass GEMM mainloop, BK=64. Stage = A 16KB + B 16KB = 32KB; 3 stages.
// ---------------------------------------------------------------------------
constexpr int NT64 = HID_ / 64;           // 32 iterations
constexpr uint32_t STAGE_B = 32768;
constexpr int GEMM_DSMEM = 3 * STAGE_B;   // 98304

__device__ __forceinline__ void gemm_mainloop(
    const __half* __restrict__ Apack, const __half* __restrict__ Bpack,
    char* dsm, int row0, int col0, float acc[4][4][4])
{
    const uint32_t sb = (uint32_t)__cvta_generic_to_shared(dsm);
    const int tid = threadIdx.x;
    const int lane = tid & 31;
    const int wid = tid >> 5;
    const int warp_m = wid & 1;
    const int warp_n = wid >> 1;

    const __half* Ab = Apack + (size_t)(row0 >> 4) * (KS16_ * 32 * 8);
    const __half* Bb = Bpack + (size_t)(col0 >> 3) * (KS16_ * 32 * 4);

    auto load_stage = [&](int kt64, int s) {
        uint32_t sa = sb + (uint32_t)s * STAGE_B;
        uint32_t sbm = sa + 16384;
        const __half* Abase = Ab + (size_t)kt64 * 1024;
        const __half* Bbase = Bb + (size_t)kt64 * 512;
        #pragma unroll
        for (int i = 0; i < 4; i++) {          // A: 1024 x 16B chunks
            int c = tid + i * 256;
            int mt = c >> 7, inner = c & 127;
            cp_async16(sa + (uint32_t)c * 16, Abase + (size_t)mt * 32768 + inner * 8);
        }
        #pragma unroll
        for (int i = 0; i < 4; i++) {          // B: 1024 x 16B chunks
            int c = tid + i * 256;
            int nt = c >> 6, inner = c & 63;
            cp_async16(sbm + (uint32_t)c * 16, Bbase + (size_t)nt * 16384 + inner * 8);
        }
        cp_commit();
    };

    #pragma unroll
    for (int i = 0; i < 4; i++)
        #pragma unroll
        for (int j = 0; j < 4; j++)
            #pragma unroll
            for (int r = 0; r < 4; r++) acc[i][j][r] = 0.f;

    load_stage(0, 0);
    load_stage(1, 1);
    load_stage(2, 2);

    for (int kt = 0; kt < NT64; kt++) {
        const int s = kt % 3;
        if (kt + 2 >= NT64) cp_wait<0>(); else cp_wait<2>();
        __syncthreads();

        const uint4* sa_v = reinterpret_cast<const uint4*>(dsm + (size_t)s * STAGE_B);
        const uint2* sb_v = reinterpret_cast<const uint2*>(dsm + (size_t)s * STAGE_B + 16384);

        #pragma unroll
        for (int ks = 0; ks < 4; ks++) {
            uint4 ah[4];
            uint2 bf[4];
            #pragma unroll
            for (int mt = 0; mt < 4; mt++)
                ah[mt] = sa_v[(((warp_m * 4 + mt) * 4 + ks) * 32 + lane)];
            #pragma unroll
            for (int nt = 0; nt < 4; nt++)
                bf[nt] = sb_v[((warp_n * 4 + nt) * 4 + ks) * 32 + lane];
            #pragma unroll
            for (int mt = 0; mt < 4; mt++)
                #pragma unroll
                for (int nt = 0; nt < 4; nt++)
                    mma_f16(acc[mt][nt], ah[mt], bf[nt].x, bf[nt].y);
        }
        __syncthreads();
        if (kt + 3 < NT64) load_stage(kt + 3, s);
    }
}

// ---------------------------------------------------------------------------
// Fused QKV GEMM + bias + RoPE + attention-fragment packing (all hi-only).
// ---------------------------------------------------------------------------
__global__ void __launch_bounds__(256, 2)
gemm_qkv_fused(const __half* __restrict__ Apack, const __half* __restrict__ Bpack,
               const float* __restrict__ bq, const float* __restrict__ bk,
               const float* __restrict__ bv, const int* __restrict__ pos,
               __half* __restrict__ Qout, __half* __restrict__ Kout,
               __half* __restrict__ Vout) {
    extern __shared__ __align__(16) char dsm[];
    const int z = blockIdx.z;
    const size_t BPSZ = (size_t)HID_ * HID_;
    const int row0 = blockIdx.y * 128;
    const int col0 = blockIdx.x * 128;

    float acc[4][4][4];
    gemm_mainloop(Apack, Bpack + (size_t)z * BPSZ, dsm, row0, col0, acc);

    // Epilogue stage 1: acc + bias -> fp32 smem tile [128][132]
    const int tid = threadIdx.x;
    const int lane = tid & 31;
    const int wid = tid >> 5;
    const int warp_m = wid & 1;
    const int warp_n = wid >> 1;
    const int lg = lane >> 2, lc = lane & 3;
    const float* bias = (z == 0) ? bq : (z == 1) ? bk : bv;
    float* tile = reinterpret_cast<float*>(dsm);

    #pragma unroll
    for (int mt = 0; mt < 4; mt++) {
        int rl = warp_m * 64 + mt * 16 + lg;
        #pragma unroll
        for (int nt = 0; nt < 4; nt++) {
            int cl_ = warp_n * 32 + nt * 8 + lc * 2;
            float b0 = bias[col0 + cl_], b1 = bias[col0 + cl_ + 1];
            float* ch = acc[mt][nt];
            tile[rl * 132 + cl_]           = ch[0] + b0;
            tile[rl * 132 + cl_ + 1]       = ch[1] + b1;
            tile[(rl + 8) * 132 + cl_]     = ch[2] + b0;
            tile[(rl + 8) * 132 + cl_ + 1] = ch[3] + b1;
        }
    }
    __syncthreads();

    const int b = row0 >> 11;
    const int s0 = row0 & 2047;
    const int h = col0 >> 7;
    const int bh = b * 16 + h;

    if (z == 0) {
        // Q: A-frag pack (hi only), rope + scaling. 2048 units of 8 halfs.
        #pragma unroll
        for (int u = 0; u < 8; u++) {
            int unit = tid + u * 256;
            int lane_u = unit & 31, ks = (unit >> 5) & 7, mt_l = unit >> 8;
            int lgu = lane_u >> 2, lcu = lane_u & 3;
            int r0l = mt_l * 16 + lgu;
            int p0 = pos[b * S_ + s0 + r0l];
            int p1 = pos[b * S_ + s0 + r0l + 8];
            int c0 = ks * 16 + 2 * lcu;
            int cols[4] = { c0, c0 + 1, c0 + 8, c0 + 9 };
            int i0[4] = { 0, 1, 4, 5 }, i1[4] = { 2, 3, 6, 7 };
            __half out[8];
            #pragma unroll
            for (int i = 0; i < 4; i++) {
                int d = cols[i];
                out[i0[i]] = __float2half_rn(
                    rope_val(tile[r0l * 132 + d], tile[r0l * 132 + (d ^ 64)], d, p0) * SCALING_);
                out[i1[i]] = __float2half_rn(
                    rope_val(tile[(r0l + 8) * 132 + d], tile[(r0l + 8) * 132 + (d ^ 64)], d, p1) * SCALING_);
            }
            *reinterpret_cast<uint4*>(
                Qout + (((size_t)(bh * 128 + (s0 >> 4) + mt_l) * 8 + ks) * 32 + lane_u) * 8) =
                *reinterpret_cast<uint4*>(&out[0]);
        }
    } else if (z == 1) {
        // K: B-frag pack (hi only), rope.
        #pragma unroll
        for (int u = 0; u < 16; u++) {
            int unit = tid + u * 256;
            int lane_u = unit & 31, ks = (unit >> 5) & 7, nt_l = unit >> 8;
            int lgu = lane_u >> 2, lcu = lane_u & 3;
            int tl = nt_l * 8 + lgu;
            int p = pos[b * S_ + s0 + tl];
            int c0 = ks * 16 + 2 * lcu;
            int cols[4] = { c0, c0 + 1, c0 + 8, c0 + 9 };
            __half out[4];
            #pragma unroll
            for (int i = 0; i < 4; i++) {
                int d = cols[i];
                out[i] = __float2half_rn(
                    rope_val(tile[tl * 132 + d], tile[tl * 132 + (d ^ 64)], d, p));
            }
            *reinterpret_cast<uint2*>(
                Kout + (((size_t)(bh * 256 + (s0 >> 3) + nt_l) * 8 + ks) * 32 + lane_u) * 4) =
                *reinterpret_cast<uint2*>(&out[0]);
        }
    } else {
        // V: B-frag pack (hi only) over tokens.
        #pragma unroll
        for (int u = 0; u < 16; u++) {
            int unit = tid + u * 256;
            int lane_u = unit & 31, ks_l = (unit >> 5) & 7, nt = unit >> 8;
            int lgu = lane_u >> 2, lcu = lane_u & 3;
            int n = nt * 8 + lgu;
            int k0 = ks_l * 16 + 2 * lcu;
            __half out[4];
            out[0] = __float2half_rn(tile[k0 * 132 + n]);
            out[1] = __float2half_rn(tile[(k0 + 1) * 132 + n]);
            out[2] = __float2half_rn(tile[(k0 + 8) * 132 + n]);
            out[3] = __float2half_rn(tile[(k0 + 9) * 132 + n]);
            *reinterpret_cast<uint2*>(
                Vout + (((size_t)(bh * 16 + nt) * 128 + (s0 >> 4) + ks_l) * 32 + lane_u) * 4) =
                *reinterpret_cast<uint2*>(&out[0]);
        }
    }
}

// Out-projection GEMM (1-pass, fp32 gmem epilogue)
__global__ void __launch_bounds__(256, 2)
gemm_tc_kernel(const __half* __restrict__ Apack, const __half* __restrict__ Bpack,
               float* __restrict__ C) {
    extern __shared__ __align__(16) char dsm[];
    const int row0 = blockIdx.y * 128;
    const int col0 = blockIdx.x * 128;
    float acc[4][4][4];
    gemm_mainloop(Apack, Bpack, dsm, row0, col0, acc);

    const int tid = threadIdx.x;
    const int lane = tid & 31;
    const int wid = tid >> 5;
    const int warp_m = wid & 1;
    const int warp_n = wid >> 1;
    const int lg = lane >> 2, lc = lane & 3;
    #pragma unroll
    for (int mt = 0; mt < 4; mt++) {
        int grow = row0 + (warp_m * 4 + mt) * 16 + lg;
        #pragma unroll
        for (int nt = 0; nt < 4; nt++) {
            int gcol = col0 + (warp_n * 4 + nt) * 8 + lc * 2;
            float* ch = acc[mt][nt];
            *reinterpret_cast<float2*>(C + (size_t)grow * HID_ + gcol) =
                make_float2(ch[0], ch[1]);
            *reinterpret_cast<float2*>(C + (size_t)(grow + 8) * HID_ + gcol) =
                make_float2(ch[2], ch[3]);
        }
    }
}

// ---------------------------------------------------------------------------
// Tensor-core causal flash attention. QK 1-pass, PV 1-pass.
// smem: Q 32KB + 2 x (K 16KB + V 16KB) = 96KB.
// ---------------------------------------------------------------------------
constexpr uint32_t KV_STAGE = 32768;            // 16KB K + 16KB V
constexpr int AT2_SMEM = 32768 + 2 * 32768;     // 98304

__global__ void __launch_bounds__(256, 1)
attn_tc_kernel(const __half* __restrict__ Qp, const __half* __restrict__ Kp,
               const __half* __restrict__ Vp, __half* __restrict__ APout) {
    extern __shared__ __align__(16) char smem_raw[];
    const uint32_t sb = (uint32_t)__cvta_generic_to_shared(smem_raw);
    const int tid = threadIdx.x;
    const int lane = tid & 31;
    const int warp = tid >> 5;
    const int lg = lane >> 2, lc = lane & 3;
    const int qi = 15 - (int)(blockIdx.x >> 5);
    const int bh = blockIdx.x & 31;
    const int b = bh >> 4, h = bh & 15;
    const int q0 = qi * 128;
    const int ntiles = 2 * qi + 2;

    const __half* Qb = Qp + ((size_t)bh * 128 + (size_t)qi * 8) * 2048;  // hi-only
    const __half* Kb = Kp + (size_t)bh * 256 * 1024;
    const __half* Vb = Vp + (size_t)bh * 16 * 16384;

    // Q tile: 16384 halfs = 2048 x 16B chunks
    #pragma unroll
    for (int i = 0; i < 8; i++) {
        int c = tid + i * 256;
        cp_async16(sb + (uint32_t)c * 16, Qb + (size_t)c * 8);
    }
    cp_commit();

    auto load_KV = [&](int t, int s) {
        uint32_t base = sb + 32768 + (uint32_t)s * KV_STAGE;
        const __half* Ksrc = Kb + (size_t)t * 8192;
        #pragma unroll
        for (int i = 0; i < 4; i++) {
            int c = tid + i * 256;
            cp_async16(base + (uint32_t)c * 16, Ksrc + (size_t)c * 8);
        }
        #pragma unroll
        for (int i = 0; i < 4; i++) {
            int c = tid + i * 256;
            int nt = c >> 6, inner = c & 63;
            cp_async16(base + 16384 + (uint32_t)c * 16,
                       Vb + (size_t)nt * 16384 + (size_t)t * 512 + inner * 8);
        }
        cp_commit();
    };
    load_KV(0, 0);
    load_KV(1, 1);

    float oacc[16][4];
    #pragma unroll
    for (int i = 0; i < 16; i++)
        #pragma unroll
        for (int r = 0; r < 4; r++) oacc[i][r] = 0.f;
    float m0 = -1e30f, m1 = -1e30f, l0 = 0.f, l1 = 0.f;

    const uint4* Qv = reinterpret_cast<const uint4*>(smem_raw);

    for (int t = 0; t < ntiles; t++) {
        if (t + 1 >= ntiles) cp_wait<0>(); else cp_wait<1>();
        __syncthreads();
        const int s = t & 1;
        const uint2* Kv = reinterpret_cast<const uint2*>(smem_raw + 32768 + (size_t)s * KV_STAGE);
        const uint2* Vv = reinterpret_cast<const uint2*>(smem_raw + 32768 + (size_t)s * KV_STAGE + 16384);

        // S = Q @ K^T (1-pass: q-hi x k-hi)
        float sacc[8][4];
        #pragma unroll
        for (int nt = 0; nt < 8; nt++)
            #pragma unroll
            for (int r = 0; r < 4; r++) sacc[nt][r] = 0.f;
        #pragma unroll
        for (int ks = 0; ks < 8; ks++) {
            uint4 ahi = Qv[(warp * 8 + ks) * 32 + lane];
            uint2 kf[8];
            #pragma unroll
            for (int nt = 0; nt < 8; nt++)
                kf[nt] = Kv[(nt * 8 + ks) * 32 + lane];
            #pragma unroll
            for (int nt = 0; nt < 8; nt++)
                mma_f16(sacc[nt], ahi, kf[nt].x, kf[nt].y);
        }

        if (t >= ntiles - 2) {
            int gr0 = q0 + warp * 16 + lg;
            int gr1 = gr0 + 8;
            #pragma unroll
            for (int nt = 0; nt < 8; nt++) {
                int gc = t * 64 + nt * 8 + 2 * lc;
                if (gc > gr0)     sacc[nt][0] = -1e30f;
                if (gc + 1 > gr0) sacc[nt][1] = -1e30f;
                if (gc > gr1)     sacc[nt][2] = -1e30f;
                if (gc + 1 > gr1) sacc[nt][3] = -1e30f;
            }
        }

        // Online softmax
        float mx0 = -1e30f, mx1 = -1e30f;
        #pragma unroll
        for (int nt = 0; nt < 8; nt++) {
            mx0 = fmaxf(mx0, fmaxf(sacc[nt][0], sacc[nt][1]));
            mx1 = fmaxf(mx1, fmaxf(sacc[nt][2], sacc[nt][3]));
        }
        mx0 = fmaxf(mx0, __shfl_xor_sync(0xFFFFFFFFu, mx0, 1));
        mx0 = fmaxf(mx0, __shfl_xor_sync(0xFFFFFFFFu, mx0, 2));
        mx1 = fmaxf(mx1, __shfl_xor_sync(0xFFFFFFFFu, mx1, 1));
        mx1 = fmaxf(mx1, __shfl_xor_sync(0xFFFFFFFFu, mx1, 2));
        float mn0 = fmaxf(m0, mx0), mn1 = fmaxf(m1, mx1);
        float c0 = __expf(m0 - mn0), c1 = __expf(m1 - mn1);
        m0 = mn0; m1 = mn1;
        float sum0 = 0.f, sum1 = 0.f;
        #pragma unroll
        for (int nt = 0; nt < 8; nt++) {
            sacc[nt][0] = __expf(sacc[nt][0] - mn0); sum0 += sacc[nt][0];
            sacc[nt][1] = __expf(sacc[nt][1] - mn0); sum0 += sacc[nt][1];
            sacc[nt][2] = __expf(sacc[nt][2] - mn1); sum1 += sacc[nt][2];
            sacc[nt][3] = __expf(sacc[nt][3] - mn1); sum1 += sacc[nt][3];
        }
        sum0 += __shfl_xor_sync(0xFFFFFFFFu, sum0, 1);
        sum0 += __shfl_xor_sync(0xFFFFFFFFu, sum0, 2);
        sum1 += __shfl_xor_sync(0xFFFFFFFFu, sum1, 1);
        sum1 += __shfl_xor_sync(0xFFFFFFFFu, sum1, 2);
        l0 = l0 * c0 + sum0;
        l1 = l1 * c1 + sum1;
        #pragma unroll
        for (int nt = 0; nt < 16; nt++) {
            oacc[nt][0] *= c0; oacc[nt][1] *= c0;
            oacc[nt][2] *= c1; oacc[nt][3] *= c1;
        }

        // O += P @ V (1-pass)
        #pragma unroll
        for (int j = 0; j < 4; j++) {
            const float* pa = sacc[2 * j];
            const float* pb = sacc[2 * j + 1];
            __half2 h01 = __floats2half2_rn(pa[0], pa[1]);
            __half2 h23 = __floats2half2_rn(pa[2], pa[3]);
            __half2 h45 = __floats2half2_rn(pb[0], pb[1]);
            __half2 h67 = __floats2half2_rn(pb[2], pb[3]);
            uint4 phi = make_uint4(h2u(h01), h2u(h23), h2u(h45), h2u(h67));
            #pragma unroll
            for (int blk = 0; blk < 2; blk++) {
                uint2 vf[8];
                #pragma unroll
                for (int i = 0; i < 8; i++)
                    vf[i] = Vv[((blk * 8 + i) * 4 + j) * 32 + lane];
                #pragma unroll
                for (int i = 0; i < 8; i++)
                    mma_f16(oacc[blk * 8 + i], phi, vf[i].x, vf[i].y);
            }
        }

        __syncthreads();
        if (t + 2 < ntiles) load_KV(t + 2, s);
    }

    // Epilogue: normalize + write out-proj A-frag pack (hi-only)
    float inv0 = 1.f / l0, inv1 = 1.f / l1;
    const int mtg = b * 128 + qi * 8 + warp;
    #pragma unroll
    for (int j = 0; j < 8; j++) {
        const int ksg = h * 8 + j;
        __half out[8];
        out[0] = __float2half_rn(oacc[2 * j][0] * inv0);
        out[1] = __float2half_rn(oacc[2 * j][1] * inv0);
        out[2] = __float2half_rn(oacc[2 * j][2] * inv1);
        out[3] = __float2half_rn(oacc[2 * j][3] * inv1);
        out[4] = __float2half_rn(oacc[2 * j + 1][0] * inv0);
        out[5] = __float2half_rn(oacc[2 * j + 1][1] * inv0);
        out[6] = __float2half_rn(oacc[2 * j + 1][2] * inv1);
        out[7] = __float2half_rn(oacc[2 * j + 1][3] * inv1);
        *reinterpret_cast<uint4*>(
            APout + (((size_t)mtg * KS16_ + ksg) * 32 + lane) * 8) =
            *reinterpret_cast<uint4*>(&out[0]);
    }
}

// ---------------------------------------------------------------------------
// Launch
// ---------------------------------------------------------------------------
extern "C" void kernel_launch(void* const* d_in, const int* in_sizes, int n_in,
                              void* d_out, int out_size) {
    const float* hs  = (const float*)d_in[0];
    const int*   pos = (const int*)  d_in[1];
    const float* wq  = (const float*)d_in[2];
    const float* bq  = (const float*)d_in[3];
    const float* wk  = (const float*)d_in[4];
    const float* bk  = (const float*)d_in[5];
    const float* wv  = (const float*)d_in[6];
    const float* bv  = (const float*)d_in[7];
    const float* wc  = (const float*)d_in[8];
    float* out = (float*)d_out;

    __half *apack, *bpack, *qpk, *kpk, *vpk;
    cudaGetSymbolAddress((void**)&apack, g_apack);
    cudaGetSymbolAddress((void**)&bpack, g_bpack);
    cudaGetSymbolAddress((void**)&qpk, g_qpack);
    cudaGetSymbolAddress((void**)&kpk, g_kpack);
    cudaGetSymbolAddress((void**)&vpk, g_vpack);

    const size_t BPSZ = (size_t)HID_ * HID_;

    cudaFuncSetAttribute(gemm_qkv_fused,
                         cudaFuncAttributeMaxDynamicSharedMemorySize, GEMM_DSMEM);
    cudaFuncSetAttribute(gemm_tc_kernel,
                         cudaFuncAttributeMaxDynamicSharedMemorySize, GEMM_DSMEM);
    cudaFuncSetAttribute(attn_tc_kernel,
                         cudaFuncAttributeMaxDynamicSharedMemorySize, AT2_SMEM);

    // Weight + activation packs (hi-only)
    dim3 pbgrid((HID_ / 8) * KS16_ * 32 / 256, 4);   // (4096, 4)
    pack_b4_kernel<<<pbgrid, 256>>>(wq, wk, wv, wc, bpack);
    const int pa_blocks = (M_ / 16) * KS16_ * 32 / 256;    // 4096
    pack_a_kernel<<<pa_blocks, 256>>>(hs, apack);

    // Fused QKV projections + rope + attention packing (1-pass GEMM)
    dim3 qkv_grid(HID_ / 128, M_ / 128, 3);   // (16, 32, 3)
    gemm_qkv_fused<<<qkv_grid, 256, GEMM_DSMEM>>>(apack, bpack, bq, bk, bv, pos,
                                                  qpk, kpk, vpk);

    // Tensor-core attention (writes out-proj A-pack directly)
    attn_tc_kernel<<<512, 256, AT2_SMEM>>>(qpk, kpk, vpk, apack);

    // Output projection (1-pass)
    dim3 ggrid(HID_ / 128, M_ / 128);   // (16, 32)
    gemm_tc_kernel<<<ggrid, 256, GEMM_DSMEM>>>(apack, bpack + 3 * BPSZ, out);
}

// round 13
// speedup vs baseline: 10.3223x; 1.0148x over previous
#include <cuda_runtime.h>
#include <cuda_fp16.h>
#include <cstdint>

// Problem constants
constexpr int B_  = 2;
constexpr int S_  = 2048;
constexpr int HID_ = 2048;
constexpr int NH_ = 16;
constexpr int HD_ = 128;
constexpr float SCALING_ = 0.08838834764831845f; // 128^-0.5
constexpr int M_ = B_ * S_;      // 4096
constexpr int KS16_ = HID_ / 16; // 128 k16-steps across K

// Scratch (allocation-free rule: __device__ globals) — all packs hi-only fp16
__device__ __half g_apack[(size_t)M_ * HID_];
__device__ __half g_bpack[(size_t)4 * HID_ * HID_];
__device__ __half g_qpack[(size_t)32 * 128 * 8 * 32 * 8];   // Q: hi only
__device__ __half g_kpack[(size_t)32 * 256 * 8 * 32 * 4];   // K: hi only
__device__ __half g_vpack[(size_t)32 * 16 * 128 * 32 * 4];  // V: hi only

// ---------------------------------------------------------------------------
// PTX helpers
// ---------------------------------------------------------------------------
__device__ __forceinline__ void cp_async16(uint32_t s, const void* g) {
    asm volatile("cp.async.cg.shared.global [%0], [%1], 16;" :: "r"(s), "l"(g));
}
__device__ __forceinline__ void cp_commit() {
    asm volatile("cp.async.commit_group;");
}
template <int N>
__device__ __forceinline__ void cp_wait() {
    asm volatile("cp.async.wait_group %0;" :: "n"(N));
}
__device__ __forceinline__ void mma_f16(float* c, uint4 a, uint32_t b0, uint32_t b1) {
    asm volatile(
        "mma.sync.aligned.m16n8k16.row.col.f32.f16.f16.f32 "
        "{%0,%1,%2,%3}, {%4,%5,%6,%7}, {%8,%9}, {%0,%1,%2,%3};"
        : "+f"(c[0]), "+f"(c[1]), "+f"(c[2]), "+f"(c[3])
        : "r"(a.x), "r"(a.y), "r"(a.z), "r"(a.w), "r"(b0), "r"(b1));
}
__device__ __forceinline__ uint32_t h2u(__half2 v) {
    return *reinterpret_cast<uint32_t*>(&v);
}
__device__ __forceinline__ float rope_val(float x, float y, int d, int p) {
    int dj = d & 63;
    float inv_freq = exp2f((float)dj * -0.2076205f);
    float f = (float)p * inv_freq;
    float sn, cs;
    sincosf(f, &sn, &cs);
    return (d < 64) ? (x * cs - y * sn) : (x * cs + y * sn);
}

// ---------------------------------------------------------------------------
// Pack kernels (hi-only)
// ---------------------------------------------------------------------------
__global__ void pack_a_kernel(const float* __restrict__ A, __half* __restrict__ P) {
    int idx = blockIdx.x * blockDim.x + threadIdx.x;
    int lane = idx & 31;
    int t = idx >> 5;
    int ks = t & (KS16_ - 1);
    int mt = t >> 7;
    int lg = lane >> 2, lc = lane & 3;
    int row = mt * 16 + lg;
    int col = ks * 16 + lc * 2;
    const float* r0 = A + (size_t)row * HID_ + col;
    const float* r1 = A + (size_t)(row + 8) * HID_ + col;
    __half out[8];
    out[0] = __float2half_rn(r0[0]);
    out[1] = __float2half_rn(r0[1]);
    out[2] = __float2half_rn(r1[0]);
    out[3] = __float2half_rn(r1[1]);
    out[4] = __float2half_rn(r0[8]);
    out[5] = __float2half_rn(r0[9]);
    out[6] = __float2half_rn(r1[8]);
    out[7] = __float2half_rn(r1[9]);
    *reinterpret_cast<uint4*>(P + (size_t)idx * 8) = *reinterpret_cast<uint4*>(&out[0]);
}

__global__ void pack_b4_kernel(const float* __restrict__ w0, const float* __restrict__ w1,
                               const float* __restrict__ w2, const float* __restrict__ w3,
                               __half* __restrict__ P) {
    const int z = blockIdx.y;
    const float* W = (z == 0) ? w0 : (z == 1) ? w1 : (z == 2) ? w2 : w3;
    __half* Pz = P + (size_t)z * HID_ * HID_;
    int idx = blockIdx.x * blockDim.x + threadIdx.x;
    int lane = idx & 31;
    int t = idx >> 5;
    int ks = t & (KS16_ - 1);
    int nt = t >> 7;
    int lg = lane >> 2, lc = lane & 3;
    int n = nt * 8 + lg;
    int k = ks * 16 + lc * 2;
    __half out[4];
    out[0] = __float2half_rn(W[(size_t)k * HID_ + n]);
    out[1] = __float2half_rn(W[(size_t)(k + 1) * HID_ + n]);
    out[2] = __float2half_rn(W[(size_t)(k + 8) * HID_ + n]);
    out[3] = __float2half_rn(W[(size_t)(k + 9) * HID_ + n]);
    *reinterpret_cast<uint2*>(Pz + (size_t)idx * 4) = *reinterpret_cast<uint2*>(&out[0]);
}

// ---------------------------------------------------------------------------
// fp16 1-pass GEMM mainloop, BK=64. Stage = A 16KB + B 16KB = 32KB; 3 stages.
// ---------------------------------------------------------------------------
constexpr int NT64 = HID_ / 64;           // 32 iterations
constexpr uint32_t STAGE_B = 32768;
constexpr int GEMM_DSMEM = 3 * STAGE_B;   // 98304

__device__ __forceinline__ void gemm_mainloop(
    const __half* __restrict__ Apack, const __half* __restrict__ Bpack,
    char* dsm, int row0, int col0, float acc[4][4][4])
{
    const uint32_t sb = (uint32_t)__cvta_generic_to_shared(dsm);
    const int tid = threadIdx.x;
    const int lane = tid & 31;
    const int wid = tid >> 5;
    const int warp_m = wid & 1;
    const int warp_n = wid >> 1;

    const __half* Ab = Apack + (size_t)(row0 >> 4) * (KS16_ * 32 * 8);
    const __half* Bb = Bpack + (size_t)(col0 >> 3) * (KS16_ * 32 * 4);

    auto load_stage = [&](int kt64, int s) {
        uint32_t sa = sb + (uint32_t)s * STAGE_B;
        uint32_t sbm = sa + 16384;
        const __half* Abase = Ab + (size_t)kt64 * 1024;
        const __half* Bbase = Bb + (size_t)kt64 * 512;
        #pragma unroll
        for (int i = 0; i < 4; i++) {          // A: 1024 x 16B chunks
            int c = tid + i * 256;
            int mt = c >> 7, inner = c & 127;
            cp_async16(sa + (uint32_t)c * 16, Abase + (size_t)mt * 32768 + inner * 8);
        }
        #pragma unroll
        for (int i = 0; i < 4; i++) {          // B: 1024 x 16B chunks
            int c = tid + i * 256;
            int nt = c >> 6, inner = c & 63;
            cp_async16(sbm + (uint32_t)c * 16, Bbase + (size_t)nt * 16384 + inner * 8);
        }
        cp_commit();
    };

    #pragma unroll
    for (int i = 0; i < 4; i++)
        #pragma unroll
        for (int j = 0; j < 4; j++)
            #pragma unroll
            for (int r = 0; r < 4; r++) acc[i][j][r] = 0.f;

    load_stage(0, 0);
    load_stage(1, 1);
    load_stage(2, 2);

    for (int kt = 0; kt < NT64; kt++) {
        const int s = kt % 3;
        if (kt + 2 >= NT64) cp_wait<0>(); else cp_wait<2>();
        __syncthreads();

        const uint4* sa_v = reinterpret_cast<const uint4*>(dsm + (size_t)s * STAGE_B);
        const uint2* sb_v = reinterpret_cast<const uint2*>(dsm + (size_t)s * STAGE_B + 16384);

        #pragma unroll
        for (int ks = 0; ks < 4; ks++) {
            uint4 ah[4];
            uint2 bf[4];
            #pragma unroll
            for (int mt = 0; mt < 4; mt++)
                ah[mt] = sa_v[(((warp_m * 4 + mt) * 4 + ks) * 32 + lane)];
            #pragma unroll
            for (int nt = 0; nt < 4; nt++)
                bf[nt] = sb_v[((warp_n * 4 + nt) * 4 + ks) * 32 + lane];
            #pragma unroll
            for (int mt = 0; mt < 4; mt++)
                #pragma unroll
                for (int nt = 0; nt < 4; nt++)
                    mma_f16(acc[mt][nt], ah[mt], bf[nt].x, bf[nt].y);
        }
        __syncthreads();
        if (kt + 3 < NT64) load_stage(kt + 3, s);
    }
}

// ---------------------------------------------------------------------------
// Fused QKV GEMM + bias + RoPE + attention-fragment packing (all hi-only).
// ---------------------------------------------------------------------------
__global__ void __launch_bounds__(256, 2)
gemm_qkv_fused(const __half* __restrict__ Apack, const __half* __restrict__ Bpack,
               const float* __restrict__ bq, const float* __restrict__ bk,
               const float* __restrict__ bv, const int* __restrict__ pos,
               __half* __restrict__ Qout, __half* __restrict__ Kout,
               __half* __restrict__ Vout) {
    extern __shared__ __align__(16) char dsm[];
    const int z = blockIdx.z;
    const size_t BPSZ = (size_t)HID_ * HID_;
    const int row0 = blockIdx.y * 128;
    const int col0 = blockIdx.x * 128;

    float acc[4][4][4];
    gemm_mainloop(Apack, Bpack + (size_t)z * BPSZ, dsm, row0, col0, acc);

    // Epilogue stage 1: acc + bias -> fp32 smem tile [128][132]
    const int tid = threadIdx.x;
    const int lane = tid & 31;
    const int wid = tid >> 5;
    const int warp_m = wid & 1;
    const int warp_n = wid >> 1;
    const int lg = lane >> 2, lc = lane & 3;
    const float* bias = (z == 0) ? bq : (z == 1) ? bk : bv;
    float* tile = reinterpret_cast<float*>(dsm);

    #pragma unroll
    for (int mt = 0; mt < 4; mt++) {
        int rl = warp_m * 64 + mt * 16 + lg;
        #pragma unroll
        for (int nt = 0; nt < 4; nt++) {
            int cl_ = warp_n * 32 + nt * 8 + lc * 2;
            float b0 = bias[col0 + cl_], b1 = bias[col0 + cl_ + 1];
            float* ch = acc[mt][nt];
            tile[rl * 132 + cl_]           = ch[0] + b0;
            tile[rl * 132 + cl_ + 1]       = ch[1] + b1;
            tile[(rl + 8) * 132 + cl_]     = ch[2] + b0;
            tile[(rl + 8) * 132 + cl_ + 1] = ch[3] + b1;
        }
    }
    __syncthreads();

    const int b = row0 >> 11;
    const int s0 = row0 & 2047;
    const int h = col0 >> 7;
    const int bh = b * 16 + h;

    if (z == 0) {
        // Q: A-frag pack (hi only), rope + scaling.
        #pragma unroll
        for (int u = 0; u < 8; u++) {
            int unit = tid + u * 256;
            int lane_u = unit & 31, ks = (unit >> 5) & 7, mt_l = unit >> 8;
            int lgu = lane_u >> 2, lcu = lane_u & 3;
            int r0l = mt_l * 16 + lgu;
            int p0 = pos[b * S_ + s0 + r0l];
            int p1 = pos[b * S_ + s0 + r0l + 8];
            int c0 = ks * 16 + 2 * lcu;
            int cols[4] = { c0, c0 + 1, c0 + 8, c0 + 9 };
            int i0[4] = { 0, 1, 4, 5 }, i1[4] = { 2, 3, 6, 7 };
            __half out[8];
            #pragma unroll
            for (int i = 0; i < 4; i++) {
                int d = cols[i];
                out[i0[i]] = __float2half_rn(
                    rope_val(tile[r0l * 132 + d], tile[r0l * 132 + (d ^ 64)], d, p0) * SCALING_);
                out[i1[i]] = __float2half_rn(
                    rope_val(tile[(r0l + 8) * 132 + d], tile[(r0l + 8) * 132 + (d ^ 64)], d, p1) * SCALING_);
            }
            *reinterpret_cast<uint4*>(
                Qout + (((size_t)(bh * 128 + (s0 >> 4) + mt_l) * 8 + ks) * 32 + lane_u) * 8) =
                *reinterpret_cast<uint4*>(&out[0]);
        }
    } else if (z == 1) {
        // K: B-frag pack (hi only), rope.
        #pragma unroll
        for (int u = 0; u < 16; u++) {
            int unit = tid + u * 256;
            int lane_u = unit & 31, ks = (unit >> 5) & 7, nt_l = unit >> 8;
            int lgu = lane_u >> 2, lcu = lane_u & 3;
            int tl = nt_l * 8 + lgu;
            int p = pos[b * S_ + s0 + tl];
            int c0 = ks * 16 + 2 * lcu;
            int cols[4] = { c0, c0 + 1, c0 + 8, c0 + 9 };
            __half out[4];
            #pragma unroll
            for (int i = 0; i < 4; i++) {
                int d = cols[i];
                out[i] = __float2half_rn(
                    rope_val(tile[tl * 132 + d], tile[tl * 132 + (d ^ 64)], d, p));
            }
            *reinterpret_cast<uint2*>(
                Kout + (((size_t)(bh * 256 + (s0 >> 3) + nt_l) * 8 + ks) * 32 + lane_u) * 4) =
                *reinterpret_cast<uint2*>(&out[0]);
        }
    } else {
        // V: B-frag pack (hi only) over tokens.
        #pragma unroll
        for (int u = 0; u < 16; u++) {
            int unit = tid + u * 256;
            int lane_u = unit & 31, ks_l = (unit >> 5) & 7, nt = unit >> 8;
            int lgu = lane_u >> 2, lcu = lane_u & 3;
            int n = nt * 8 + lgu;
            int k0 = ks_l * 16 + 2 * lcu;
            __half out[4];
            out[0] = __float2half_rn(tile[k0 * 132 + n]);
            out[1] = __float2half_rn(tile[(k0 + 1) * 132 + n]);
            out[2] = __float2half_rn(tile[(k0 + 8) * 132 + n]);
            out[3] = __float2half_rn(tile[(k0 + 9) * 132 + n]);
            *reinterpret_cast<uint2*>(
                Vout + (((size_t)(bh * 16 + nt) * 128 + (s0 >> 4) + ks_l) * 32 + lane_u) * 4) =
                *reinterpret_cast<uint2*>(&out[0]);
        }
    }
}

// Out-projection GEMM (1-pass, fp32 gmem epilogue)
__global__ void __launch_bounds__(256, 2)
gemm_tc_kernel(const __half* __restrict__ Apack, const __half* __restrict__ Bpack,
               float* __restrict__ C) {
    extern __shared__ __align__(16) char dsm[];
    const int row0 = blockIdx.y * 128;
    const int col0 = blockIdx.x * 128;
    float acc[4][4][4];
    gemm_mainloop(Apack, Bpack, dsm, row0, col0, acc);

    const int tid = threadIdx.x;
    const int lane = tid & 31;
    const int wid = tid >> 5;
    const int warp_m = wid & 1;
    const int warp_n = wid >> 1;
    const int lg = lane >> 2, lc = lane & 3;
    #pragma unroll
    for (int mt = 0; mt < 4; mt++) {
        int grow = row0 + (warp_m * 4 + mt) * 16 + lg;
        #pragma unroll
        for (int nt = 0; nt < 4; nt++) {
            int gcol = col0 + (warp_n * 4 + nt) * 8 + lc * 2;
            float* ch = acc[mt][nt];
            *reinterpret_cast<float2*>(C + (size_t)grow * HID_ + gcol) =
                make_float2(ch[0], ch[1]);
            *reinterpret_cast<float2*>(C + (size_t)(grow + 8) * HID_ + gcol) =
                make_float2(ch[2], ch[3]);
        }
    }
}

// ---------------------------------------------------------------------------
// Tensor-core causal flash attention. QK 1-pass, PV 1-pass, BN=128 tiles.
// smem: Q 32KB + 2 x (K 32KB + V 32KB) = 160KB.
// ---------------------------------------------------------------------------
constexpr uint32_t KV_STAGE = 65536;            // 32KB K + 32KB V
constexpr int AT2_SMEM = 32768 + 2 * 65536;     // 163840

__global__ void __launch_bounds__(256, 1)
attn_tc_kernel(const __half* __restrict__ Qp, const __half* __restrict__ Kp,
               const __half* __restrict__ Vp, __half* __restrict__ APout) {
    extern __shared__ __align__(16) char smem_raw[];
    const uint32_t sb = (uint32_t)__cvta_generic_to_shared(smem_raw);
    const int tid = threadIdx.x;
    const int lane = tid & 31;
    const int warp = tid >> 5;
    const int lg = lane >> 2, lc = lane & 3;
    const int qi = 15 - (int)(blockIdx.x >> 5);   // heavy-first
    const int bh = blockIdx.x & 31;
    const int b = bh >> 4, h = bh & 15;
    const int q0 = qi * 128;
    const int ntiles = qi + 1;                    // BN=128: diagonal = 1 tile

    const __half* Qb = Qp + ((size_t)bh * 128 + (size_t)qi * 8) * 2048;
    const __half* Kb = Kp + (size_t)bh * 256 * 1024;
    const __half* Vb = Vp + (size_t)bh * 16 * 16384;

    // Q tile: 16384 halfs = 2048 x 16B chunks
    #pragma unroll
    for (int i = 0; i < 8; i++) {
        int c = tid + i * 256;
        cp_async16(sb + (uint32_t)c * 16, Qb + (size_t)c * 8);
    }
    cp_commit();

    auto load_KV = [&](int t, int s) {
        uint32_t base = sb + 32768 + (uint32_t)s * KV_STAGE;
        const __half* Ksrc = Kb + (size_t)t * 16384;   // 16 nt x 1024 halfs
        #pragma unroll
        for (int i = 0; i < 8; i++) {                   // K: 2048 chunks
            int c = tid + i * 256;
            cp_async16(base + (uint32_t)c * 16, Ksrc + (size_t)c * 8);
        }
        #pragma unroll
        for (int i = 0; i < 8; i++) {                   // V: 2048 chunks
            int c = tid + i * 256;
            int nt = c >> 7, inner = c & 127;
            cp_async16(base + 32768 + (uint32_t)c * 16,
                       Vb + (size_t)nt * 16384 + (size_t)t * 1024 + inner * 8);
        }
        cp_commit();
    };
    load_KV(0, 0);
    if (ntiles > 1) load_KV(1, 1); else cp_commit();   // keep group count consistent

    float oacc[16][4];
    #pragma unroll
    for (int i = 0; i < 16; i++)
        #pragma unroll
        for (int r = 0; r < 4; r++) oacc[i][r] = 0.f;
    float m0 = -1e30f, m1 = -1e30f, l0 = 0.f, l1 = 0.f;

    const uint4* Qv = reinterpret_cast<const uint4*>(smem_raw);

    for (int t = 0; t < ntiles; t++) {
        if (t + 1 >= ntiles) cp_wait<0>(); else cp_wait<1>();
        __syncthreads();
        const int s = t & 1;
        const uint2* Kv = reinterpret_cast<const uint2*>(smem_raw + 32768 + (size_t)s * KV_STAGE);
        const uint2* Vv = reinterpret_cast<const uint2*>(smem_raw + 32768 + (size_t)s * KV_STAGE + 32768);

        // S = Q @ K^T (1-pass), 16 n-tiles of 8 cols
        float sacc[16][4];
        #pragma unroll
        for (int nt = 0; nt < 16; nt++)
            #pragma unroll
            for (int r = 0; r < 4; r++) sacc[nt][r] = 0.f;
        #pragma unroll
        for (int ks = 0; ks < 8; ks++) {
            uint4 ahi = Qv[(warp * 8 + ks) * 32 + lane];
            #pragma unroll
            for (int half = 0; half < 2; half++) {
                uint2 kf[8];
                #pragma unroll
                for (int i = 0; i < 8; i++)
                    kf[i] = Kv[((half * 8 + i) * 8 + ks) * 32 + lane];
                #pragma unroll
                for (int i = 0; i < 8; i++)
                    mma_f16(sacc[half * 8 + i], ahi, kf[i].x, kf[i].y);
            }
        }

        // Causal mask: only the last tile is diagonal
        if (t == ntiles - 1) {
            int gr0 = q0 + warp * 16 + lg;
            int gr1 = gr0 + 8;
            #pragma unroll
            for (int nt = 0; nt < 16; nt++) {
                int gc = t * 128 + nt * 8 + 2 * lc;
                if (gc > gr0)     sacc[nt][0] = -1e30f;
                if (gc + 1 > gr0) sacc[nt][1] = -1e30f;
                if (gc > gr1)     sacc[nt][2] = -1e30f;
                if (gc + 1 > gr1) sacc[nt][3] = -1e30f;
            }
        }

        // Online softmax over 128 columns
        float mx0 = -1e30f, mx1 = -1e30f;
        #pragma unroll
        for (int nt = 0; nt < 16; nt++) {
            mx0 = fmaxf(mx0, fmaxf(sacc[nt][0], sacc[nt][1]));
            mx1 = fmaxf(mx1, fmaxf(sacc[nt][2], sacc[nt][3]));
        }
        mx0 = fmaxf(mx0, __shfl_xor_sync(0xFFFFFFFFu, mx0, 1));
        mx0 = fmaxf(mx0, __shfl_xor_sync(0xFFFFFFFFu, mx0, 2));
        mx1 = fmaxf(mx1, __shfl_xor_sync(0xFFFFFFFFu, mx1, 1));
        mx1 = fmaxf(mx1, __shfl_xor_sync(0xFFFFFFFFu, mx1, 2));
        float mn0 = fmaxf(m0, mx0), mn1 = fmaxf(m1, mx1);
        float c0 = __expf(m0 - mn0), c1 = __expf(m1 - mn1);
        m0 = mn0; m1 = mn1;
        float sum0 = 0.f, sum1 = 0.f;
        #pragma unroll
        for (int nt = 0; nt < 16; nt++) {
            sacc[nt][0] = __expf(sacc[nt][0] - mn0); sum0 += sacc[nt][0];
            sacc[nt][1] = __expf(sacc[nt][1] - mn0); sum0 += sacc[nt][1];
            sacc[nt][2] = __expf(sacc[nt][2] - mn1); sum1 += sacc[nt][2];
            sacc[nt][3] = __expf(sacc[nt][3] - mn1); sum1 += sacc[nt][3];
        }
        sum0 += __shfl_xor_sync(0xFFFFFFFFu, sum0, 1);
        sum0 += __shfl_xor_sync(0xFFFFFFFFu, sum0, 2);
        sum1 += __shfl_xor_sync(0xFFFFFFFFu, sum1, 1);
        sum1 += __shfl_xor_sync(0xFFFFFFFFu, sum1, 2);
        l0 = l0 * c0 + sum0;
        l1 = l1 * c1 + sum1;
        #pragma unroll
        for (int nt = 0; nt < 16; nt++) {
            oacc[nt][0] *= c0; oacc[nt][1] *= c0;
            oacc[nt][2] *= c1; oacc[nt][3] *= c1;
        }

        // O += P @ V (1-pass), 8 k16-chunks of 16 tokens
        #pragma unroll
        for (int j = 0; j < 8; j++) {
            const float* pa = sacc[2 * j];
            const float* pb = sacc[2 * j + 1];
            __half2 h01 = __floats2half2_rn(pa[0], pa[1]);
            __half2 h23 = __floats2half2_rn(pa[2], pa[3]);
            __half2 h45 = __floats2half2_rn(pb[0], pb[1]);
            __half2 h67 = __floats2half2_rn(pb[2], pb[3]);
            uint4 phi = make_uint4(h2u(h01), h2u(h23), h2u(h45), h2u(h67));
            #pragma unroll
            for (int blk = 0; blk < 2; blk++) {
                uint2 vf[8];
                #pragma unroll
                for (int i = 0; i < 8; i++)
                    vf[i] = Vv[((blk * 8 + i) * 8 + j) * 32 + lane];
                #pragma unroll
                for (int i = 0; i < 8; i++)
                    mma_f16(oacc[blk * 8 + i], phi, vf[i].x, vf[i].y);
            }
        }

        __syncthreads();
        if (t + 2 < ntiles) load_KV(t + 2, s);
    }

    // Epilogue: normalize + write out-proj A-frag pack (hi-only)
    float inv0 = 1.f / l0, inv1 = 1.f / l1;
    const int mtg = b * 128 + qi * 8 + warp;
    #pragma unroll
    for (int j = 0; j < 8; j++) {
        const int ksg = h * 8 + j;
        __half out[8];
        out[0] = __float2half_rn(oacc[2 * j][0] * inv0);
        out[1] = __float2half_rn(oacc[2 * j][1] * inv0);
        out[2] = __float2half_rn(oacc[2 * j][2] * inv1);
        out[3] = __float2half_rn(oacc[2 * j][3] * inv1);
        out[4] = __float2half_rn(oacc[2 * j + 1][0] * inv0);
        out[5] = __float2half_rn(oacc[2 * j + 1][1] * inv0);
        out[6] = __float2half_rn(oacc[2 * j + 1][2] * inv1);
        out[7] = __float2half_rn(oacc[2 * j + 1][3] * inv1);
        *reinterpret_cast<uint4*>(
            APout + (((size_t)mtg * KS16_ + ksg) * 32 + lane) * 8) =
            *reinterpret_cast<uint4*>(&out[0]);
    }
}

// ---------------------------------------------------------------------------
// Launch
// ---------------------------------------------------------------------------
extern "C" void kernel_launch(void* const* d_in, const int* in_sizes, int n_in,
                              void* d_out, int out_size) {
    const float* hs  = (const float*)d_in[0];
    const int*   pos = (const int*)  d_in[1];
    const float* wq  = (const float*)d_in[2];
    const float* bq  = (const float*)d_in[3];
    const float* wk  = (const float*)d_in[4];
    const float* bk  = (const float*)d_in[5];
    const float* wv  = (const float*)d_in[6];
    const float* bv  = (const float*)d_in[7];
    const float* wc  = (const float*)d_in[8];
    float* out = (float*)d_out;

    __half *apack, *bpack, *qpk, *kpk, *vpk;
    cudaGetSymbolAddress((void**)&apack, g_apack);
    cudaGetSymbolAddress((void**)&bpack, g_bpack);
    cudaGetSymbolAddress((void**)&qpk, g_qpack);
    cudaGetSymbolAddress((void**)&kpk, g_kpack);
    cudaGetSymbolAddress((void**)&vpk, g_vpack);

    const size_t BPSZ = (size_t)HID_ * HID_;

    cudaFuncSetAttribute(gemm_qkv_fused,
                         cudaFuncAttributeMaxDynamicSharedMemorySize, GEMM_DSMEM);
    cudaFuncSetAttribute(gemm_tc_kernel,
                         cudaFuncAttributeMaxDynamicSharedMemorySize, GEMM_DSMEM);
    cudaFuncSetAttribute(attn_tc_kernel,
                         cudaFuncAttributeMaxDynamicSharedMemorySize, AT2_SMEM);

    // Weight + activation packs (hi-only)
    dim3 pbgrid((HID_ / 8) * KS16_ * 32 / 256, 4);   // (4096, 4)
    pack_b4_kernel<<<pbgrid, 256>>>(wq, wk, wv, wc, bpack);
    const int pa_blocks = (M_ / 16) * KS16_ * 32 / 256;    // 4096
    pack_a_kernel<<<pa_blocks, 256>>>(hs, apack);

    // Fused QKV projections + rope + attention packing (1-pass GEMM)
    dim3 qkv_grid(HID_ / 128, M_ / 128, 3);   // (16, 32, 3)
    gemm_qkv_fused<<<qkv_grid, 256, GEMM_DSMEM>>>(apack, bpack, bq, bk, bv, pos,
                                                  qpk, kpk, vpk);

    // Tensor-core attention (BN=128, writes out-proj A-pack directly)
    attn_tc_kernel<<<512, 256, AT2_SMEM>>>(qpk, kpk, vpk, apack);

    // Output projection (1-pass)
    dim3 ggrid(HID_ / 128, M_ / 128);   // (16, 32)
    gemm_tc_kernel<<<ggrid, 256, GEMM_DSMEM>>>(apack, bpack + 3 * BPSZ, out);
}